// round 3
// baseline (speedup 1.0000x reference)
#include <cuda_runtime.h>
#include <cstdint>
#include <math.h>

#define NL    4
#define DMODEL 512
#define NH    8
#define DHEAD 64
#define DFF_  1024
#define SEQ   2048
#define BATCH 2
#define NROWS (BATCH*SEQ)          // 4096
#define OUTX  ((size_t)NROWS*DMODEL)  // 2097152

// ---------------- scratch (static device memory; no allocation) ----------------
__device__ float g_x [NROWS*DMODEL];
__device__ float g_h [NROWS*DMODEL];
__device__ float g_q [NROWS*DMODEL];
__device__ float g_k [NROWS*DMODEL];
__device__ float g_v [NROWS*DMODEL];
__device__ float g_o [NROWS*DMODEL];
__device__ float g_f0[NROWS*DFF_];
__device__ float g_f1[NROWS*DFF_];
__device__ float g_s  [(size_t)BATCH*NH*SEQ*SEQ];  // 268 MB scores
__device__ float g_bias[(size_t)NH*SEQ*SEQ];       // 134 MB pos bias

// ---------------- embedding gather ----------------
__global__ __launch_bounds__(256) void embed_k(const int* __restrict__ ids,
                                               const float* __restrict__ emb,
                                               float* __restrict__ x) {
    const int row = blockIdx.x;
    const size_t src = (size_t)ids[row] * DMODEL;
    const size_t dst = (size_t)row * DMODEL;
    for (int i = threadIdx.x; i < DMODEL; i += 256) x[dst + i] = emb[src + i];
}

// ---------------- T5 relative position bias ----------------
__global__ __launch_bounds__(256) void bias_k(const float* __restrict__ rb,
                                              float* __restrict__ bias,
                                              float* __restrict__ out2) {
    size_t idx = (size_t)blockIdx.x * 256 + threadIdx.x;
    if (idx >= (size_t)NH * SEQ * SEQ) return;
    int kk = (int)(idx & (SEQ - 1));
    int qq = (int)((idx >> 11) & (SEQ - 1));
    int hh = (int)(idx >> 22);
    int rel = kk - qq;
    int bucket = (rel > 0) ? 16 : 0;
    int rp = (rel < 0) ? -rel : rel;
    int add;
    if (rp < 8) {
        add = rp;
    } else {
        // mimic jnp: log(rp/8)/log(16)*8, all f32, truncate to int
        float t = logf((float)rp / 8.0f);
        t = t / 2.7725887298583984f;   // float(math.log(16.0))
        t = t * 8.0f;
        add = 8 + (int)t;
        if (add > 15) add = 15;
    }
    float val = rb[(bucket + add) * NH + hh];
    bias[idx] = val;
    if (out2) out2[idx] = val;
}

// ---------------- T5 RMS layernorm ----------------
__global__ __launch_bounds__(256) void rms_k(const float* __restrict__ x,
                                             const float* __restrict__ w,
                                             float* __restrict__ y) {
    const size_t base = (size_t)blockIdx.x * DMODEL;
    const int t = threadIdx.x;
    float v0 = x[base + t], v1 = x[base + t + 256];
    float ss = v0 * v0 + v1 * v1;
    #pragma unroll
    for (int off = 16; off; off >>= 1) ss += __shfl_xor_sync(0xffffffffu, ss, off);
    __shared__ float red[8];
    __shared__ float bval;
    if ((t & 31) == 0) red[t >> 5] = ss;
    __syncthreads();
    if (t == 0) {
        float tot = 0.f;
        #pragma unroll
        for (int i = 0; i < 8; i++) tot += red[i];
        bval = rsqrtf(tot * (1.0f / DMODEL) + 1e-6f);
    }
    __syncthreads();
    const float inv = bval;
    y[base + t]       = w[t]       * (v0 * inv);
    y[base + t + 256] = w[t + 256] * (v1 * inv);
}

// ---------------- softmax over rows of 2048 ----------------
__global__ __launch_bounds__(256) void softmax_k(float* __restrict__ s) {
    float* p = s + (size_t)blockIdx.x * SEQ;
    const int t = threadIdx.x;
    float v[8];
    float mx = -3.402823466e38f;
    #pragma unroll
    for (int i = 0; i < 8; i++) { v[i] = p[t + i * 256]; mx = fmaxf(mx, v[i]); }
    #pragma unroll
    for (int off = 16; off; off >>= 1) mx = fmaxf(mx, __shfl_xor_sync(0xffffffffu, mx, off));
    __shared__ float red[8];
    __shared__ float bval;
    const int w = t >> 5, ln = t & 31;
    if (ln == 0) red[w] = mx;
    __syncthreads();
    if (t == 0) {
        float m = red[0];
        #pragma unroll
        for (int i = 1; i < 8; i++) m = fmaxf(m, red[i]);
        bval = m;
    }
    __syncthreads();
    mx = bval;
    float sum = 0.f;
    #pragma unroll
    for (int i = 0; i < 8; i++) { v[i] = expf(v[i] - mx); sum += v[i]; }
    #pragma unroll
    for (int off = 16; off; off >>= 1) sum += __shfl_xor_sync(0xffffffffu, sum, off);
    if (ln == 0) red[w] = sum;
    __syncthreads();
    if (t == 0) {
        float tot = 0.f;
        #pragma unroll
        for (int i = 0; i < 8; i++) tot += red[i];
        bval = 1.0f / tot;
    }
    __syncthreads();
    const float inv = bval;
    #pragma unroll
    for (int i = 0; i < 8; i++) p[t + i * 256] = v[i] * inv;
}

// ---------------- gated-GELU combine ----------------
__global__ __launch_bounds__(256) void geglu_k(float* __restrict__ f0,
                                               const float* __restrict__ f1, int n) {
    int i = blockIdx.x * blockDim.x + threadIdx.x;
    int stride = gridDim.x * blockDim.x;
    for (; i < n; i += stride) {
        float xx = f0[i];
        float inner = 0.7978845608028654f * (xx + 0.044715f * (xx * xx * xx));
        float g = 0.5f * xx * (1.0f + tanhf(inner));
        f0[i] = g * f1[i];
    }
}

// ---------------- tiled SGEMM ----------------
// C[M,N] = A[M,K] @ B  (+ residual E, or + per-head bias E for attention scores)
// TRANSB=1: B stored [N,K] (keys x dh)   TRANSB=0: B stored [K,N]
// EPI: 0 none, 1 residual add (E has C layout), 2 pos-bias add (E=[NH,SEQ,SEQ], head=z&7)
// blockIdx.z batching: z = b*8 + h; pointer += (z>>3)*SB + (z&7)*SH
template <int BN, int TN, int TRANSB, int EPI>
__global__ __launch_bounds__(256) void gemm_k(
    const float* __restrict__ A, int lda, size_t aSB, size_t aSH,
    const float* __restrict__ B, int ldb, size_t bSB, size_t bSH,
    float* __restrict__ C, int ldc, size_t cSB, size_t cSH,
    const float* __restrict__ E, int K)
{
    constexpr int BM = 128, BK = 16, TM = 8;
    __shared__ float As[BK][BM + 4];
    __shared__ float Bs[BK][BN + 4];
    const int z = blockIdx.z;
    const int zb = z >> 3, zh = z & 7;
    A += (size_t)zb * aSB + (size_t)zh * aSH;
    B += (size_t)zb * bSB + (size_t)zh * bSH;
    C += (size_t)zb * cSB + (size_t)zh * cSH;
    const int m0 = blockIdx.y * BM, n0 = blockIdx.x * BN;
    const int t = threadIdx.x;
    const int tx = t & 15, ty = t >> 4;

    float acc[TM][TN];
    #pragma unroll
    for (int i = 0; i < TM; i++)
        #pragma unroll
        for (int j = 0; j < TN; j++) acc[i][j] = 0.f;

    for (int k0 = 0; k0 < K; k0 += BK) {
        // A tile 128x16, stored transposed As[k][m]
        #pragma unroll
        for (int i = 0; i < 2; i++) {
            int idx = t + i * 256;
            int r = idx >> 2, c4 = idx & 3;
            const float4 av = *reinterpret_cast<const float4*>(
                A + (size_t)(m0 + r) * lda + (k0 + c4 * 4));
            As[c4 * 4 + 0][r] = av.x; As[c4 * 4 + 1][r] = av.y;
            As[c4 * 4 + 2][r] = av.z; As[c4 * 4 + 3][r] = av.w;
        }
        // B tile
        if (TRANSB) {
            #pragma unroll
            for (int i = 0; i < BN / 64; i++) {
                int idx = t + i * 256;
                int n = idx >> 2, c4 = idx & 3;
                const float4 bv = *reinterpret_cast<const float4*>(
                    B + (size_t)(n0 + n) * ldb + (k0 + c4 * 4));
                Bs[c4 * 4 + 0][n] = bv.x; Bs[c4 * 4 + 1][n] = bv.y;
                Bs[c4 * 4 + 2][n] = bv.z; Bs[c4 * 4 + 3][n] = bv.w;
            }
        } else {
            #pragma unroll
            for (int i = 0; i < BN / 64; i++) {
                int idx = t + i * 256;
                int r = idx / (BN / 4), c = idx % (BN / 4);
                *reinterpret_cast<float4*>(&Bs[r][c * 4]) =
                    *reinterpret_cast<const float4*>(B + (size_t)(k0 + r) * ldb + n0 + c * 4);
            }
        }
        __syncthreads();
        #pragma unroll
        for (int kk = 0; kk < BK; kk++) {
            float ar[TM], br[TN];
            *reinterpret_cast<float4*>(&ar[0]) =
                *reinterpret_cast<const float4*>(&As[kk][ty * TM]);
            *reinterpret_cast<float4*>(&ar[4]) =
                *reinterpret_cast<const float4*>(&As[kk][ty * TM + 4]);
            *reinterpret_cast<float4*>(&br[0]) =
                *reinterpret_cast<const float4*>(&Bs[kk][tx * TN]);
            if constexpr (TN == 8)
                *reinterpret_cast<float4*>(&br[4]) =
                    *reinterpret_cast<const float4*>(&Bs[kk][tx * TN + 4]);
            #pragma unroll
            for (int i = 0; i < TM; i++)
                #pragma unroll
                for (int j = 0; j < TN; j++)
                    acc[i][j] = fmaf(ar[i], br[j], acc[i][j]);
        }
        __syncthreads();
    }
    #pragma unroll
    for (int i = 0; i < TM; i++) {
        int m = m0 + ty * TM + i;
        #pragma unroll
        for (int j4 = 0; j4 < TN / 4; j4++) {
            int n = n0 + tx * TN + j4 * 4;
            float4 cv = make_float4(acc[i][j4 * 4], acc[i][j4 * 4 + 1],
                                    acc[i][j4 * 4 + 2], acc[i][j4 * 4 + 3]);
            if constexpr (EPI == 1) {
                const float4 rv = *reinterpret_cast<const float4*>(
                    E + (size_t)zb * cSB + (size_t)zh * cSH + (size_t)m * ldc + n);
                cv.x += rv.x; cv.y += rv.y; cv.z += rv.z; cv.w += rv.w;
            } else if constexpr (EPI == 2) {
                const float4 bv = *reinterpret_cast<const float4*>(
                    E + ((size_t)zh * SEQ + m) * SEQ + n);
                cv.x += bv.x; cv.y += bv.y; cv.z += bv.z; cv.w += bv.w;
            }
            *reinterpret_cast<float4*>(C + (size_t)m * ldc + n) = cv;
        }
    }
}

// ---------------- launch ----------------
extern "C" void kernel_launch(void* const* d_in, const int* in_sizes, int n_in,
                              void* d_out, int out_size) {
    const int*   ids    = (const int*)  d_in[0];
    const float* embed  = (const float*)d_in[1];
    const float* Wq     = (const float*)d_in[2];
    const float* Wk     = (const float*)d_in[3];
    const float* Wv     = (const float*)d_in[4];
    const float* Wo     = (const float*)d_in[5];
    const float* relb   = (const float*)d_in[6];
    const float* wi0    = (const float*)d_in[7];
    const float* wi1    = (const float*)d_in[8];
    const float* wo_ffn = (const float*)d_in[9];
    const float* ln0    = (const float*)d_in[10];
    const float* ln1    = (const float*)d_in[11];
    const float* flw    = (const float*)d_in[12];
    float* out = (float*)d_out;

    float *x, *h, *q, *k, *v, *o, *f0, *f1, *s, *bias;
    cudaGetSymbolAddress((void**)&x,  g_x);
    cudaGetSymbolAddress((void**)&h,  g_h);
    cudaGetSymbolAddress((void**)&q,  g_q);
    cudaGetSymbolAddress((void**)&k,  g_k);
    cudaGetSymbolAddress((void**)&v,  g_v);
    cudaGetSymbolAddress((void**)&o,  g_o);
    cudaGetSymbolAddress((void**)&f0, g_f0);
    cudaGetSymbolAddress((void**)&f1, g_f1);
    cudaGetSymbolAddress((void**)&s,  g_s);
    cudaGetSymbolAddress((void**)&bias, g_bias);

    float* out_bias = ((size_t)out_size > OUTX) ? (out + OUTX) : nullptr;

    embed_k<<<NROWS, 256>>>(ids, embed, x);
    {
        size_t nb = ((size_t)NH * SEQ * SEQ + 255) / 256;
        bias_k<<<(unsigned)nb, 256>>>(relb, bias, out_bias);
    }

    const size_t bhA = (size_t)SEQ * NH * DHEAD;   // per-batch stride in q/k/v/o
    const size_t bhS = (size_t)NH * SEQ * SEQ;     // per-batch stride in scores
    const size_t hS  = (size_t)SEQ * SEQ;          // per-head stride in scores

    for (int i = 0; i < NL; i++) {
        // ---- self attention ----
        rms_k<<<NROWS, 256>>>(x, ln0 + (size_t)i * DMODEL, h);
        dim3 gQKV(DMODEL / 128, NROWS / 128, 1);
        gemm_k<128, 8, 0, 0><<<gQKV, 256>>>(h, DMODEL, 0, 0,
                                            Wq + (size_t)i * DMODEL * DMODEL, DMODEL, 0, 0,
                                            q, DMODEL, 0, 0, nullptr, DMODEL);
        gemm_k<128, 8, 0, 0><<<gQKV, 256>>>(h, DMODEL, 0, 0,
                                            Wk + (size_t)i * DMODEL * DMODEL, DMODEL, 0, 0,
                                            k, DMODEL, 0, 0, nullptr, DMODEL);
        gemm_k<128, 8, 0, 0><<<gQKV, 256>>>(h, DMODEL, 0, 0,
                                            Wv + (size_t)i * DMODEL * DMODEL, DMODEL, 0, 0,
                                            v, DMODEL, 0, 0, nullptr, DMODEL);
        // scores[b,h,q,k] = Q @ K^T + pos_bias
        dim3 gS(SEQ / 128, SEQ / 128, BATCH * NH);
        gemm_k<128, 8, 1, 2><<<gS, 256>>>(q, NH * DHEAD, bhA, DHEAD,
                                          k, NH * DHEAD, bhA, DHEAD,
                                          s, SEQ, bhS, hS,
                                          bias, DHEAD);
        softmax_k<<<BATCH * NH * SEQ, 256>>>(s);
        // o = attn @ V
        dim3 gPV(1, SEQ / 128, BATCH * NH);
        gemm_k<64, 4, 0, 0><<<gPV, 256>>>(s, SEQ, bhS, hS,
                                          v, NH * DHEAD, bhA, DHEAD,
                                          o, NH * DHEAD, bhA, DHEAD,
                                          nullptr, SEQ);
        // x = x + o @ Wo
        gemm_k<128, 8, 0, 1><<<gQKV, 256>>>(o, DMODEL, 0, 0,
                                            Wo + (size_t)i * DMODEL * DMODEL, DMODEL, 0, 0,
                                            x, DMODEL, 0, 0, x, DMODEL);
        // ---- gated-GELU FFN ----
        rms_k<<<NROWS, 256>>>(x, ln1 + (size_t)i * DMODEL, h);
        dim3 gFF(DFF_ / 128, NROWS / 128, 1);
        gemm_k<128, 8, 0, 0><<<gFF, 256>>>(h, DMODEL, 0, 0,
                                           wi0 + (size_t)i * DMODEL * DFF_, DFF_, 0, 0,
                                           f0, DFF_, 0, 0, nullptr, DMODEL);
        gemm_k<128, 8, 0, 0><<<gFF, 256>>>(h, DMODEL, 0, 0,
                                           wi1 + (size_t)i * DMODEL * DFF_, DFF_, 0, 0,
                                           f1, DFF_, 0, 0, nullptr, DMODEL);
        geglu_k<<<4096, 256>>>(f0, f1, NROWS * DFF_);
        // x = x + geglu @ wo_ffn   (K = DFF_, E = x residual)
        gemm_k<128, 8, 0, 1><<<gQKV, 256>>>(f0, DFF_, 0, 0,
                                            wo_ffn + (size_t)i * DFF_ * DMODEL, DMODEL, 0, 0,
                                            x, DMODEL, 0, 0,
                                            x, DFF_);
    }
    rms_k<<<NROWS, 256>>>(x, flw, out);
}

// round 4
// speedup vs baseline: 1.0483x; 1.0483x over previous
#include <cuda_runtime.h>
#include <cstdint>
#include <math.h>

#define NL    4
#define DMODEL 512
#define NH    8
#define DHEAD 64
#define DFF_  1024
#define SEQ   2048
#define BATCH 2
#define NROWS (BATCH*SEQ)          // 4096
#define OUTX  ((size_t)NROWS*DMODEL)  // 2097152

typedef unsigned long long u64;

// ---------------- scratch (static device memory; no allocation) ----------------
__device__ float g_x [NROWS*DMODEL];
__device__ float g_h [NROWS*DMODEL];
__device__ float g_q [NROWS*DMODEL];
__device__ float g_k [NROWS*DMODEL];
__device__ float g_v [NROWS*DMODEL];
__device__ float g_o [NROWS*DMODEL];
__device__ float g_f0[NROWS*DFF_];
__device__ float g_f1[NROWS*DFF_];
__device__ float g_s  [(size_t)BATCH*NH*SEQ*SEQ];  // 268 MB scores
__device__ float g_bias[(size_t)NH*SEQ*SEQ];       // 134 MB pos bias

// ---------------- f32x2 helpers ----------------
__device__ __forceinline__ u64 pack2(float lo, float hi) {
    u64 r; asm("mov.b64 %0, {%1, %2};" : "=l"(r) : "f"(lo), "f"(hi)); return r;
}
__device__ __forceinline__ void unpack2(u64 v, float& lo, float& hi) {
    asm("mov.b64 {%0, %1}, %2;" : "=f"(lo), "=f"(hi) : "l"(v));
}
__device__ __forceinline__ void ffma2(u64& d, u64 a, u64 b) {
    asm("fma.rn.f32x2 %0, %1, %2, %0;" : "+l"(d) : "l"(a), "l"(b));
}

// ---------------- embedding gather ----------------
__global__ __launch_bounds__(256) void embed_k(const int* __restrict__ ids,
                                               const float* __restrict__ emb,
                                               float* __restrict__ x) {
    const int row = blockIdx.x;
    const size_t src = (size_t)ids[row] * DMODEL;
    const size_t dst = (size_t)row * DMODEL;
    for (int i = threadIdx.x; i < DMODEL; i += 256) x[dst + i] = emb[src + i];
}

// ---------------- T5 relative position bias ----------------
__global__ __launch_bounds__(256) void bias_k(const float* __restrict__ rb,
                                              float* __restrict__ bias,
                                              float* __restrict__ out2) {
    size_t idx = (size_t)blockIdx.x * 256 + threadIdx.x;
    if (idx >= (size_t)NH * SEQ * SEQ) return;
    int kk = (int)(idx & (SEQ - 1));
    int qq = (int)((idx >> 11) & (SEQ - 1));
    int hh = (int)(idx >> 22);
    int rel = kk - qq;
    int bucket = (rel > 0) ? 16 : 0;
    int rp = (rel < 0) ? -rel : rel;
    int add;
    if (rp < 8) {
        add = rp;
    } else {
        float t = logf((float)rp / 8.0f);
        t = t / 2.7725887298583984f;   // float(math.log(16.0))
        t = t * 8.0f;
        add = 8 + (int)t;
        if (add > 15) add = 15;
    }
    float val = rb[(bucket + add) * NH + hh];
    bias[idx] = val;
    if (out2) out2[idx] = val;
}

// ---------------- T5 RMS layernorm ----------------
__global__ __launch_bounds__(256) void rms_k(const float* __restrict__ x,
                                             const float* __restrict__ w,
                                             float* __restrict__ y) {
    const size_t base = (size_t)blockIdx.x * DMODEL;
    const int t = threadIdx.x;
    float v0 = x[base + t], v1 = x[base + t + 256];
    float ss = v0 * v0 + v1 * v1;
    #pragma unroll
    for (int off = 16; off; off >>= 1) ss += __shfl_xor_sync(0xffffffffu, ss, off);
    __shared__ float red[8];
    __shared__ float bval;
    if ((t & 31) == 0) red[t >> 5] = ss;
    __syncthreads();
    if (t == 0) {
        float tot = 0.f;
        #pragma unroll
        for (int i = 0; i < 8; i++) tot += red[i];
        bval = rsqrtf(tot * (1.0f / DMODEL) + 1e-6f);
    }
    __syncthreads();
    const float inv = bval;
    y[base + t]       = w[t]       * (v0 * inv);
    y[base + t + 256] = w[t + 256] * (v1 * inv);
}

// ---------------- softmax over rows of 2048 ----------------
__global__ __launch_bounds__(256) void softmax_k(float* __restrict__ s) {
    float* p = s + (size_t)blockIdx.x * SEQ;
    const int t = threadIdx.x;
    float v[8];
    float mx = -3.402823466e38f;
    #pragma unroll
    for (int i = 0; i < 8; i++) { v[i] = p[t + i * 256]; mx = fmaxf(mx, v[i]); }
    #pragma unroll
    for (int off = 16; off; off >>= 1) mx = fmaxf(mx, __shfl_xor_sync(0xffffffffu, mx, off));
    __shared__ float red[8];
    __shared__ float bval;
    const int w = t >> 5, ln = t & 31;
    if (ln == 0) red[w] = mx;
    __syncthreads();
    if (t == 0) {
        float m = red[0];
        #pragma unroll
        for (int i = 1; i < 8; i++) m = fmaxf(m, red[i]);
        bval = m;
    }
    __syncthreads();
    mx = bval;
    float sum = 0.f;
    #pragma unroll
    for (int i = 0; i < 8; i++) { v[i] = expf(v[i] - mx); sum += v[i]; }
    #pragma unroll
    for (int off = 16; off; off >>= 1) sum += __shfl_xor_sync(0xffffffffu, sum, off);
    if (ln == 0) red[w] = sum;
    __syncthreads();
    if (t == 0) {
        float tot = 0.f;
        #pragma unroll
        for (int i = 0; i < 8; i++) tot += red[i];
        bval = 1.0f / tot;
    }
    __syncthreads();
    const float inv = bval;
    #pragma unroll
    for (int i = 0; i < 8; i++) p[t + i * 256] = v[i] * inv;
}

// ---------------- gated-GELU combine ----------------
__global__ __launch_bounds__(256) void geglu_k(float* __restrict__ f0,
                                               const float* __restrict__ f1, int n) {
    int i = blockIdx.x * blockDim.x + threadIdx.x;
    int stride = gridDim.x * blockDim.x;
    for (; i < n; i += stride) {
        float xx = f0[i];
        float inner = 0.7978845608028654f * (xx + 0.044715f * (xx * xx * xx));
        float g = 0.5f * xx * (1.0f + tanhf(inner));
        f0[i] = g * f1[i];
    }
}

// ---------------- tiled SGEMM core (FFMA2 mainloop) ----------------
// C[M,N] = A[M,K] @ B  (+ epilogue)
// TRANSB=1: B stored [N,K]   TRANSB=0: B stored [K,N]
// EPI: 0 none, 1 residual add (E pre-offset, C layout), 2 pos-bias (E=[NH,SEQ,SEQ], head=zh)
template <int BN, int TN, int TRANSB, int EPI>
__device__ __forceinline__ void gemm_core(
    const float* __restrict__ A, int lda,
    const float* __restrict__ B, int ldb,
    float* __restrict__ C, int ldc,
    const float* __restrict__ E, int K, int zh)
{
    constexpr int BM = 128, BK = 16, TM = 8;
    __shared__ float As[BK][BM + 4];
    __shared__ float Bs[BK][BN + 4];
    const int m0 = blockIdx.y * BM, n0 = blockIdx.x * BN;
    const int t = threadIdx.x;
    const int tx = t & 15, ty = t >> 4;

    u64 acc[TM][TN / 2];
    #pragma unroll
    for (int i = 0; i < TM; i++)
        #pragma unroll
        for (int j = 0; j < TN / 2; j++) acc[i][j] = 0ull;

    for (int k0 = 0; k0 < K; k0 += BK) {
        // A tile 128x16, stored transposed As[k][m]
        #pragma unroll
        for (int i = 0; i < 2; i++) {
            int idx = t + i * 256;
            int r = idx >> 2, c4 = idx & 3;
            const float4 av = *reinterpret_cast<const float4*>(
                A + (size_t)(m0 + r) * lda + (k0 + c4 * 4));
            As[c4 * 4 + 0][r] = av.x; As[c4 * 4 + 1][r] = av.y;
            As[c4 * 4 + 2][r] = av.z; As[c4 * 4 + 3][r] = av.w;
        }
        // B tile
        if (TRANSB) {
            #pragma unroll
            for (int i = 0; i < BN / 64; i++) {
                int idx = t + i * 256;
                int n = idx >> 2, c4 = idx & 3;
                const float4 bv = *reinterpret_cast<const float4*>(
                    B + (size_t)(n0 + n) * ldb + (k0 + c4 * 4));
                Bs[c4 * 4 + 0][n] = bv.x; Bs[c4 * 4 + 1][n] = bv.y;
                Bs[c4 * 4 + 2][n] = bv.z; Bs[c4 * 4 + 3][n] = bv.w;
            }
        } else {
            #pragma unroll
            for (int i = 0; i < BN / 64; i++) {
                int idx = t + i * 256;
                int r = idx / (BN / 4), c = idx % (BN / 4);
                *reinterpret_cast<float4*>(&Bs[r][c * 4]) =
                    *reinterpret_cast<const float4*>(B + (size_t)(k0 + r) * ldb + n0 + c * 4);
            }
        }
        __syncthreads();
        #pragma unroll
        for (int kk = 0; kk < BK; kk++) {
            float ar[TM];
            *reinterpret_cast<float4*>(&ar[0]) =
                *reinterpret_cast<const float4*>(&As[kk][ty * TM]);
            *reinterpret_cast<float4*>(&ar[4]) =
                *reinterpret_cast<const float4*>(&As[kk][ty * TM + 4]);
            u64 br[TN / 2];
            const u64* bp = reinterpret_cast<const u64*>(&Bs[kk][tx * TN]);
            #pragma unroll
            for (int j = 0; j < TN / 2; j++) br[j] = bp[j];
            #pragma unroll
            for (int i = 0; i < TM; i++) {
                const u64 a2 = pack2(ar[i], ar[i]);
                #pragma unroll
                for (int j = 0; j < TN / 2; j++) ffma2(acc[i][j], a2, br[j]);
            }
        }
        __syncthreads();
    }
    #pragma unroll
    for (int i = 0; i < TM; i++) {
        int m = m0 + ty * TM + i;
        #pragma unroll
        for (int j4 = 0; j4 < TN / 4; j4++) {
            int n = n0 + tx * TN + j4 * 4;
            float4 cv;
            unpack2(acc[i][j4 * 2 + 0], cv.x, cv.y);
            unpack2(acc[i][j4 * 2 + 1], cv.z, cv.w);
            if constexpr (EPI == 1) {
                const float4 rv = *reinterpret_cast<const float4*>(
                    E + (size_t)m * ldc + n);
                cv.x += rv.x; cv.y += rv.y; cv.z += rv.z; cv.w += rv.w;
            } else if constexpr (EPI == 2) {
                const float4 bv = *reinterpret_cast<const float4*>(
                    E + ((size_t)zh * SEQ + m) * SEQ + n);
                cv.x += bv.x; cv.y += bv.y; cv.z += bv.z; cv.w += bv.w;
            }
            *reinterpret_cast<float4*>(C + (size_t)m * ldc + n) = cv;
        }
    }
}

// batched wrapper (z = b*8 + h)
template <int BN, int TN, int TRANSB, int EPI>
__global__ __launch_bounds__(256) void gemm_k(
    const float* __restrict__ A, int lda, size_t aSB, size_t aSH,
    const float* __restrict__ B, int ldb, size_t bSB, size_t bSH,
    float* __restrict__ C, int ldc, size_t cSB, size_t cSH,
    const float* __restrict__ E, int K)
{
    const int z = blockIdx.z;
    const int zb = z >> 3, zh = z & 7;
    A += (size_t)zb * aSB + (size_t)zh * aSH;
    B += (size_t)zb * bSB + (size_t)zh * bSH;
    const size_t cOff = (size_t)zb * cSB + (size_t)zh * cSH;
    C += cOff;
    const float* Ep = (EPI == 1) ? (E + cOff) : E;
    gemm_core<BN, TN, TRANSB, EPI>(A, lda, B, ldb, C, ldc, Ep, K, zh);
}

// multi-output wrapper: z selects (B, C) pair — fuses QKV (z=3) / FFN-in (z=2)
template <int BN, int TN>
__global__ __launch_bounds__(256) void gemm3_k(
    const float* __restrict__ A, int lda,
    const float* __restrict__ B0, const float* __restrict__ B1,
    const float* __restrict__ B2, int ldb,
    float* __restrict__ C0, float* __restrict__ C1, float* __restrict__ C2,
    int ldc, int K)
{
    const int z = blockIdx.z;
    const float* B = (z == 0) ? B0 : (z == 1) ? B1 : B2;
    float*       C = (z == 0) ? C0 : (z == 1) ? C1 : C2;
    gemm_core<BN, TN, 0, 0>(A, lda, B, ldb, C, ldc, nullptr, K, 0);
}

// ---------------- launch ----------------
extern "C" void kernel_launch(void* const* d_in, const int* in_sizes, int n_in,
                              void* d_out, int out_size) {
    const int*   ids    = (const int*)  d_in[0];
    const float* embed  = (const float*)d_in[1];
    const float* Wq     = (const float*)d_in[2];
    const float* Wk     = (const float*)d_in[3];
    const float* Wv     = (const float*)d_in[4];
    const float* Wo     = (const float*)d_in[5];
    const float* relb   = (const float*)d_in[6];
    const float* wi0    = (const float*)d_in[7];
    const float* wi1    = (const float*)d_in[8];
    const float* wo_ffn = (const float*)d_in[9];
    const float* ln0    = (const float*)d_in[10];
    const float* ln1    = (const float*)d_in[11];
    const float* flw    = (const float*)d_in[12];
    float* out = (float*)d_out;

    float *x, *h, *q, *k, *v, *o, *f0, *f1, *s, *bias;
    cudaGetSymbolAddress((void**)&x,  g_x);
    cudaGetSymbolAddress((void**)&h,  g_h);
    cudaGetSymbolAddress((void**)&q,  g_q);
    cudaGetSymbolAddress((void**)&k,  g_k);
    cudaGetSymbolAddress((void**)&v,  g_v);
    cudaGetSymbolAddress((void**)&o,  g_o);
    cudaGetSymbolAddress((void**)&f0, g_f0);
    cudaGetSymbolAddress((void**)&f1, g_f1);
    cudaGetSymbolAddress((void**)&s,  g_s);
    cudaGetSymbolAddress((void**)&bias, g_bias);

    float* out_bias = ((size_t)out_size > OUTX) ? (out + OUTX) : nullptr;

    embed_k<<<NROWS, 256>>>(ids, embed, x);
    {
        size_t nb = ((size_t)NH * SEQ * SEQ + 255) / 256;
        bias_k<<<(unsigned)nb, 256>>>(relb, bias, out_bias);
    }

    const size_t bhA = (size_t)SEQ * NH * DHEAD;   // per-batch stride in q/k/v/o
    const size_t bhS = (size_t)NH * SEQ * SEQ;     // per-batch stride in scores
    const size_t hS  = (size_t)SEQ * SEQ;          // per-head stride in scores

    for (int i = 0; i < NL; i++) {
        // ---- self attention ----
        rms_k<<<NROWS, 256>>>(x, ln0 + (size_t)i * DMODEL, h);
        // fused QKV: z in {0,1,2} selects weight/output
        dim3 gQKV3(DMODEL / 128, NROWS / 128, 3);
        gemm3_k<128, 8><<<gQKV3, 256>>>(h, DMODEL,
                                        Wq + (size_t)i * DMODEL * DMODEL,
                                        Wk + (size_t)i * DMODEL * DMODEL,
                                        Wv + (size_t)i * DMODEL * DMODEL, DMODEL,
                                        q, k, v, DMODEL, DMODEL);
        // scores[b,h,q,k] = Q @ K^T + pos_bias
        dim3 gS(SEQ / 128, SEQ / 128, BATCH * NH);
        gemm_k<128, 8, 1, 2><<<gS, 256>>>(q, NH * DHEAD, bhA, DHEAD,
                                          k, NH * DHEAD, bhA, DHEAD,
                                          s, SEQ, bhS, hS,
                                          bias, DHEAD);
        softmax_k<<<BATCH * NH * SEQ, 256>>>(s);
        // o = attn @ V
        dim3 gPV(1, SEQ / 128, BATCH * NH);
        gemm_k<64, 4, 0, 0><<<gPV, 256>>>(s, SEQ, bhS, hS,
                                          v, NH * DHEAD, bhA, DHEAD,
                                          o, NH * DHEAD, bhA, DHEAD,
                                          nullptr, SEQ);
        // x = x + o @ Wo
        dim3 gQKV(DMODEL / 128, NROWS / 128, 1);
        gemm_k<128, 8, 0, 1><<<gQKV, 256>>>(o, DMODEL, 0, 0,
                                            Wo + (size_t)i * DMODEL * DMODEL, DMODEL, 0, 0,
                                            x, DMODEL, 0, 0, x, DMODEL);
        // ---- gated-GELU FFN ----
        rms_k<<<NROWS, 256>>>(x, ln1 + (size_t)i * DMODEL, h);
        // fused FFN-in pair: z in {0,1}
        dim3 gFF2(DFF_ / 128, NROWS / 128, 2);
        gemm3_k<128, 8><<<gFF2, 256>>>(h, DMODEL,
                                       wi0 + (size_t)i * DMODEL * DFF_,
                                       wi1 + (size_t)i * DMODEL * DFF_,
                                       wi0 + (size_t)i * DMODEL * DFF_, DFF_,
                                       f0, f1, f0, DFF_, DMODEL);
        geglu_k<<<4096, 256>>>(f0, f1, NROWS * DFF_);
        // x = x + geglu @ wo_ffn   (K = DFF_)
        gemm_k<128, 8, 0, 1><<<gQKV, 256>>>(f0, DFF_, 0, 0,
                                            wo_ffn + (size_t)i * DFF_ * DMODEL, DMODEL, 0, 0,
                                            x, DMODEL, 0, 0,
                                            x, DFF_);
    }
    rms_k<<<NROWS, 256>>>(x, flw, out);
}

// round 5
// speedup vs baseline: 1.3390x; 1.2772x over previous
#include <cuda_runtime.h>
#include <cstdint>
#include <math.h>

#define NL    4
#define DMODEL 512
#define NH    8
#define DHEAD 64
#define DFF_  1024
#define SEQ   2048
#define BATCH 2
#define NROWS (BATCH*SEQ)          // 4096
#define OUTX  ((size_t)NROWS*DMODEL)  // 2097152

typedef unsigned long long u64;

// ---------------- scratch (static device memory; no allocation) ----------------
__device__ float g_x [NROWS*DMODEL];
__device__ float g_h [NROWS*DMODEL];
__device__ float g_q [NROWS*DMODEL];
__device__ float g_k [NROWS*DMODEL];
__device__ float g_v [NROWS*DMODEL];
__device__ float g_o [NROWS*DMODEL];
__device__ float g_f0[NROWS*DFF_];
__device__ float g_f1[NROWS*DFF_];
__device__ float g_s  [(size_t)BATCH*NH*SEQ*SEQ];  // 268 MB scores
__device__ float g_bias[(size_t)NH*SEQ*SEQ];       // 134 MB pos bias

// ---------------- f32x2 helpers ----------------
__device__ __forceinline__ u64 pack2(float lo, float hi) {
    u64 r; asm("mov.b64 %0, {%1, %2};" : "=l"(r) : "f"(lo), "f"(hi)); return r;
}
__device__ __forceinline__ void unpack2(u64 v, float& lo, float& hi) {
    asm("mov.b64 {%0, %1}, %2;" : "=f"(lo), "=f"(hi) : "l"(v));
}
__device__ __forceinline__ void ffma2(u64& d, u64 a, u64 b) {
    asm("fma.rn.f32x2 %0, %1, %2, %0;" : "+l"(d) : "l"(a), "l"(b));
}
union F4U { float4 f; u64 d[2]; };

// ---------------- embedding gather ----------------
__global__ __launch_bounds__(256) void embed_k(const int* __restrict__ ids,
                                               const float* __restrict__ emb,
                                               float* __restrict__ x) {
    const int row = blockIdx.x;
    const size_t src = (size_t)ids[row] * DMODEL;
    const size_t dst = (size_t)row * DMODEL;
    for (int i = threadIdx.x; i < DMODEL; i += 256) x[dst + i] = emb[src + i];
}

// ---------------- T5 relative position bias ----------------
__global__ __launch_bounds__(256) void bias_k(const float* __restrict__ rb,
                                              float* __restrict__ bias,
                                              float* __restrict__ out2) {
    size_t idx = (size_t)blockIdx.x * 256 + threadIdx.x;
    if (idx >= (size_t)NH * SEQ * SEQ) return;
    int kk = (int)(idx & (SEQ - 1));
    int qq = (int)((idx >> 11) & (SEQ - 1));
    int hh = (int)(idx >> 22);
    int rel = kk - qq;
    int bucket = (rel > 0) ? 16 : 0;
    int rp = (rel < 0) ? -rel : rel;
    int add;
    if (rp < 8) {
        add = rp;
    } else {
        float t = logf((float)rp / 8.0f);
        t = t / 2.7725887298583984f;   // float(math.log(16.0))
        t = t * 8.0f;
        add = 8 + (int)t;
        if (add > 15) add = 15;
    }
    float val = rb[(bucket + add) * NH + hh];
    bias[idx] = val;
    if (out2) out2[idx] = val;
}

// ---------------- T5 RMS layernorm ----------------
__global__ __launch_bounds__(256) void rms_k(const float* __restrict__ x,
                                             const float* __restrict__ w,
                                             float* __restrict__ y) {
    const size_t base = (size_t)blockIdx.x * DMODEL;
    const int t = threadIdx.x;
    float v0 = x[base + t], v1 = x[base + t + 256];
    float ss = v0 * v0 + v1 * v1;
    #pragma unroll
    for (int off = 16; off; off >>= 1) ss += __shfl_xor_sync(0xffffffffu, ss, off);
    __shared__ float red[8];
    __shared__ float bval;
    if ((t & 31) == 0) red[t >> 5] = ss;
    __syncthreads();
    if (t == 0) {
        float tot = 0.f;
        #pragma unroll
        for (int i = 0; i < 8; i++) tot += red[i];
        bval = rsqrtf(tot * (1.0f / DMODEL) + 1e-6f);
    }
    __syncthreads();
    const float inv = bval;
    y[base + t]       = w[t]       * (v0 * inv);
    y[base + t + 256] = w[t + 256] * (v1 * inv);
}

// ---------------- softmax over rows of 2048 ----------------
__global__ __launch_bounds__(256) void softmax_k(float* __restrict__ s) {
    float* p = s + (size_t)blockIdx.x * SEQ;
    const int t = threadIdx.x;
    float v[8];
    float mx = -3.402823466e38f;
    #pragma unroll
    for (int i = 0; i < 8; i++) { v[i] = p[t + i * 256]; mx = fmaxf(mx, v[i]); }
    #pragma unroll
    for (int off = 16; off; off >>= 1) mx = fmaxf(mx, __shfl_xor_sync(0xffffffffu, mx, off));
    __shared__ float red[8];
    __shared__ float bval;
    const int w = t >> 5, ln = t & 31;
    if (ln == 0) red[w] = mx;
    __syncthreads();
    if (t == 0) {
        float m = red[0];
        #pragma unroll
        for (int i = 1; i < 8; i++) m = fmaxf(m, red[i]);
        bval = m;
    }
    __syncthreads();
    mx = bval;
    float sum = 0.f;
    #pragma unroll
    for (int i = 0; i < 8; i++) { v[i] = expf(v[i] - mx); sum += v[i]; }
    #pragma unroll
    for (int off = 16; off; off >>= 1) sum += __shfl_xor_sync(0xffffffffu, sum, off);
    if (ln == 0) red[w] = sum;
    __syncthreads();
    if (t == 0) {
        float tot = 0.f;
        #pragma unroll
        for (int i = 0; i < 8; i++) tot += red[i];
        bval = 1.0f / tot;
    }
    __syncthreads();
    const float inv = bval;
    #pragma unroll
    for (int i = 0; i < 8; i++) p[t + i * 256] = v[i] * inv;
}

// ---------------- gated-GELU combine ----------------
__global__ __launch_bounds__(256) void geglu_k(float* __restrict__ f0,
                                               const float* __restrict__ f1, int n) {
    int i = blockIdx.x * blockDim.x + threadIdx.x;
    int stride = gridDim.x * blockDim.x;
    for (; i < n; i += stride) {
        float xx = f0[i];
        float inner = 0.7978845608028654f * (xx + 0.044715f * (xx * xx * xx));
        float g = 0.5f * xx * (1.0f + tanhf(inner));
        f0[i] = g * f1[i];
    }
}

// ---------------- tiled SGEMM core ----------------
// FFMA2 mainloop, split-B fragments (conflict-free LDS), double-buffered smem.
// C[M,N] = A[M,K] @ B  (+ epilogue)
// TRANSB=1: B stored [N,K]   TRANSB=0: B stored [K,N]
// EPI: 0 none, 1 residual add (E pre-offset, C layout), 2 pos-bias (E=[NH,SEQ,SEQ], head=zh)
// Thread (tx,ty), tx=t&15, ty=t>>4 owns rows ty*8..+7 and cols {s*64 + tx*4 .. +3} for s<TN/4.
template <int BN, int TN, int TRANSB, int EPI>
__device__ __forceinline__ void gemm_core(
    const float* __restrict__ A, int lda,
    const float* __restrict__ B, int ldb,
    float* __restrict__ C, int ldc,
    const float* __restrict__ E, int K, int zh)
{
    constexpr int BM = 128, BK = 16, TM = 8;
    constexpr int NS = TN / 4;            // column splits per thread (1 or 2)
    constexpr int NBL = BN / 64;          // B-tile float4 loads per thread
    __shared__ float As[2][BK][BM + 4];
    __shared__ float Bs[2][BK][BN + 4];
    const int m0 = blockIdx.y * BM, n0 = blockIdx.x * BN;
    const int t = threadIdx.x;
    const int tx = t & 15, ty = t >> 4;

    u64 acc[TM][TN / 2];
    #pragma unroll
    for (int i = 0; i < TM; i++)
        #pragma unroll
        for (int j = 0; j < TN / 2; j++) acc[i][j] = 0ull;

    float4 aReg[2];
    float4 bReg[NBL];

    auto loadG = [&](int k0) {
        #pragma unroll
        for (int i = 0; i < 2; i++) {
            int idx = t + i * 256;
            int r = idx >> 2, c4 = idx & 3;
            aReg[i] = *reinterpret_cast<const float4*>(
                A + (size_t)(m0 + r) * lda + (k0 + c4 * 4));
        }
        if (TRANSB) {
            #pragma unroll
            for (int i = 0; i < NBL; i++) {
                int idx = t + i * 256;
                int n = idx >> 2, c4 = idx & 3;
                bReg[i] = *reinterpret_cast<const float4*>(
                    B + (size_t)(n0 + n) * ldb + (k0 + c4 * 4));
            }
        } else {
            #pragma unroll
            for (int i = 0; i < NBL; i++) {
                int idx = t + i * 256;
                int r = idx / (BN / 4), c = idx % (BN / 4);
                bReg[i] = *reinterpret_cast<const float4*>(
                    B + (size_t)(k0 + r) * ldb + n0 + c * 4);
            }
        }
    };
    auto storeS = [&](int bf) {
        #pragma unroll
        for (int i = 0; i < 2; i++) {
            int idx = t + i * 256;
            int r = idx >> 2, c4 = idx & 3;
            As[bf][c4 * 4 + 0][r] = aReg[i].x;
            As[bf][c4 * 4 + 1][r] = aReg[i].y;
            As[bf][c4 * 4 + 2][r] = aReg[i].z;
            As[bf][c4 * 4 + 3][r] = aReg[i].w;
        }
        if (TRANSB) {
            #pragma unroll
            for (int i = 0; i < NBL; i++) {
                int idx = t + i * 256;
                int n = idx >> 2, c4 = idx & 3;
                Bs[bf][c4 * 4 + 0][n] = bReg[i].x;
                Bs[bf][c4 * 4 + 1][n] = bReg[i].y;
                Bs[bf][c4 * 4 + 2][n] = bReg[i].z;
                Bs[bf][c4 * 4 + 3][n] = bReg[i].w;
            }
        } else {
            #pragma unroll
            for (int i = 0; i < NBL; i++) {
                int idx = t + i * 256;
                int r = idx / (BN / 4), c = idx % (BN / 4);
                *reinterpret_cast<float4*>(&Bs[bf][r][c * 4]) = bReg[i];
            }
        }
    };

    loadG(0);
    storeS(0);
    __syncthreads();

    int buf = 0;
    for (int k0 = 0; k0 < K; k0 += BK) {
        const bool more = (k0 + BK) < K;
        if (more) loadG(k0 + BK);
        #pragma unroll
        for (int kk = 0; kk < BK; kk++) {
            float ar[TM];
            *reinterpret_cast<float4*>(&ar[0]) =
                *reinterpret_cast<const float4*>(&As[buf][kk][ty * TM]);
            *reinterpret_cast<float4*>(&ar[4]) =
                *reinterpret_cast<const float4*>(&As[buf][kk][ty * TM + 4]);
            u64 br[TN / 2];
            #pragma unroll
            for (int s = 0; s < NS; s++) {
                F4U bu;
                bu.f = *reinterpret_cast<const float4*>(&Bs[buf][kk][s * 64 + tx * 4]);
                br[s * 2 + 0] = bu.d[0];
                br[s * 2 + 1] = bu.d[1];
            }
            #pragma unroll
            for (int i = 0; i < TM; i++) {
                const u64 a2 = pack2(ar[i], ar[i]);
                #pragma unroll
                for (int j = 0; j < TN / 2; j++) ffma2(acc[i][j], a2, br[j]);
            }
        }
        if (more) {
            storeS(buf ^ 1);
            __syncthreads();
            buf ^= 1;
        }
    }

    #pragma unroll
    for (int i = 0; i < TM; i++) {
        int m = m0 + ty * TM + i;
        #pragma unroll
        for (int s = 0; s < NS; s++) {
            int n = n0 + s * 64 + tx * 4;
            float4 cv;
            unpack2(acc[i][s * 2 + 0], cv.x, cv.y);
            unpack2(acc[i][s * 2 + 1], cv.z, cv.w);
            if constexpr (EPI == 1) {
                const float4 rv = *reinterpret_cast<const float4*>(
                    E + (size_t)m * ldc + n);
                cv.x += rv.x; cv.y += rv.y; cv.z += rv.z; cv.w += rv.w;
            } else if constexpr (EPI == 2) {
                const float4 bv = *reinterpret_cast<const float4*>(
                    E + ((size_t)zh * SEQ + m) * SEQ + n);
                cv.x += bv.x; cv.y += bv.y; cv.z += bv.z; cv.w += bv.w;
            }
            *reinterpret_cast<float4*>(C + (size_t)m * ldc + n) = cv;
        }
    }
}

// batched wrapper (z = b*8 + h)
template <int BN, int TN, int TRANSB, int EPI>
__global__ __launch_bounds__(256, 2) void gemm_k(
    const float* __restrict__ A, int lda, size_t aSB, size_t aSH,
    const float* __restrict__ B, int ldb, size_t bSB, size_t bSH,
    float* __restrict__ C, int ldc, size_t cSB, size_t cSH,
    const float* __restrict__ E, int K)
{
    const int z = blockIdx.z;
    const int zb = z >> 3, zh = z & 7;
    A += (size_t)zb * aSB + (size_t)zh * aSH;
    B += (size_t)zb * bSB + (size_t)zh * bSH;
    const size_t cOff = (size_t)zb * cSB + (size_t)zh * cSH;
    C += cOff;
    const float* Ep = (EPI == 1) ? (E + cOff) : E;
    gemm_core<BN, TN, TRANSB, EPI>(A, lda, B, ldb, C, ldc, Ep, K, zh);
}

// multi-output wrapper: z selects (B, C) pair — fuses QKV (z=3) / FFN-in (z=2)
template <int BN, int TN>
__global__ __launch_bounds__(256, 2) void gemm3_k(
    const float* __restrict__ A, int lda,
    const float* __restrict__ B0, const float* __restrict__ B1,
    const float* __restrict__ B2, int ldb,
    float* __restrict__ C0, float* __restrict__ C1, float* __restrict__ C2,
    int ldc, int K)
{
    const int z = blockIdx.z;
    const float* B = (z == 0) ? B0 : (z == 1) ? B1 : B2;
    float*       C = (z == 0) ? C0 : (z == 1) ? C1 : C2;
    gemm_core<BN, TN, 0, 0>(A, lda, B, ldb, C, ldc, nullptr, K, 0);
}

// ---------------- launch ----------------
extern "C" void kernel_launch(void* const* d_in, const int* in_sizes, int n_in,
                              void* d_out, int out_size) {
    const int*   ids    = (const int*)  d_in[0];
    const float* embed  = (const float*)d_in[1];
    const float* Wq     = (const float*)d_in[2];
    const float* Wk     = (const float*)d_in[3];
    const float* Wv     = (const float*)d_in[4];
    const float* Wo     = (const float*)d_in[5];
    const float* relb   = (const float*)d_in[6];
    const float* wi0    = (const float*)d_in[7];
    const float* wi1    = (const float*)d_in[8];
    const float* wo_ffn = (const float*)d_in[9];
    const float* ln0    = (const float*)d_in[10];
    const float* ln1    = (const float*)d_in[11];
    const float* flw    = (const float*)d_in[12];
    float* out = (float*)d_out;

    float *x, *h, *q, *k, *v, *o, *f0, *f1, *s, *bias;
    cudaGetSymbolAddress((void**)&x,  g_x);
    cudaGetSymbolAddress((void**)&h,  g_h);
    cudaGetSymbolAddress((void**)&q,  g_q);
    cudaGetSymbolAddress((void**)&k,  g_k);
    cudaGetSymbolAddress((void**)&v,  g_v);
    cudaGetSymbolAddress((void**)&o,  g_o);
    cudaGetSymbolAddress((void**)&f0, g_f0);
    cudaGetSymbolAddress((void**)&f1, g_f1);
    cudaGetSymbolAddress((void**)&s,  g_s);
    cudaGetSymbolAddress((void**)&bias, g_bias);

    float* out_bias = ((size_t)out_size > OUTX) ? (out + OUTX) : nullptr;

    embed_k<<<NROWS, 256>>>(ids, embed, x);
    {
        size_t nb = ((size_t)NH * SEQ * SEQ + 255) / 256;
        bias_k<<<(unsigned)nb, 256>>>(relb, bias, out_bias);
    }

    const size_t bhA = (size_t)SEQ * NH * DHEAD;   // per-batch stride in q/k/v/o
    const size_t bhS = (size_t)NH * SEQ * SEQ;     // per-batch stride in scores
    const size_t hS  = (size_t)SEQ * SEQ;          // per-head stride in scores

    for (int i = 0; i < NL; i++) {
        // ---- self attention ----
        rms_k<<<NROWS, 256>>>(x, ln0 + (size_t)i * DMODEL, h);
        // fused QKV: z in {0,1,2} selects weight/output
        dim3 gQKV3(DMODEL / 128, NROWS / 128, 3);
        gemm3_k<128, 8><<<gQKV3, 256>>>(h, DMODEL,
                                        Wq + (size_t)i * DMODEL * DMODEL,
                                        Wk + (size_t)i * DMODEL * DMODEL,
                                        Wv + (size_t)i * DMODEL * DMODEL, DMODEL,
                                        q, k, v, DMODEL, DMODEL);
        // scores[b,h,q,k] = Q @ K^T + pos_bias
        dim3 gS(SEQ / 128, SEQ / 128, BATCH * NH);
        gemm_k<128, 8, 1, 2><<<gS, 256>>>(q, NH * DHEAD, bhA, DHEAD,
                                          k, NH * DHEAD, bhA, DHEAD,
                                          s, SEQ, bhS, hS,
                                          bias, DHEAD);
        softmax_k<<<BATCH * NH * SEQ, 256>>>(s);
        // o = attn @ V
        dim3 gPV(1, SEQ / 128, BATCH * NH);
        gemm_k<64, 4, 0, 0><<<gPV, 256>>>(s, SEQ, bhS, hS,
                                          v, NH * DHEAD, bhA, DHEAD,
                                          o, NH * DHEAD, bhA, DHEAD,
                                          nullptr, SEQ);
        // x = x + o @ Wo
        dim3 gQKV(DMODEL / 128, NROWS / 128, 1);
        gemm_k<128, 8, 0, 1><<<gQKV, 256>>>(o, DMODEL, 0, 0,
                                            Wo + (size_t)i * DMODEL * DMODEL, DMODEL, 0, 0,
                                            x, DMODEL, 0, 0, x, DMODEL);
        // ---- gated-GELU FFN ----
        rms_k<<<NROWS, 256>>>(x, ln1 + (size_t)i * DMODEL, h);
        // fused FFN-in pair: z in {0,1}
        dim3 gFF2(DFF_ / 128, NROWS / 128, 2);
        gemm3_k<128, 8><<<gFF2, 256>>>(h, DMODEL,
                                       wi0 + (size_t)i * DMODEL * DFF_,
                                       wi1 + (size_t)i * DMODEL * DFF_,
                                       wi0 + (size_t)i * DMODEL * DFF_, DFF_,
                                       f0, f1, f0, DFF_, DMODEL);
        geglu_k<<<4096, 256>>>(f0, f1, NROWS * DFF_);
        // x = x + geglu @ wo_ffn   (K = DFF_)
        gemm_k<128, 8, 0, 1><<<gQKV, 256>>>(f0, DFF_, 0, 0,
                                            wo_ffn + (size_t)i * DFF_ * DMODEL, DMODEL, 0, 0,
                                            x, DMODEL, 0, 0,
                                            x, DFF_);
    }
    rms_k<<<NROWS, 256>>>(x, flw, out);
}

// round 7
// speedup vs baseline: 1.6113x; 1.2034x over previous
#include <cuda_runtime.h>
#include <cuda_bf16.h>
#include <cstdint>
#include <math.h>

#define NL    4
#define DMODEL 512
#define NH    8
#define DHEAD 64
#define DFF_  1024
#define SEQ   2048
#define BATCH 2
#define NROWS (BATCH*SEQ)          // 4096
#define OUTX  ((size_t)NROWS*DMODEL)  // 2097152

typedef unsigned long long u64;

// ---------------- scratch ----------------
__device__ float g_x [NROWS*DMODEL];
__device__ float g_h [NROWS*DMODEL];
__device__ float g_q [NROWS*DMODEL];
__device__ float g_k [NROWS*DMODEL];
__device__ float g_v [NROWS*DMODEL];
__device__ float g_o [NROWS*DMODEL];
__device__ float g_f0[NROWS*DFF_];
__device__ float g_f1[NROWS*DFF_];
__device__ float g_s  [(size_t)BATCH*NH*SEQ*SEQ];  // scores
__device__ float g_bias[(size_t)NH*SEQ*SEQ];       // pos bias
// bf16 split buffers
__device__ __nv_bfloat16 g_ah[NROWS*DFF_];
__device__ __nv_bfloat16 g_al[NROWS*DFF_];
__device__ __nv_bfloat16 g_wh[DMODEL*DFF_*2];      // transposed weights hi
__device__ __nv_bfloat16 g_wl[DMODEL*DFF_*2];

// ---------------- helpers ----------------
__device__ __forceinline__ uint32_t smem_u32(const void* p) {
    uint32_t a;
    asm("{ .reg .u64 t; cvta.to.shared.u64 t, %1; cvt.u32.u64 %0, t; }" : "=r"(a) : "l"(p));
    return a;
}
__device__ __forceinline__ u64 pack2(float lo, float hi) {
    u64 r; asm("mov.b64 %0, {%1, %2};" : "=l"(r) : "f"(lo), "f"(hi)); return r;
}
__device__ __forceinline__ void unpack2(u64 v, float& lo, float& hi) {
    asm("mov.b64 {%0, %1}, %2;" : "=f"(lo), "=f"(hi) : "l"(v));
}
__device__ __forceinline__ void ffma2(u64& d, u64 a, u64 b) {
    asm("fma.rn.f32x2 %0, %1, %2, %0;" : "+l"(d) : "l"(a), "l"(b));
}
union F4U { float4 f; u64 d[2]; };

#define CP_ASYNC16(sa, ga) \
    asm volatile("cp.async.cg.shared.global [%0], [%1], 16;" :: "r"(sa), "l"(ga))
#define CP_COMMIT() asm volatile("cp.async.commit_group;" ::: "memory")
template <int N>
__device__ __forceinline__ void cp_wait() {
    asm volatile("cp.async.wait_group %0;" :: "n"(N) : "memory");
}
__device__ __forceinline__ void ldmx4(uint32_t* r, uint32_t addr) {
    asm volatile("ldmatrix.sync.aligned.m8n8.x4.shared.b16 {%0,%1,%2,%3}, [%4];"
                 : "=r"(r[0]), "=r"(r[1]), "=r"(r[2]), "=r"(r[3]) : "r"(addr));
}
__device__ __forceinline__ void mma16816(float* d, const uint32_t* a,
                                         uint32_t b0, uint32_t b1) {
    asm volatile(
        "mma.sync.aligned.m16n8k16.row.col.f32.bf16.bf16.f32 "
        "{%0,%1,%2,%3}, {%4,%5,%6,%7}, {%8,%9}, {%0,%1,%2,%3};"
        : "+f"(d[0]), "+f"(d[1]), "+f"(d[2]), "+f"(d[3])
        : "r"(a[0]), "r"(a[1]), "r"(a[2]), "r"(a[3]), "r"(b0), "r"(b1));
}

// ---------------- small kernels ----------------
__global__ __launch_bounds__(256) void embed_k(const int* __restrict__ ids,
                                               const float* __restrict__ emb,
                                               float* __restrict__ x) {
    const int row = blockIdx.x;
    const size_t src = (size_t)ids[row] * DMODEL;
    const size_t dst = (size_t)row * DMODEL;
    for (int i = threadIdx.x; i < DMODEL; i += 256) x[dst + i] = emb[src + i];
}

__global__ __launch_bounds__(256) void bias_k(const float* __restrict__ rb,
                                              float* __restrict__ bias,
                                              float* __restrict__ out2) {
    size_t idx = (size_t)blockIdx.x * 256 + threadIdx.x;
    if (idx >= (size_t)NH * SEQ * SEQ) return;
    int kk = (int)(idx & (SEQ - 1));
    int qq = (int)((idx >> 11) & (SEQ - 1));
    int hh = (int)(idx >> 22);
    int rel = kk - qq;
    int bucket = (rel > 0) ? 16 : 0;
    int rp = (rel < 0) ? -rel : rel;
    int add;
    if (rp < 8) {
        add = rp;
    } else {
        float t = logf((float)rp / 8.0f);
        t = t / 2.7725887298583984f;
        t = t * 8.0f;
        add = 8 + (int)t;
        if (add > 15) add = 15;
    }
    float val = rb[(bucket + add) * NH + hh];
    bias[idx] = val;
    if (out2) out2[idx] = val;
}

__global__ __launch_bounds__(256) void rms_k(const float* __restrict__ x,
                                             const float* __restrict__ w,
                                             float* __restrict__ y) {
    const size_t base = (size_t)blockIdx.x * DMODEL;
    const int t = threadIdx.x;
    float v0 = x[base + t], v1 = x[base + t + 256];
    float ss = v0 * v0 + v1 * v1;
    #pragma unroll
    for (int off = 16; off; off >>= 1) ss += __shfl_xor_sync(0xffffffffu, ss, off);
    __shared__ float red[8];
    __shared__ float bval;
    if ((t & 31) == 0) red[t >> 5] = ss;
    __syncthreads();
    if (t == 0) {
        float tot = 0.f;
        #pragma unroll
        for (int i = 0; i < 8; i++) tot += red[i];
        bval = rsqrtf(tot * (1.0f / DMODEL) + 1e-6f);
    }
    __syncthreads();
    const float inv = bval;
    y[base + t]       = w[t]       * (v0 * inv);
    y[base + t + 256] = w[t + 256] * (v1 * inv);
}

__global__ __launch_bounds__(256) void softmax_k(float* __restrict__ s) {
    float* p = s + (size_t)blockIdx.x * SEQ;
    const int t = threadIdx.x;
    float v[8];
    float mx = -3.402823466e38f;
    #pragma unroll
    for (int i = 0; i < 8; i++) { v[i] = p[t + i * 256]; mx = fmaxf(mx, v[i]); }
    #pragma unroll
    for (int off = 16; off; off >>= 1) mx = fmaxf(mx, __shfl_xor_sync(0xffffffffu, mx, off));
    __shared__ float red[8];
    __shared__ float bval;
    const int w = t >> 5, ln = t & 31;
    if (ln == 0) red[w] = mx;
    __syncthreads();
    if (t == 0) {
        float m = red[0];
        #pragma unroll
        for (int i = 1; i < 8; i++) m = fmaxf(m, red[i]);
        bval = m;
    }
    __syncthreads();
    mx = bval;
    float sum = 0.f;
    #pragma unroll
    for (int i = 0; i < 8; i++) { v[i] = expf(v[i] - mx); sum += v[i]; }
    #pragma unroll
    for (int off = 16; off; off >>= 1) sum += __shfl_xor_sync(0xffffffffu, sum, off);
    if (ln == 0) red[w] = sum;
    __syncthreads();
    if (t == 0) {
        float tot = 0.f;
        #pragma unroll
        for (int i = 0; i < 8; i++) tot += red[i];
        bval = 1.0f / tot;
    }
    __syncthreads();
    const float inv = bval;
    #pragma unroll
    for (int i = 0; i < 8; i++) p[t + i * 256] = v[i] * inv;
}

__global__ __launch_bounds__(256) void geglu_k(float* __restrict__ f0,
                                               const float* __restrict__ f1, int n) {
    int i = blockIdx.x * blockDim.x + threadIdx.x;
    int stride = gridDim.x * blockDim.x;
    for (; i < n; i += stride) {
        float xx = f0[i];
        float inner = 0.7978845608028654f * (xx + 0.044715f * (xx * xx * xx));
        float g = 0.5f * xx * (1.0f + tanhf(inner));
        f0[i] = g * f1[i];
    }
}

// ---------------- bf16 split conversions ----------------
__device__ __forceinline__ void split_bf16(float v, __nv_bfloat16& h, __nv_bfloat16& l) {
    h = __float2bfloat16(v);
    l = __float2bfloat16(v - __bfloat162float(h));
}
__global__ __launch_bounds__(256) void cvt_act_k(const float* __restrict__ x,
                                                 __nv_bfloat16* __restrict__ hi,
                                                 __nv_bfloat16* __restrict__ lo, int n) {
    int i = (blockIdx.x * 256 + threadIdx.x) * 4;
    if (i >= n) return;
    float4 v = *reinterpret_cast<const float4*>(x + i);
    __nv_bfloat16 h0, h1, h2, h3, l0, l1, l2, l3;
    split_bf16(v.x, h0, l0); split_bf16(v.y, h1, l1);
    split_bf16(v.z, h2, l2); split_bf16(v.w, h3, l3);
    __nv_bfloat162 hp0(h0, h1), hp1(h2, h3), lp0(l0, l1), lp1(l2, l3);
    uint2 H = make_uint2(*reinterpret_cast<uint32_t*>(&hp0), *reinterpret_cast<uint32_t*>(&hp1));
    uint2 L = make_uint2(*reinterpret_cast<uint32_t*>(&lp0), *reinterpret_cast<uint32_t*>(&lp1));
    *reinterpret_cast<uint2*>(hi + i) = H;
    *reinterpret_cast<uint2*>(lo + i) = L;
}
// W[K,N] f32 -> transposed Wt[N,K] hi/lo bf16
__global__ __launch_bounds__(256) void cvt_wt_k(const float* __restrict__ W,
                                                __nv_bfloat16* __restrict__ th,
                                                __nv_bfloat16* __restrict__ tl,
                                                int Kd, int Nd) {
    __shared__ float tile[32][33];
    int kb = blockIdx.y * 32, nb = blockIdx.x * 32;
    int tx = threadIdx.x & 31, ty = threadIdx.x >> 5;
    for (int r = ty; r < 32; r += 8)
        tile[r][tx] = W[(size_t)(kb + r) * Nd + nb + tx];
    __syncthreads();
    for (int r = ty; r < 32; r += 8) {
        float v = tile[tx][r];
        __nv_bfloat16 h, l;
        split_bf16(v, h, l);
        size_t oidx = (size_t)(nb + r) * Kd + kb + tx;
        th[oidx] = h;
        tl[oidx] = l;
    }
}

// ---------------- warp-MMA bf16x3 GEMM ----------------
// C[M,N] = A[M,K] @ Wt[N,K]^T, A/Wt pre-split bf16 hi/lo.
// CTA tile 128x128, BK=32, 8 warps (2x4), warp tile 64x32.
// smem per operand tile: 128 rows x 40 bf16 (80B stride); 4 tiles/buffer, 2 buffers.
#define MG_ROWB   80
#define MG_TILE   (128 * MG_ROWB)       // 10240
#define MG_BUF    (4 * MG_TILE)         // 40960
#define MG_SMEM   (2 * MG_BUF)          // 81920
template <int EPI>
__global__ __launch_bounds__(256) void mgemm_k(
    const __nv_bfloat16* __restrict__ ah, const __nv_bfloat16* __restrict__ al,
    const __nv_bfloat16* __restrict__ wh, const __nv_bfloat16* __restrict__ wl,
    float* C0, float* C1, float* C2,
    const float* __restrict__ E, int K, int ldc, size_t wSlot)
{
    extern __shared__ char smem[];
    const uint32_t sb = smem_u32(smem);
    const int t = threadIdx.x;
    const int lane = t & 31, wid = t >> 5;
    const int wr = wid & 1, wc = wid >> 1;     // warp: m-half(64), n-quarter(32)
    const int z = blockIdx.z;
    const __nv_bfloat16* Bh = wh + (size_t)z * wSlot;
    const __nv_bfloat16* Bl = wl + (size_t)z * wSlot;
    float* C = (z == 0) ? C0 : (z == 1) ? C1 : C2;
    const int m0 = blockIdx.y * 128, n0 = blockIdx.x * 128;

    float d[4][4][4];
    #pragma unroll
    for (int mi = 0; mi < 4; mi++)
        #pragma unroll
        for (int nj = 0; nj < 4; nj++)
            #pragma unroll
            for (int r = 0; r < 4; r++) d[mi][nj][r] = 0.f;

    const int lr = t >> 2;        // 0..63
    const int lc = t & 3;         // 16B chunk within 32-k
    const __nv_bfloat16* srcs[4] = { ah, al, Bh, Bl };

    auto issue = [&](int kc, int buf) {
        const uint32_t base = sb + buf * MG_BUF;
        #pragma unroll
        for (int tile = 0; tile < 4; tile++) {
            const __nv_bfloat16* s = srcs[tile];
            const int baseRow = (tile < 2) ? m0 : n0;
            #pragma unroll
            for (int h = 0; h < 2; h++) {
                const int row = lr + h * 64;
                const __nv_bfloat16* g = s + (size_t)(baseRow + row) * K + kc * 32 + lc * 8;
                const uint32_t sa = base + tile * MG_TILE + row * MG_ROWB + lc * 16;
                CP_ASYNC16(sa, g);
            }
        }
        CP_COMMIT();
    };

    const int nch = K >> 5;
    issue(0, 0);

    const int mat = lane >> 3, l8 = lane & 7;
    for (int kc = 0; kc < nch; kc++) {
        const int buf = kc & 1;
        if (kc + 1 < nch) { issue(kc + 1, buf ^ 1); cp_wait<1>(); }
        else              { cp_wait<0>(); }
        __syncthreads();
        const uint32_t bbase = sb + buf * MG_BUF;
        #pragma unroll
        for (int kk = 0; kk < 2; kk++) {
            uint32_t Ah[4][4], Al[4][4], Bhf[2][4], Blf[2][4];
            #pragma unroll
            for (int mi = 0; mi < 4; mi++) {
                const int row = wr * 64 + mi * 16 + (mat & 1) * 8 + l8;
                const uint32_t ad = bbase + row * MG_ROWB + kk * 32 + (mat >> 1) * 16;
                ldmx4(Ah[mi], ad);
                ldmx4(Al[mi], ad + MG_TILE);
            }
            #pragma unroll
            for (int nj2 = 0; nj2 < 2; nj2++) {
                const int n = wc * 32 + nj2 * 16 + (mat >> 1) * 8 + l8;
                const uint32_t bd = bbase + 2 * MG_TILE + n * MG_ROWB + kk * 32 + (mat & 1) * 16;
                ldmx4(Bhf[nj2], bd);
                ldmx4(Blf[nj2], bd + MG_TILE);
            }
            #pragma unroll
            for (int mi = 0; mi < 4; mi++)
                #pragma unroll
                for (int nj = 0; nj < 4; nj++) {
                    const int g = nj >> 1, o = (nj & 1) * 2;
                    mma16816(d[mi][nj], Ah[mi], Bhf[g][o], Bhf[g][o + 1]);
                    mma16816(d[mi][nj], Ah[mi], Blf[g][o], Blf[g][o + 1]);
                    mma16816(d[mi][nj], Al[mi], Bhf[g][o], Bhf[g][o + 1]);
                }
        }
        __syncthreads();
    }

    // epilogue: d0/d1 -> row (lane>>2), cols 2*(lane&3)+{0,1}; d2/d3 -> row+8
    #pragma unroll
    for (int mi = 0; mi < 4; mi++) {
        #pragma unroll
        for (int nj = 0; nj < 4; nj++) {
            const int row = m0 + wr * 64 + mi * 16 + (lane >> 2);
            const int col = n0 + wc * 32 + nj * 8 + (lane & 3) * 2;
            #pragma unroll
            for (int hh = 0; hh < 2; hh++) {
                const int m = row + hh * 8;
                float2 cv = make_float2(d[mi][nj][hh * 2], d[mi][nj][hh * 2 + 1]);
                if constexpr (EPI == 1) {
                    const float2 rv = *reinterpret_cast<const float2*>(
                        E + (size_t)m * ldc + col);
                    cv.x += rv.x; cv.y += rv.y;
                }
                *reinterpret_cast<float2*>(C + (size_t)m * ldc + col) = cv;
            }
        }
    }
}

// ---------------- SIMT SGEMM (attention: scores + PV) ----------------
template <int BN, int TN, int TRANSB, int EPI>
__device__ __forceinline__ void gemm_core(
    const float* __restrict__ A, int lda,
    const float* __restrict__ B, int ldb,
    float* __restrict__ C, int ldc,
    const float* __restrict__ E, int K, int zh)
{
    constexpr int BM = 128, BK = 16, TM = 8;
    constexpr int NS = TN / 4;
    constexpr int NBL = BN / 64;
    __shared__ float As[2][BK][BM + 4];
    __shared__ float Bs[2][BK][BN + 4];
    const int m0 = blockIdx.y * BM, n0 = blockIdx.x * BN;
    const int t = threadIdx.x;
    const int tx = t & 15, ty = t >> 4;

    u64 acc[TM][TN / 2];
    #pragma unroll
    for (int i = 0; i < TM; i++)
        #pragma unroll
        for (int j = 0; j < TN / 2; j++) acc[i][j] = 0ull;

    float4 aReg[2];
    float4 bReg[NBL];

    auto loadG = [&](int k0) {
        #pragma unroll
        for (int i = 0; i < 2; i++) {
            int idx = t + i * 256;
            int r = idx >> 2, c4 = idx & 3;
            aReg[i] = *reinterpret_cast<const float4*>(
                A + (size_t)(m0 + r) * lda + (k0 + c4 * 4));
        }
        if (TRANSB) {
            #pragma unroll
            for (int i = 0; i < NBL; i++) {
                int idx = t + i * 256;
                int n = idx >> 2, c4 = idx & 3;
                bReg[i] = *reinterpret_cast<const float4*>(
                    B + (size_t)(n0 + n) * ldb + (k0 + c4 * 4));
            }
        } else {
            #pragma unroll
            for (int i = 0; i < NBL; i++) {
                int idx = t + i * 256;
                int r = idx / (BN / 4), c = idx % (BN / 4);
                bReg[i] = *reinterpret_cast<const float4*>(
                    B + (size_t)(k0 + r) * ldb + n0 + c * 4);
            }
        }
    };
    auto storeS = [&](int bf) {
        #pragma unroll
        for (int i = 0; i < 2; i++) {
            int idx = t + i * 256;
            int r = idx >> 2, c4 = idx & 3;
            As[bf][c4 * 4 + 0][r] = aReg[i].x;
            As[bf][c4 * 4 + 1][r] = aReg[i].y;
            As[bf][c4 * 4 + 2][r] = aReg[i].z;
            As[bf][c4 * 4 + 3][r] = aReg[i].w;
        }
        if (TRANSB) {
            #pragma unroll
            for (int i = 0; i < NBL; i++) {
                int idx = t + i * 256;
                int n = idx >> 2, c4 = idx & 3;
                Bs[bf][c4 * 4 + 0][n] = bReg[i].x;
                Bs[bf][c4 * 4 + 1][n] = bReg[i].y;
                Bs[bf][c4 * 4 + 2][n] = bReg[i].z;
                Bs[bf][c4 * 4 + 3][n] = bReg[i].w;
            }
        } else {
            #pragma unroll
            for (int i = 0; i < NBL; i++) {
                int idx = t + i * 256;
                int r = idx / (BN / 4), c = idx % (BN / 4);
                *reinterpret_cast<float4*>(&Bs[bf][r][c * 4]) = bReg[i];
            }
        }
    };

    loadG(0);
    storeS(0);
    __syncthreads();

    int buf = 0;
    for (int k0 = 0; k0 < K; k0 += BK) {
        const bool more = (k0 + BK) < K;
        if (more) loadG(k0 + BK);
        #pragma unroll
        for (int kk = 0; kk < BK; kk++) {
            float ar[TM];
            *reinterpret_cast<float4*>(&ar[0]) =
                *reinterpret_cast<const float4*>(&As[buf][kk][ty * TM]);
            *reinterpret_cast<float4*>(&ar[4]) =
                *reinterpret_cast<const float4*>(&As[buf][kk][ty * TM + 4]);
            u64 br[TN / 2];
            #pragma unroll
            for (int s = 0; s < NS; s++) {
                F4U bu;
                bu.f = *reinterpret_cast<const float4*>(&Bs[buf][kk][s * 64 + tx * 4]);
                br[s * 2 + 0] = bu.d[0];
                br[s * 2 + 1] = bu.d[1];
            }
            #pragma unroll
            for (int i = 0; i < TM; i++) {
                const u64 a2 = pack2(ar[i], ar[i]);
                #pragma unroll
                for (int j = 0; j < TN / 2; j++) ffma2(acc[i][j], a2, br[j]);
            }
        }
        if (more) {
            storeS(buf ^ 1);
            __syncthreads();
            buf ^= 1;
        }
    }

    #pragma unroll
    for (int i = 0; i < TM; i++) {
        int m = m0 + ty * TM + i;
        #pragma unroll
        for (int s = 0; s < NS; s++) {
            int n = n0 + s * 64 + tx * 4;
            float4 cv;
            unpack2(acc[i][s * 2 + 0], cv.x, cv.y);
            unpack2(acc[i][s * 2 + 1], cv.z, cv.w);
            if constexpr (EPI == 1) {
                const float4 rv = *reinterpret_cast<const float4*>(
                    E + (size_t)m * ldc + n);
                cv.x += rv.x; cv.y += rv.y; cv.z += rv.z; cv.w += rv.w;
            } else if constexpr (EPI == 2) {
                const float4 bv = *reinterpret_cast<const float4*>(
                    E + ((size_t)zh * SEQ + m) * SEQ + n);
                cv.x += bv.x; cv.y += bv.y; cv.z += bv.z; cv.w += bv.w;
            }
            *reinterpret_cast<float4*>(C + (size_t)m * ldc + n) = cv;
        }
    }
}

template <int BN, int TN, int TRANSB, int EPI>
__global__ __launch_bounds__(256, 2) void gemm_k(
    const float* __restrict__ A, int lda, size_t aSB, size_t aSH,
    const float* __restrict__ B, int ldb, size_t bSB, size_t bSH,
    float* __restrict__ C, int ldc, size_t cSB, size_t cSH,
    const float* __restrict__ E, int K)
{
    const int z = blockIdx.z;
    const int zb = z >> 3, zh = z & 7;
    A += (size_t)zb * aSB + (size_t)zh * aSH;
    B += (size_t)zb * bSB + (size_t)zh * bSH;
    const size_t cOff = (size_t)zb * cSB + (size_t)zh * cSH;
    C += cOff;
    const float* Ep = (EPI == 1) ? (E + cOff) : E;
    gemm_core<BN, TN, TRANSB, EPI>(A, lda, B, ldb, C, ldc, Ep, K, zh);
}

// ---------------- launch ----------------
extern "C" void kernel_launch(void* const* d_in, const int* in_sizes, int n_in,
                              void* d_out, int out_size) {
    const int*   ids    = (const int*)  d_in[0];
    const float* embed  = (const float*)d_in[1];
    const float* Wq     = (const float*)d_in[2];
    const float* Wk     = (const float*)d_in[3];
    const float* Wv     = (const float*)d_in[4];
    const float* Wo     = (const float*)d_in[5];
    const float* relb   = (const float*)d_in[6];
    const float* wi0    = (const float*)d_in[7];
    const float* wi1    = (const float*)d_in[8];
    const float* wo_ffn = (const float*)d_in[9];
    const float* ln0    = (const float*)d_in[10];
    const float* ln1    = (const float*)d_in[11];
    const float* flw    = (const float*)d_in[12];
    float* out = (float*)d_out;

    float *x, *h, *q, *k, *v, *o, *f0, *f1, *s, *bias;
    __nv_bfloat16 *ah, *al, *wh, *wl;
    cudaGetSymbolAddress((void**)&x,  g_x);
    cudaGetSymbolAddress((void**)&h,  g_h);
    cudaGetSymbolAddress((void**)&q,  g_q);
    cudaGetSymbolAddress((void**)&k,  g_k);
    cudaGetSymbolAddress((void**)&v,  g_v);
    cudaGetSymbolAddress((void**)&o,  g_o);
    cudaGetSymbolAddress((void**)&f0, g_f0);
    cudaGetSymbolAddress((void**)&f1, g_f1);
    cudaGetSymbolAddress((void**)&s,  g_s);
    cudaGetSymbolAddress((void**)&bias, g_bias);
    cudaGetSymbolAddress((void**)&ah, g_ah);
    cudaGetSymbolAddress((void**)&al, g_al);
    cudaGetSymbolAddress((void**)&wh, g_wh);
    cudaGetSymbolAddress((void**)&wl, g_wl);

    cudaFuncSetAttribute(mgemm_k<0>, cudaFuncAttributeMaxDynamicSharedMemorySize, MG_SMEM);
    cudaFuncSetAttribute(mgemm_k<1>, cudaFuncAttributeMaxDynamicSharedMemorySize, MG_SMEM);

    float* out_bias = ((size_t)out_size > OUTX) ? (out + OUTX) : nullptr;

    embed_k<<<NROWS, 256>>>(ids, embed, x);
    {
        size_t nb = ((size_t)NH * SEQ * SEQ + 255) / 256;
        bias_k<<<(unsigned)nb, 256>>>(relb, bias, out_bias);
    }

    const size_t bhA = (size_t)SEQ * NH * DHEAD;
    const size_t bhS = (size_t)NH * SEQ * SEQ;
    const size_t hS  = (size_t)SEQ * SEQ;
    const size_t DD  = (size_t)DMODEL * DMODEL;
    const size_t DF  = (size_t)DMODEL * DFF_;

    for (int i = 0; i < NL; i++) {
        // ---- self attention ----
        rms_k<<<NROWS, 256>>>(x, ln0 + (size_t)i * DMODEL, h);
        cvt_act_k<<<NROWS * DMODEL / 1024, 256>>>(h, ah, al, NROWS * DMODEL);
        {
            dim3 gW(DMODEL / 32, DMODEL / 32);
            cvt_wt_k<<<gW, 256>>>(Wq + i * DD, wh,          wl,          DMODEL, DMODEL);
            cvt_wt_k<<<gW, 256>>>(Wk + i * DD, wh + DD,     wl + DD,     DMODEL, DMODEL);
            cvt_wt_k<<<gW, 256>>>(Wv + i * DD, wh + 2 * DD, wl + 2 * DD, DMODEL, DMODEL);
        }
        mgemm_k<0><<<dim3(4, 32, 3), 256, MG_SMEM>>>(ah, al, wh, wl,
                                                     q, k, v, nullptr,
                                                     DMODEL, DMODEL, DD);
        // scores + softmax + PV (SIMT)
        dim3 gS(SEQ / 128, SEQ / 128, BATCH * NH);
        gemm_k<128, 8, 1, 2><<<gS, 256>>>(q, NH * DHEAD, bhA, DHEAD,
                                          k, NH * DHEAD, bhA, DHEAD,
                                          s, SEQ, bhS, hS,
                                          bias, DHEAD);
        softmax_k<<<BATCH * NH * SEQ, 256>>>(s);
        dim3 gPV(1, SEQ / 128, BATCH * NH);
        gemm_k<64, 4, 0, 0><<<gPV, 256>>>(s, SEQ, bhS, hS,
                                          v, NH * DHEAD, bhA, DHEAD,
                                          o, NH * DHEAD, bhA, DHEAD,
                                          nullptr, SEQ);
        // x = x + o @ Wo
        cvt_act_k<<<NROWS * DMODEL / 1024, 256>>>(o, ah, al, NROWS * DMODEL);
        cvt_wt_k<<<dim3(DMODEL / 32, DMODEL / 32), 256>>>(Wo + i * DD, wh, wl, DMODEL, DMODEL);
        mgemm_k<1><<<dim3(4, 32, 1), 256, MG_SMEM>>>(ah, al, wh, wl,
                                                     x, x, x, x,
                                                     DMODEL, DMODEL, 0);
        // ---- gated-GELU FFN ----
        rms_k<<<NROWS, 256>>>(x, ln1 + (size_t)i * DMODEL, h);
        cvt_act_k<<<NROWS * DMODEL / 1024, 256>>>(h, ah, al, NROWS * DMODEL);
        {
            dim3 gW(DFF_ / 32, DMODEL / 32);
            cvt_wt_k<<<gW, 256>>>(wi0 + i * DF, wh,      wl,      DMODEL, DFF_);
            cvt_wt_k<<<gW, 256>>>(wi1 + i * DF, wh + DF, wl + DF, DMODEL, DFF_);
        }
        mgemm_k<0><<<dim3(8, 32, 2), 256, MG_SMEM>>>(ah, al, wh, wl,
                                                     f0, f1, f1, nullptr,
                                                     DMODEL, DFF_, DF);
        geglu_k<<<4096, 256>>>(f0, f1, NROWS * DFF_);
        cvt_act_k<<<NROWS * DFF_ / 1024, 256>>>(f0, ah, al, NROWS * DFF_);
        cvt_wt_k<<<dim3(DMODEL / 32, DFF_ / 32), 256>>>(wo_ffn + i * DF, wh, wl, DFF_, DMODEL);
        mgemm_k<1><<<dim3(4, 32, 1), 256, MG_SMEM>>>(ah, al, wh, wl,
                                                     x, x, x, x,
                                                     DFF_, DMODEL, 0);
    }
    rms_k<<<NROWS, 256>>>(x, flw, out);
}

// round 8
// speedup vs baseline: 1.9147x; 1.1883x over previous
#include <cuda_runtime.h>
#include <cuda_bf16.h>
#include <cstdint>
#include <math.h>

#define NL    4
#define DMODEL 512
#define NH    8
#define DHEAD 64
#define DFF_  1024
#define SEQ   2048
#define BATCH 2
#define NROWS (BATCH*SEQ)          // 4096
#define OUTX  ((size_t)NROWS*DMODEL)  // 2097152

typedef unsigned long long u64;

// ---------------- scratch ----------------
__device__ float g_x [NROWS*DMODEL];
__device__ float g_h [NROWS*DMODEL];
__device__ float g_q [NROWS*DMODEL];
__device__ float g_k [NROWS*DMODEL];
__device__ float g_v [NROWS*DMODEL];
__device__ float g_o [NROWS*DMODEL];
__device__ float g_f0[NROWS*DFF_];
__device__ float g_f1[NROWS*DFF_];
__device__ float g_s  [(size_t)BATCH*NH*SEQ*SEQ];          // f32 scores
__device__ __nv_bfloat16 g_sh[(size_t)BATCH*NH*SEQ*SEQ];   // attn hi
__device__ __nv_bfloat16 g_sl[(size_t)BATCH*NH*SEQ*SEQ];   // attn lo
__device__ float g_bias[(size_t)NH*SEQ*SEQ];               // pos bias
// bf16 split buffers
__device__ __nv_bfloat16 g_ah[NROWS*DFF_];
__device__ __nv_bfloat16 g_al[NROWS*DFF_];
__device__ __nv_bfloat16 g_wh[DMODEL*DFF_*2];
__device__ __nv_bfloat16 g_wl[DMODEL*DFF_*2];
__device__ __nv_bfloat16 g_vth[(size_t)BATCH*NH*DHEAD*SEQ]; // V^T hi [B,H,DH,S]
__device__ __nv_bfloat16 g_vtl[(size_t)BATCH*NH*DHEAD*SEQ];

// ---------------- helpers ----------------
__device__ __forceinline__ uint32_t smem_u32(const void* p) {
    uint32_t a;
    asm("{ .reg .u64 t; cvta.to.shared.u64 t, %1; cvt.u32.u64 %0, t; }" : "=r"(a) : "l"(p));
    return a;
}
#define CP_ASYNC16(sa, ga) \
    asm volatile("cp.async.cg.shared.global [%0], [%1], 16;" :: "r"(sa), "l"(ga))
#define CP_COMMIT() asm volatile("cp.async.commit_group;" ::: "memory")
template <int N>
__device__ __forceinline__ void cp_wait() {
    asm volatile("cp.async.wait_group %0;" :: "n"(N) : "memory");
}
__device__ __forceinline__ void ldmx4(uint32_t* r, uint32_t addr) {
    asm volatile("ldmatrix.sync.aligned.m8n8.x4.shared.b16 {%0,%1,%2,%3}, [%4];"
                 : "=r"(r[0]), "=r"(r[1]), "=r"(r[2]), "=r"(r[3]) : "r"(addr));
}
__device__ __forceinline__ void mma16816(float* d, const uint32_t* a,
                                         uint32_t b0, uint32_t b1) {
    asm volatile(
        "mma.sync.aligned.m16n8k16.row.col.f32.bf16.bf16.f32 "
        "{%0,%1,%2,%3}, {%4,%5,%6,%7}, {%8,%9}, {%0,%1,%2,%3};"
        : "+f"(d[0]), "+f"(d[1]), "+f"(d[2]), "+f"(d[3])
        : "r"(a[0]), "r"(a[1]), "r"(a[2]), "r"(a[3]), "r"(b0), "r"(b1));
}

// ---------------- small kernels ----------------
__global__ __launch_bounds__(256) void embed_k(const int* __restrict__ ids,
                                               const float* __restrict__ emb,
                                               float* __restrict__ x) {
    const int row = blockIdx.x;
    const size_t src = (size_t)ids[row] * DMODEL;
    const size_t dst = (size_t)row * DMODEL;
    for (int i = threadIdx.x; i < DMODEL; i += 256) x[dst + i] = emb[src + i];
}

__global__ __launch_bounds__(256) void bias_k(const float* __restrict__ rb,
                                              float* __restrict__ bias,
                                              float* __restrict__ out2) {
    size_t idx = (size_t)blockIdx.x * 256 + threadIdx.x;
    if (idx >= (size_t)NH * SEQ * SEQ) return;
    int kk = (int)(idx & (SEQ - 1));
    int qq = (int)((idx >> 11) & (SEQ - 1));
    int hh = (int)(idx >> 22);
    int rel = kk - qq;
    int bucket = (rel > 0) ? 16 : 0;
    int rp = (rel < 0) ? -rel : rel;
    int add;
    if (rp < 8) {
        add = rp;
    } else {
        float t = logf((float)rp / 8.0f);
        t = t / 2.7725887298583984f;
        t = t * 8.0f;
        add = 8 + (int)t;
        if (add > 15) add = 15;
    }
    float val = rb[(bucket + add) * NH + hh];
    bias[idx] = val;
    if (out2) out2[idx] = val;
}

__global__ __launch_bounds__(256) void rms_k(const float* __restrict__ x,
                                             const float* __restrict__ w,
                                             float* __restrict__ y) {
    const size_t base = (size_t)blockIdx.x * DMODEL;
    const int t = threadIdx.x;
    float v0 = x[base + t], v1 = x[base + t + 256];
    float ss = v0 * v0 + v1 * v1;
    #pragma unroll
    for (int off = 16; off; off >>= 1) ss += __shfl_xor_sync(0xffffffffu, ss, off);
    __shared__ float red[8];
    __shared__ float bval;
    if ((t & 31) == 0) red[t >> 5] = ss;
    __syncthreads();
    if (t == 0) {
        float tot = 0.f;
        #pragma unroll
        for (int i = 0; i < 8; i++) tot += red[i];
        bval = rsqrtf(tot * (1.0f / DMODEL) + 1e-6f);
    }
    __syncthreads();
    const float inv = bval;
    y[base + t]       = w[t]       * (v0 * inv);
    y[base + t + 256] = w[t + 256] * (v1 * inv);
}

// softmax over rows of 2048; emits attn as bf16 hi/lo split
__global__ __launch_bounds__(256) void softmax_k(const float* __restrict__ s,
                                                 __nv_bfloat16* __restrict__ sh,
                                                 __nv_bfloat16* __restrict__ sl) {
    const size_t base = (size_t)blockIdx.x * SEQ;
    const float* p = s + base;
    const int t = threadIdx.x;
    float v[8];
    float mx = -3.402823466e38f;
    #pragma unroll
    for (int i = 0; i < 8; i++) { v[i] = p[t + i * 256]; mx = fmaxf(mx, v[i]); }
    #pragma unroll
    for (int off = 16; off; off >>= 1) mx = fmaxf(mx, __shfl_xor_sync(0xffffffffu, mx, off));
    __shared__ float red[8];
    __shared__ float bval;
    const int w = t >> 5, ln = t & 31;
    if (ln == 0) red[w] = mx;
    __syncthreads();
    if (t == 0) {
        float m = red[0];
        #pragma unroll
        for (int i = 1; i < 8; i++) m = fmaxf(m, red[i]);
        bval = m;
    }
    __syncthreads();
    mx = bval;
    float sum = 0.f;
    #pragma unroll
    for (int i = 0; i < 8; i++) { v[i] = expf(v[i] - mx); sum += v[i]; }
    #pragma unroll
    for (int off = 16; off; off >>= 1) sum += __shfl_xor_sync(0xffffffffu, sum, off);
    if (ln == 0) red[w] = sum;
    __syncthreads();
    if (t == 0) {
        float tot = 0.f;
        #pragma unroll
        for (int i = 0; i < 8; i++) tot += red[i];
        bval = 1.0f / tot;
    }
    __syncthreads();
    const float inv = bval;
    #pragma unroll
    for (int i = 0; i < 8; i++) {
        float pv = v[i] * inv;
        __nv_bfloat16 hh = __float2bfloat16(pv);
        __nv_bfloat16 ll = __float2bfloat16(pv - __bfloat162float(hh));
        sh[base + t + i * 256] = hh;
        sl[base + t + i * 256] = ll;
    }
}

__global__ __launch_bounds__(256) void geglu_k(float* __restrict__ f0,
                                               const float* __restrict__ f1, int n) {
    int i = blockIdx.x * blockDim.x + threadIdx.x;
    int stride = gridDim.x * blockDim.x;
    for (; i < n; i += stride) {
        float xx = f0[i];
        float inner = 0.7978845608028654f * (xx + 0.044715f * (xx * xx * xx));
        float g = 0.5f * xx * (1.0f + tanhf(inner));
        f0[i] = g * f1[i];
    }
}

// ---------------- bf16 split conversions ----------------
__device__ __forceinline__ void split_bf16(float v, __nv_bfloat16& h, __nv_bfloat16& l) {
    h = __float2bfloat16(v);
    l = __float2bfloat16(v - __bfloat162float(h));
}
__global__ __launch_bounds__(256) void cvt_act_k(const float* __restrict__ x,
                                                 __nv_bfloat16* __restrict__ hi,
                                                 __nv_bfloat16* __restrict__ lo, int n) {
    int i = (blockIdx.x * 256 + threadIdx.x) * 4;
    if (i >= n) return;
    float4 v = *reinterpret_cast<const float4*>(x + i);
    __nv_bfloat16 h0, h1, h2, h3, l0, l1, l2, l3;
    split_bf16(v.x, h0, l0); split_bf16(v.y, h1, l1);
    split_bf16(v.z, h2, l2); split_bf16(v.w, h3, l3);
    __nv_bfloat162 hp0(h0, h1), hp1(h2, h3), lp0(l0, l1), lp1(l2, l3);
    uint2 H = make_uint2(*reinterpret_cast<uint32_t*>(&hp0), *reinterpret_cast<uint32_t*>(&hp1));
    uint2 L = make_uint2(*reinterpret_cast<uint32_t*>(&lp0), *reinterpret_cast<uint32_t*>(&lp1));
    *reinterpret_cast<uint2*>(hi + i) = H;
    *reinterpret_cast<uint2*>(lo + i) = L;
}
// W[K,N] f32 -> transposed Wt[N,K] hi/lo bf16
__global__ __launch_bounds__(256) void cvt_wt_k(const float* __restrict__ W,
                                                __nv_bfloat16* __restrict__ th,
                                                __nv_bfloat16* __restrict__ tl,
                                                int Kd, int Nd) {
    __shared__ float tile[32][33];
    int kb = blockIdx.y * 32, nb = blockIdx.x * 32;
    int tx = threadIdx.x & 31, ty = threadIdx.x >> 5;
    for (int r = ty; r < 32; r += 8)
        tile[r][tx] = W[(size_t)(kb + r) * Nd + nb + tx];
    __syncthreads();
    for (int r = ty; r < 32; r += 8) {
        float v = tile[tx][r];
        __nv_bfloat16 h, l;
        split_bf16(v, h, l);
        size_t oidx = (size_t)(nb + r) * Kd + kb + tx;
        th[oidx] = h;
        tl[oidx] = l;
    }
}
// V [NROWS, 512] f32 -> V^T [B,H,DH,S] hi/lo bf16
__global__ __launch_bounds__(256) void cvt_vt_k(const float* __restrict__ v,
                                                __nv_bfloat16* __restrict__ th,
                                                __nv_bfloat16* __restrict__ tl) {
    __shared__ float tile[32][33];
    const int z = blockIdx.z;                 // b*8+h
    const int zb = z >> 3, zh = z & 7;
    const int s0 = blockIdx.x * 32;           // seq base
    const int d0 = blockIdx.y * 32;           // dh base
    const int tx = threadIdx.x & 31, ty = threadIdx.x >> 5;
    for (int r = ty; r < 32; r += 8)
        tile[r][tx] = v[(size_t)(zb * SEQ + s0 + r) * DMODEL + zh * DHEAD + d0 + tx];
    __syncthreads();
    for (int r = ty; r < 32; r += 8) {
        float val = tile[tx][r];              // = V[s0+tx][d0+r]
        __nv_bfloat16 h, l;
        split_bf16(val, h, l);
        size_t oidx = ((size_t)z * DHEAD + d0 + r) * SEQ + s0 + tx;
        th[oidx] = h;
        tl[oidx] = l;
    }
}

// ---------------- warp-MMA bf16x3 GEMM (dense, weights path) ----------------
#define MG_ROWB   80
#define MG_TILE   (128 * MG_ROWB)
#define MG_BUF    (4 * MG_TILE)
#define MG_SMEM   (2 * MG_BUF)
template <int EPI>
__global__ __launch_bounds__(256) void mgemm_k(
    const __nv_bfloat16* __restrict__ ah, const __nv_bfloat16* __restrict__ al,
    const __nv_bfloat16* __restrict__ wh, const __nv_bfloat16* __restrict__ wl,
    float* C0, float* C1, float* C2,
    const float* __restrict__ E, int K, int ldc, size_t wSlot)
{
    extern __shared__ char smem[];
    const uint32_t sb = smem_u32(smem);
    const int t = threadIdx.x;
    const int lane = t & 31, wid = t >> 5;
    const int wr = wid & 1, wc = wid >> 1;
    const int z = blockIdx.z;
    const __nv_bfloat16* Bh = wh + (size_t)z * wSlot;
    const __nv_bfloat16* Bl = wl + (size_t)z * wSlot;
    float* C = (z == 0) ? C0 : (z == 1) ? C1 : C2;
    const int m0 = blockIdx.y * 128, n0 = blockIdx.x * 128;

    float d[4][4][4];
    #pragma unroll
    for (int mi = 0; mi < 4; mi++)
        #pragma unroll
        for (int nj = 0; nj < 4; nj++)
            #pragma unroll
            for (int r = 0; r < 4; r++) d[mi][nj][r] = 0.f;

    const int lr = t >> 2;
    const int lc = t & 3;
    const __nv_bfloat16* srcs[4] = { ah, al, Bh, Bl };

    auto issue = [&](int kc, int buf) {
        const uint32_t base = sb + buf * MG_BUF;
        #pragma unroll
        for (int tile = 0; tile < 4; tile++) {
            const __nv_bfloat16* s = srcs[tile];
            const int baseRow = (tile < 2) ? m0 : n0;
            #pragma unroll
            for (int h = 0; h < 2; h++) {
                const int row = lr + h * 64;
                const __nv_bfloat16* g = s + (size_t)(baseRow + row) * K + kc * 32 + lc * 8;
                const uint32_t sa = base + tile * MG_TILE + row * MG_ROWB + lc * 16;
                CP_ASYNC16(sa, g);
            }
        }
        CP_COMMIT();
    };

    const int nch = K >> 5;
    issue(0, 0);

    const int mat = lane >> 3, l8 = lane & 7;
    for (int kc = 0; kc < nch; kc++) {
        const int buf = kc & 1;
        if (kc + 1 < nch) { issue(kc + 1, buf ^ 1); cp_wait<1>(); }
        else              { cp_wait<0>(); }
        __syncthreads();
        const uint32_t bbase = sb + buf * MG_BUF;
        #pragma unroll
        for (int kk = 0; kk < 2; kk++) {
            uint32_t Ah[4][4], Al[4][4], Bhf[2][4], Blf[2][4];
            #pragma unroll
            for (int mi = 0; mi < 4; mi++) {
                const int row = wr * 64 + mi * 16 + (mat & 1) * 8 + l8;
                const uint32_t ad = bbase + row * MG_ROWB + kk * 32 + (mat >> 1) * 16;
                ldmx4(Ah[mi], ad);
                ldmx4(Al[mi], ad + MG_TILE);
            }
            #pragma unroll
            for (int nj2 = 0; nj2 < 2; nj2++) {
                const int n = wc * 32 + nj2 * 16 + (mat >> 1) * 8 + l8;
                const uint32_t bd = bbase + 2 * MG_TILE + n * MG_ROWB + kk * 32 + (mat & 1) * 16;
                ldmx4(Bhf[nj2], bd);
                ldmx4(Blf[nj2], bd + MG_TILE);
            }
            #pragma unroll
            for (int mi = 0; mi < 4; mi++)
                #pragma unroll
                for (int nj = 0; nj < 4; nj++) {
                    const int g = nj >> 1, o = (nj & 1) * 2;
                    mma16816(d[mi][nj], Ah[mi], Bhf[g][o], Bhf[g][o + 1]);
                    mma16816(d[mi][nj], Ah[mi], Blf[g][o], Blf[g][o + 1]);
                    mma16816(d[mi][nj], Al[mi], Bhf[g][o], Bhf[g][o + 1]);
                }
        }
        __syncthreads();
    }

    #pragma unroll
    for (int mi = 0; mi < 4; mi++) {
        #pragma unroll
        for (int nj = 0; nj < 4; nj++) {
            const int row = m0 + wr * 64 + mi * 16 + (lane >> 2);
            const int col = n0 + wc * 32 + nj * 8 + (lane & 3) * 2;
            #pragma unroll
            for (int hh = 0; hh < 2; hh++) {
                const int m = row + hh * 8;
                float2 cv = make_float2(d[mi][nj][hh * 2], d[mi][nj][hh * 2 + 1]);
                if constexpr (EPI == 1) {
                    const float2 rv = *reinterpret_cast<const float2*>(
                        E + (size_t)m * ldc + col);
                    cv.x += rv.x; cv.y += rv.y;
                }
                *reinterpret_cast<float2*>(C + (size_t)m * ldc + col) = cv;
            }
        }
    }
}

// ---------------- warp-MMA bf16x3 batched attention GEMM ----------------
// z = b*8 + h. A [M,K] row-major (pre-split hi/lo), B [N,K] row-major (hi/lo).
// EPI: 0 plain write, 2 add pos-bias E[(zh*SEQ+m)*SEQ+col].
// CTA tile 128 x BN, 8 warps (2 x 4), warp tile 64 x BN/4.
template <int BN, int EPI>
__global__ __launch_bounds__(256) void matt_k(
    const __nv_bfloat16* __restrict__ ah, const __nv_bfloat16* __restrict__ al,
    size_t aSB, size_t aSH, int lda,
    const __nv_bfloat16* __restrict__ bh, const __nv_bfloat16* __restrict__ bl,
    size_t bSB, size_t bSH, int ldb,
    float* __restrict__ Cb, size_t cSB, size_t cSH, int ldc,
    const float* __restrict__ E, int K)
{
    constexpr int ATILE = 128 * MG_ROWB;
    constexpr int BTILE = BN * MG_ROWB;
    constexpr int BUFSZ = 2 * ATILE + 2 * BTILE;
    constexpr int NJ2 = BN / 64;          // B 16-wide groups per warp (2 or 1)
    extern __shared__ char smem[];
    const uint32_t sb = smem_u32(smem);
    const int t = threadIdx.x;
    const int lane = t & 31, wid = t >> 5;
    const int wr = wid & 1, wc = wid >> 1;
    const int z = blockIdx.z;
    const int zb = z >> 3, zh = z & 7;
    const __nv_bfloat16* Ah_g = ah + (size_t)zb * aSB + (size_t)zh * aSH;
    const __nv_bfloat16* Al_g = al + (size_t)zb * aSB + (size_t)zh * aSH;
    const __nv_bfloat16* Bh_g = bh + (size_t)zb * bSB + (size_t)zh * bSH;
    const __nv_bfloat16* Bl_g = bl + (size_t)zb * bSB + (size_t)zh * bSH;
    float* C = Cb + (size_t)zb * cSB + (size_t)zh * cSH;
    const int m0 = blockIdx.y * 128, n0 = blockIdx.x * BN;

    float d[4][2 * NJ2][4];
    #pragma unroll
    for (int mi = 0; mi < 4; mi++)
        #pragma unroll
        for (int nj = 0; nj < 2 * NJ2; nj++)
            #pragma unroll
            for (int r = 0; r < 4; r++) d[mi][nj][r] = 0.f;

    const int lr = t >> 2;
    const int lc = t & 3;

    auto issue = [&](int kc, int buf) {
        const uint32_t base = sb + buf * BUFSZ;
        #pragma unroll
        for (int h = 0; h < 2; h++) {
            const int row = lr + h * 64;
            const size_t go = (size_t)(m0 + row) * lda + kc * 32 + lc * 8;
            const uint32_t so = row * MG_ROWB + lc * 16;
            CP_ASYNC16(base + so, Ah_g + go);
            CP_ASYNC16(base + ATILE + so, Al_g + go);
        }
        #pragma unroll
        for (int h = 0; h < BN / 64; h++) {
            const int row = lr + h * 64;
            const size_t go = (size_t)(n0 + row) * ldb + kc * 32 + lc * 8;
            const uint32_t so = row * MG_ROWB + lc * 16;
            CP_ASYNC16(base + 2 * ATILE + so, Bh_g + go);
            CP_ASYNC16(base + 2 * ATILE + BTILE + so, Bl_g + go);
        }
        CP_COMMIT();
    };

    const int nch = K >> 5;
    issue(0, 0);

    const int mat = lane >> 3, l8 = lane & 7;
    for (int kc = 0; kc < nch; kc++) {
        const int buf = kc & 1;
        if (kc + 1 < nch) { issue(kc + 1, buf ^ 1); cp_wait<1>(); }
        else              { cp_wait<0>(); }
        __syncthreads();
        const uint32_t bbase = sb + buf * BUFSZ;
        #pragma unroll
        for (int kk = 0; kk < 2; kk++) {
            uint32_t Af[4][4], Alf[4][4], Bhf[NJ2][4], Blf[NJ2][4];
            #pragma unroll
            for (int mi = 0; mi < 4; mi++) {
                const int row = wr * 64 + mi * 16 + (mat & 1) * 8 + l8;
                const uint32_t ad = bbase + row * MG_ROWB + kk * 32 + (mat >> 1) * 16;
                ldmx4(Af[mi], ad);
                ldmx4(Alf[mi], ad + ATILE);
            }
            #pragma unroll
            for (int nj2 = 0; nj2 < NJ2; nj2++) {
                const int n = wc * (BN / 4) + nj2 * 16 + (mat >> 1) * 8 + l8;
                const uint32_t bd = bbase + 2 * ATILE + n * MG_ROWB + kk * 32 + (mat & 1) * 16;
                ldmx4(Bhf[nj2], bd);
                ldmx4(Blf[nj2], bd + BTILE);
            }
            #pragma unroll
            for (int mi = 0; mi < 4; mi++)
                #pragma unroll
                for (int nj = 0; nj < 2 * NJ2; nj++) {
                    const int g = nj >> 1, o = (nj & 1) * 2;
                    mma16816(d[mi][nj], Af[mi], Bhf[g][o], Bhf[g][o + 1]);
                    mma16816(d[mi][nj], Af[mi], Blf[g][o], Blf[g][o + 1]);
                    mma16816(d[mi][nj], Alf[mi], Bhf[g][o], Bhf[g][o + 1]);
                }
        }
        __syncthreads();
    }

    #pragma unroll
    for (int mi = 0; mi < 4; mi++) {
        #pragma unroll
        for (int nj = 0; nj < 2 * NJ2; nj++) {
            const int row = m0 + wr * 64 + mi * 16 + (lane >> 2);
            const int col = n0 + wc * (BN / 4) + nj * 8 + (lane & 3) * 2;
            #pragma unroll
            for (int hh = 0; hh < 2; hh++) {
                const int m = row + hh * 8;
                float2 cv = make_float2(d[mi][nj][hh * 2], d[mi][nj][hh * 2 + 1]);
                if constexpr (EPI == 2) {
                    const float2 bv = *reinterpret_cast<const float2*>(
                        E + ((size_t)zh * SEQ + m) * SEQ + col);
                    cv.x += bv.x; cv.y += bv.y;
                }
                *reinterpret_cast<float2*>(C + (size_t)m * ldc + col) = cv;
            }
        }
    }
}

// ---------------- launch ----------------
extern "C" void kernel_launch(void* const* d_in, const int* in_sizes, int n_in,
                              void* d_out, int out_size) {
    const int*   ids    = (const int*)  d_in[0];
    const float* embed  = (const float*)d_in[1];
    const float* Wq     = (const float*)d_in[2];
    const float* Wk     = (const float*)d_in[3];
    const float* Wv     = (const float*)d_in[4];
    const float* Wo     = (const float*)d_in[5];
    const float* relb   = (const float*)d_in[6];
    const float* wi0    = (const float*)d_in[7];
    const float* wi1    = (const float*)d_in[8];
    const float* wo_ffn = (const float*)d_in[9];
    const float* ln0    = (const float*)d_in[10];
    const float* ln1    = (const float*)d_in[11];
    const float* flw    = (const float*)d_in[12];
    float* out = (float*)d_out;

    float *x, *h, *q, *k, *v, *o, *f0, *f1, *s, *bias;
    __nv_bfloat16 *ah, *al, *wh, *wl, *sh, *sl, *vth, *vtl;
    cudaGetSymbolAddress((void**)&x,  g_x);
    cudaGetSymbolAddress((void**)&h,  g_h);
    cudaGetSymbolAddress((void**)&q,  g_q);
    cudaGetSymbolAddress((void**)&k,  g_k);
    cudaGetSymbolAddress((void**)&v,  g_v);
    cudaGetSymbolAddress((void**)&o,  g_o);
    cudaGetSymbolAddress((void**)&f0, g_f0);
    cudaGetSymbolAddress((void**)&f1, g_f1);
    cudaGetSymbolAddress((void**)&s,  g_s);
    cudaGetSymbolAddress((void**)&bias, g_bias);
    cudaGetSymbolAddress((void**)&ah, g_ah);
    cudaGetSymbolAddress((void**)&al, g_al);
    cudaGetSymbolAddress((void**)&wh, g_wh);
    cudaGetSymbolAddress((void**)&wl, g_wl);
    cudaGetSymbolAddress((void**)&sh, g_sh);
    cudaGetSymbolAddress((void**)&sl, g_sl);
    cudaGetSymbolAddress((void**)&vth, g_vth);
    cudaGetSymbolAddress((void**)&vtl, g_vtl);

    cudaFuncSetAttribute(mgemm_k<0>, cudaFuncAttributeMaxDynamicSharedMemorySize, MG_SMEM);
    cudaFuncSetAttribute(mgemm_k<1>, cudaFuncAttributeMaxDynamicSharedMemorySize, MG_SMEM);
    cudaFuncSetAttribute((const void*)matt_k<128, 2>, cudaFuncAttributeMaxDynamicSharedMemorySize, MG_SMEM);
    cudaFuncSetAttribute((const void*)matt_k<64, 0>, cudaFuncAttributeMaxDynamicSharedMemorySize,
                         2 * (2 * 128 * MG_ROWB + 2 * 64 * MG_ROWB));

    float* out_bias = ((size_t)out_size > OUTX) ? (out + OUTX) : nullptr;

    embed_k<<<NROWS, 256>>>(ids, embed, x);
    {
        size_t nb = ((size_t)NH * SEQ * SEQ + 255) / 256;
        bias_k<<<(unsigned)nb, 256>>>(relb, bias, out_bias);
    }

    const size_t bhA = (size_t)SEQ * DMODEL;       // per-batch stride in q/k/v/o
    const size_t bhS = (size_t)NH * SEQ * SEQ;     // per-batch stride in scores
    const size_t hS  = (size_t)SEQ * SEQ;          // per-head stride in scores
    const size_t DD  = (size_t)DMODEL * DMODEL;
    const size_t DF  = (size_t)DMODEL * DFF_;
    const size_t QK  = (size_t)NROWS * DMODEL;     // q/k bf16 buffer size
    const size_t vtB = (size_t)NH * DHEAD * SEQ;   // per-batch stride in vt
    const size_t vtH = (size_t)DHEAD * SEQ;        // per-head stride in vt
    const int attSmem64 = 2 * (2 * 128 * MG_ROWB + 2 * 64 * MG_ROWB);

    for (int i = 0; i < NL; i++) {
        // ---- self attention ----
        rms_k<<<NROWS, 256>>>(x, ln0 + (size_t)i * DMODEL, h);
        cvt_act_k<<<NROWS * DMODEL / 1024, 256>>>(h, ah, al, NROWS * DMODEL);
        {
            dim3 gW(DMODEL / 32, DMODEL / 32);
            cvt_wt_k<<<gW, 256>>>(Wq + i * DD, wh,          wl,          DMODEL, DMODEL);
            cvt_wt_k<<<gW, 256>>>(Wk + i * DD, wh + DD,     wl + DD,     DMODEL, DMODEL);
            cvt_wt_k<<<gW, 256>>>(Wv + i * DD, wh + 2 * DD, wl + 2 * DD, DMODEL, DMODEL);
        }
        mgemm_k<0><<<dim3(4, 32, 3), 256, MG_SMEM>>>(ah, al, wh, wl,
                                                     q, k, v, nullptr,
                                                     DMODEL, DMODEL, DD);
        // convert q/k (hi/lo bf16, same layout) and v (transposed per head)
        cvt_act_k<<<NROWS * DMODEL / 1024, 256>>>(q, ah, al, NROWS * DMODEL);
        cvt_act_k<<<NROWS * DMODEL / 1024, 256>>>(k, ah + QK, al + QK, NROWS * DMODEL);
        cvt_vt_k<<<dim3(SEQ / 32, DHEAD / 32, BATCH * NH), 256>>>(v, vth, vtl);
        // scores = Q @ K^T + bias   (f32 out)
        matt_k<128, 2><<<dim3(SEQ / 128, SEQ / 128, BATCH * NH), 256, MG_SMEM>>>(
            ah, al, bhA, DHEAD, DMODEL,
            ah + QK, al + QK, bhA, DHEAD, DMODEL,
            s, bhS, hS, SEQ,
            bias, DHEAD);
        softmax_k<<<BATCH * NH * SEQ, 256>>>(s, sh, sl);
        // o = attn @ V   (attn hi/lo from softmax, V^T hi/lo)
        matt_k<64, 0><<<dim3(1, SEQ / 128, BATCH * NH), 256, attSmem64>>>(
            sh, sl, bhS, hS, SEQ,
            vth, vtl, vtB, vtH, SEQ,
            o, bhA, DHEAD, DMODEL,
            nullptr, SEQ);
        // x = x + o @ Wo
        cvt_act_k<<<NROWS * DMODEL / 1024, 256>>>(o, ah, al, NROWS * DMODEL);
        cvt_wt_k<<<dim3(DMODEL / 32, DMODEL / 32), 256>>>(Wo + i * DD, wh, wl, DMODEL, DMODEL);
        mgemm_k<1><<<dim3(4, 32, 1), 256, MG_SMEM>>>(ah, al, wh, wl,
                                                     x, x, x, x,
                                                     DMODEL, DMODEL, 0);
        // ---- gated-GELU FFN ----
        rms_k<<<NROWS, 256>>>(x, ln1 + (size_t)i * DMODEL, h);
        cvt_act_k<<<NROWS * DMODEL / 1024, 256>>>(h, ah, al, NROWS * DMODEL);
        {
            dim3 gW(DFF_ / 32, DMODEL / 32);
            cvt_wt_k<<<gW, 256>>>(wi0 + i * DF, wh,      wl,      DMODEL, DFF_);
            cvt_wt_k<<<gW, 256>>>(wi1 + i * DF, wh + DF, wl + DF, DMODEL, DFF_);
        }
        mgemm_k<0><<<dim3(8, 32, 2), 256, MG_SMEM>>>(ah, al, wh, wl,
                                                     f0, f1, f1, nullptr,
                                                     DMODEL, DFF_, DF);
        geglu_k<<<4096, 256>>>(f0, f1, NROWS * DFF_);
        cvt_act_k<<<NROWS * DFF_ / 1024, 256>>>(f0, ah, al, NROWS * DFF_);
        cvt_wt_k<<<dim3(DMODEL / 32, DFF_ / 32), 256>>>(wo_ffn + i * DF, wh, wl, DFF_, DMODEL);
        mgemm_k<1><<<dim3(4, 32, 1), 256, MG_SMEM>>>(ah, al, wh, wl,
                                                     x, x, x, x,
                                                     DFF_, DMODEL, 0);
    }
    rms_k<<<NROWS, 256>>>(x, flw, out);
}

// round 9
// speedup vs baseline: 2.1744x; 1.1356x over previous
#include <cuda_runtime.h>
#include <cuda_bf16.h>
#include <cstdint>
#include <math.h>

#define NL    4
#define DMODEL 512
#define NH    8
#define DHEAD 64
#define DFF_  1024
#define SEQ   2048
#define BATCH 2
#define NROWS (BATCH*SEQ)          // 4096
#define OUTX  ((size_t)NROWS*DMODEL)  // 2097152

typedef unsigned long long u64;

// ---------------- scratch ----------------
__device__ float g_x [NROWS*DMODEL];
__device__ float g_h [NROWS*DMODEL];
__device__ float g_q [NROWS*DMODEL];
__device__ float g_k [NROWS*DMODEL];
__device__ float g_v [NROWS*DMODEL];
__device__ float g_o [NROWS*DMODEL];
__device__ float g_f0[NROWS*DFF_];
__device__ float g_f1[NROWS*DFF_];
__device__ float g_bias[(size_t)NH*SEQ*SEQ];               // pos bias
// bf16 split buffers
__device__ __nv_bfloat16 g_ah[NROWS*DFF_];
__device__ __nv_bfloat16 g_al[NROWS*DFF_];
__device__ __nv_bfloat16 g_wh[DMODEL*DFF_*2];
__device__ __nv_bfloat16 g_wl[DMODEL*DFF_*2];
__device__ __nv_bfloat16 g_vth[(size_t)BATCH*NH*DHEAD*SEQ]; // V^T hi [B,H,DH,S]
__device__ __nv_bfloat16 g_vtl[(size_t)BATCH*NH*DHEAD*SEQ];

// ---------------- helpers ----------------
__device__ __forceinline__ uint32_t smem_u32(const void* p) {
    uint32_t a;
    asm("{ .reg .u64 t; cvta.to.shared.u64 t, %1; cvt.u32.u64 %0, t; }" : "=r"(a) : "l"(p));
    return a;
}
#define CP_ASYNC16(sa, ga) \
    asm volatile("cp.async.cg.shared.global [%0], [%1], 16;" :: "r"(sa), "l"(ga))
#define CP_COMMIT() asm volatile("cp.async.commit_group;" ::: "memory")
template <int N>
__device__ __forceinline__ void cp_wait() {
    asm volatile("cp.async.wait_group %0;" :: "n"(N) : "memory");
}
__device__ __forceinline__ void ldmx4(uint32_t* r, uint32_t addr) {
    asm volatile("ldmatrix.sync.aligned.m8n8.x4.shared.b16 {%0,%1,%2,%3}, [%4];"
                 : "=r"(r[0]), "=r"(r[1]), "=r"(r[2]), "=r"(r[3]) : "r"(addr));
}
__device__ __forceinline__ void mma16816(float* d, const uint32_t* a,
                                         uint32_t b0, uint32_t b1) {
    asm volatile(
        "mma.sync.aligned.m16n8k16.row.col.f32.bf16.bf16.f32 "
        "{%0,%1,%2,%3}, {%4,%5,%6,%7}, {%8,%9}, {%0,%1,%2,%3};"
        : "+f"(d[0]), "+f"(d[1]), "+f"(d[2]), "+f"(d[3])
        : "r"(a[0]), "r"(a[1]), "r"(a[2]), "r"(a[3]), "r"(b0), "r"(b1));
}
__device__ __forceinline__ uint32_t pack_bf(__nv_bfloat16 a, __nv_bfloat16 b) {
    __nv_bfloat162 p(a, b);
    return *reinterpret_cast<uint32_t*>(&p);
}

// ---------------- small kernels ----------------
__global__ __launch_bounds__(256) void embed_k(const int* __restrict__ ids,
                                               const float* __restrict__ emb,
                                               float* __restrict__ x) {
    const int row = blockIdx.x;
    const size_t src = (size_t)ids[row] * DMODEL;
    const size_t dst = (size_t)row * DMODEL;
    for (int i = threadIdx.x; i < DMODEL; i += 256) x[dst + i] = emb[src + i];
}

__global__ __launch_bounds__(256) void bias_k(const float* __restrict__ rb,
                                              float* __restrict__ bias,
                                              float* __restrict__ out2) {
    size_t idx = (size_t)blockIdx.x * 256 + threadIdx.x;
    if (idx >= (size_t)NH * SEQ * SEQ) return;
    int kk = (int)(idx & (SEQ - 1));
    int qq = (int)((idx >> 11) & (SEQ - 1));
    int hh = (int)(idx >> 22);
    int rel = kk - qq;
    int bucket = (rel > 0) ? 16 : 0;
    int rp = (rel < 0) ? -rel : rel;
    int add;
    if (rp < 8) {
        add = rp;
    } else {
        float t = logf((float)rp / 8.0f);
        t = t / 2.7725887298583984f;
        t = t * 8.0f;
        add = 8 + (int)t;
        if (add > 15) add = 15;
    }
    float val = rb[(bucket + add) * NH + hh];
    bias[idx] = val;
    if (out2) out2[idx] = val;
}

__global__ __launch_bounds__(256) void rms_k(const float* __restrict__ x,
                                             const float* __restrict__ w,
                                             float* __restrict__ y) {
    const size_t base = (size_t)blockIdx.x * DMODEL;
    const int t = threadIdx.x;
    float v0 = x[base + t], v1 = x[base + t + 256];
    float ss = v0 * v0 + v1 * v1;
    #pragma unroll
    for (int off = 16; off; off >>= 1) ss += __shfl_xor_sync(0xffffffffu, ss, off);
    __shared__ float red[8];
    __shared__ float bval;
    if ((t & 31) == 0) red[t >> 5] = ss;
    __syncthreads();
    if (t == 0) {
        float tot = 0.f;
        #pragma unroll
        for (int i = 0; i < 8; i++) tot += red[i];
        bval = rsqrtf(tot * (1.0f / DMODEL) + 1e-6f);
    }
    __syncthreads();
    const float inv = bval;
    y[base + t]       = w[t]       * (v0 * inv);
    y[base + t + 256] = w[t + 256] * (v1 * inv);
}

__global__ __launch_bounds__(256) void geglu_k(float* __restrict__ f0,
                                               const float* __restrict__ f1, int n) {
    int i = blockIdx.x * blockDim.x + threadIdx.x;
    int stride = gridDim.x * blockDim.x;
    for (; i < n; i += stride) {
        float xx = f0[i];
        float inner = 0.7978845608028654f * (xx + 0.044715f * (xx * xx * xx));
        float g = 0.5f * xx * (1.0f + tanhf(inner));
        f0[i] = g * f1[i];
    }
}

// ---------------- bf16 split conversions ----------------
__device__ __forceinline__ void split_bf16(float v, __nv_bfloat16& h, __nv_bfloat16& l) {
    h = __float2bfloat16(v);
    l = __float2bfloat16(v - __bfloat162float(h));
}
__global__ __launch_bounds__(256) void cvt_act_k(const float* __restrict__ x,
                                                 __nv_bfloat16* __restrict__ hi,
                                                 __nv_bfloat16* __restrict__ lo, int n) {
    int i = (blockIdx.x * 256 + threadIdx.x) * 4;
    if (i >= n) return;
    float4 v = *reinterpret_cast<const float4*>(x + i);
    __nv_bfloat16 h0, h1, h2, h3, l0, l1, l2, l3;
    split_bf16(v.x, h0, l0); split_bf16(v.y, h1, l1);
    split_bf16(v.z, h2, l2); split_bf16(v.w, h3, l3);
    __nv_bfloat162 hp0(h0, h1), hp1(h2, h3), lp0(l0, l1), lp1(l2, l3);
    uint2 H = make_uint2(*reinterpret_cast<uint32_t*>(&hp0), *reinterpret_cast<uint32_t*>(&hp1));
    uint2 L = make_uint2(*reinterpret_cast<uint32_t*>(&lp0), *reinterpret_cast<uint32_t*>(&lp1));
    *reinterpret_cast<uint2*>(hi + i) = H;
    *reinterpret_cast<uint2*>(lo + i) = L;
}
// W[K,N] f32 -> transposed Wt[N,K] hi/lo bf16
__global__ __launch_bounds__(256) void cvt_wt_k(const float* __restrict__ W,
                                                __nv_bfloat16* __restrict__ th,
                                                __nv_bfloat16* __restrict__ tl,
                                                int Kd, int Nd) {
    __shared__ float tile[32][33];
    int kb = blockIdx.y * 32, nb = blockIdx.x * 32;
    int tx = threadIdx.x & 31, ty = threadIdx.x >> 5;
    for (int r = ty; r < 32; r += 8)
        tile[r][tx] = W[(size_t)(kb + r) * Nd + nb + tx];
    __syncthreads();
    for (int r = ty; r < 32; r += 8) {
        float v = tile[tx][r];
        __nv_bfloat16 h, l;
        split_bf16(v, h, l);
        size_t oidx = (size_t)(nb + r) * Kd + kb + tx;
        th[oidx] = h;
        tl[oidx] = l;
    }
}
// V [NROWS, 512] f32 -> V^T [B,H,DH,S] hi/lo bf16
__global__ __launch_bounds__(256) void cvt_vt_k(const float* __restrict__ v,
                                                __nv_bfloat16* __restrict__ th,
                                                __nv_bfloat16* __restrict__ tl) {
    __shared__ float tile[32][33];
    const int z = blockIdx.z;
    const int zb = z >> 3, zh = z & 7;
    const int s0 = blockIdx.x * 32;
    const int d0 = blockIdx.y * 32;
    const int tx = threadIdx.x & 31, ty = threadIdx.x >> 5;
    for (int r = ty; r < 32; r += 8)
        tile[r][tx] = v[(size_t)(zb * SEQ + s0 + r) * DMODEL + zh * DHEAD + d0 + tx];
    __syncthreads();
    for (int r = ty; r < 32; r += 8) {
        float val = tile[tx][r];
        __nv_bfloat16 h, l;
        split_bf16(val, h, l);
        size_t oidx = ((size_t)z * DHEAD + d0 + r) * SEQ + s0 + tx;
        th[oidx] = h;
        tl[oidx] = l;
    }
}

// ---------------- warp-MMA bf16x3 GEMM (dense, weights path) ----------------
#define MG_ROWB   80
#define MG_TILE   (128 * MG_ROWB)
#define MG_BUF    (4 * MG_TILE)
#define MG_SMEM   (2 * MG_BUF)
template <int EPI>
__global__ __launch_bounds__(256) void mgemm_k(
    const __nv_bfloat16* __restrict__ ah, const __nv_bfloat16* __restrict__ al,
    const __nv_bfloat16* __restrict__ wh, const __nv_bfloat16* __restrict__ wl,
    float* C0, float* C1, float* C2,
    const float* __restrict__ E, int K, int ldc, size_t wSlot)
{
    extern __shared__ char smem[];
    const uint32_t sb = smem_u32(smem);
    const int t = threadIdx.x;
    const int lane = t & 31, wid = t >> 5;
    const int wr = wid & 1, wc = wid >> 1;
    const int z = blockIdx.z;
    const __nv_bfloat16* Bh = wh + (size_t)z * wSlot;
    const __nv_bfloat16* Bl = wl + (size_t)z * wSlot;
    float* C = (z == 0) ? C0 : (z == 1) ? C1 : C2;
    const int m0 = blockIdx.y * 128, n0 = blockIdx.x * 128;

    float d[4][4][4];
    #pragma unroll
    for (int mi = 0; mi < 4; mi++)
        #pragma unroll
        for (int nj = 0; nj < 4; nj++)
            #pragma unroll
            for (int r = 0; r < 4; r++) d[mi][nj][r] = 0.f;

    const int lr = t >> 2;
    const int lc = t & 3;
    const __nv_bfloat16* srcs[4] = { ah, al, Bh, Bl };

    auto issue = [&](int kc, int buf) {
        const uint32_t base = sb + buf * MG_BUF;
        #pragma unroll
        for (int tile = 0; tile < 4; tile++) {
            const __nv_bfloat16* s = srcs[tile];
            const int baseRow = (tile < 2) ? m0 : n0;
            #pragma unroll
            for (int h = 0; h < 2; h++) {
                const int row = lr + h * 64;
                const __nv_bfloat16* g = s + (size_t)(baseRow + row) * K + kc * 32 + lc * 8;
                const uint32_t sa = base + tile * MG_TILE + row * MG_ROWB + lc * 16;
                CP_ASYNC16(sa, g);
            }
        }
        CP_COMMIT();
    };

    const int nch = K >> 5;
    issue(0, 0);

    const int mat = lane >> 3, l8 = lane & 7;
    for (int kc = 0; kc < nch; kc++) {
        const int buf = kc & 1;
        if (kc + 1 < nch) { issue(kc + 1, buf ^ 1); cp_wait<1>(); }
        else              { cp_wait<0>(); }
        __syncthreads();
        const uint32_t bbase = sb + buf * MG_BUF;
        #pragma unroll
        for (int kk = 0; kk < 2; kk++) {
            uint32_t Ah[4][4], Al[4][4], Bhf[2][4], Blf[2][4];
            #pragma unroll
            for (int mi = 0; mi < 4; mi++) {
                const int row = wr * 64 + mi * 16 + (mat & 1) * 8 + l8;
                const uint32_t ad = bbase + row * MG_ROWB + kk * 32 + (mat >> 1) * 16;
                ldmx4(Ah[mi], ad);
                ldmx4(Al[mi], ad + MG_TILE);
            }
            #pragma unroll
            for (int nj2 = 0; nj2 < 2; nj2++) {
                const int n = wc * 32 + nj2 * 16 + (mat >> 1) * 8 + l8;
                const uint32_t bd = bbase + 2 * MG_TILE + n * MG_ROWB + kk * 32 + (mat & 1) * 16;
                ldmx4(Bhf[nj2], bd);
                ldmx4(Blf[nj2], bd + MG_TILE);
            }
            #pragma unroll
            for (int mi = 0; mi < 4; mi++)
                #pragma unroll
                for (int nj = 0; nj < 4; nj++) {
                    const int g = nj >> 1, o = (nj & 1) * 2;
                    mma16816(d[mi][nj], Ah[mi], Bhf[g][o], Bhf[g][o + 1]);
                    mma16816(d[mi][nj], Ah[mi], Blf[g][o], Blf[g][o + 1]);
                    mma16816(d[mi][nj], Al[mi], Bhf[g][o], Bhf[g][o + 1]);
                }
        }
        __syncthreads();
    }

    #pragma unroll
    for (int mi = 0; mi < 4; mi++) {
        #pragma unroll
        for (int nj = 0; nj < 4; nj++) {
            const int row = m0 + wr * 64 + mi * 16 + (lane >> 2);
            const int col = n0 + wc * 32 + nj * 8 + (lane & 3) * 2;
            #pragma unroll
            for (int hh = 0; hh < 2; hh++) {
                const int m = row + hh * 8;
                float2 cv = make_float2(d[mi][nj][hh * 2], d[mi][nj][hh * 2 + 1]);
                if constexpr (EPI == 1) {
                    const float2 rv = *reinterpret_cast<const float2*>(
                        E + (size_t)m * ldc + col);
                    cv.x += rv.x; cv.y += rv.y;
                }
                *reinterpret_cast<float2*>(C + (size_t)m * ldc + col) = cv;
            }
        }
    }
}

// ---------------- fused flash attention (bf16x3 MMA, online softmax) ----------------
// grid: (SEQ/128, 1, BATCH*NH). 256 threads, 8 warps x 16 q-rows.
// Q/K from split activations [4096,512] (head slice), V^T from [B*H*64, 2048].
#define FL_QSTR 144
#define FL_VSTR 272
#define FL_QT   (128 * FL_QSTR)      // 18432
#define FL_VT   (64 * FL_VSTR)       // 17408
#define FL_OFF_K(buf) (2 * FL_QT + (buf) * 2 * FL_QT)
#define FL_OFF_V(buf) (6 * FL_QT + (buf) * 2 * FL_VT)
#define FL_SMEM (6 * FL_QT + 4 * FL_VT)   // 180224
__global__ __launch_bounds__(256) void flash_k(
    const __nv_bfloat16* __restrict__ qh_g, const __nv_bfloat16* __restrict__ ql_g,
    const __nv_bfloat16* __restrict__ kh_g, const __nv_bfloat16* __restrict__ kl_g,
    const __nv_bfloat16* __restrict__ vth_g, const __nv_bfloat16* __restrict__ vtl_g,
    const float* __restrict__ bias, float* __restrict__ O)
{
    extern __shared__ char smem[];
    const uint32_t sb = smem_u32(smem);
    const int t = threadIdx.x, lane = t & 31, wid = t >> 5;
    const int z = blockIdx.z, zb = z >> 3, zh = z & 7;
    const int m0 = blockIdx.x * 128;
    const int mat = lane >> 3, l8 = lane & 7;

    auto loadQ = [&]() {
        #pragma unroll
        for (int i = 0; i < 4; i++) {
            int idx = t + i * 256, row = idx >> 3, c = idx & 7;
            size_t go = (size_t)(zb * SEQ + m0 + row) * DMODEL + zh * 64 + c * 8;
            CP_ASYNC16(sb + row * FL_QSTR + c * 16, qh_g + go);
            CP_ASYNC16(sb + FL_QT + row * FL_QSTR + c * 16, ql_g + go);
        }
    };
    auto loadKV = [&](int kt, int buf) {
        #pragma unroll
        for (int i = 0; i < 4; i++) {
            int idx = t + i * 256, row = idx >> 3, c = idx & 7;
            size_t go = (size_t)(zb * SEQ + kt * 128 + row) * DMODEL + zh * 64 + c * 8;
            CP_ASYNC16(sb + FL_OFF_K(buf) + row * FL_QSTR + c * 16, kh_g + go);
            CP_ASYNC16(sb + FL_OFF_K(buf) + FL_QT + row * FL_QSTR + c * 16, kl_g + go);
        }
        #pragma unroll
        for (int i = 0; i < 4; i++) {
            int idx = t + i * 256, row = idx >> 4, c = idx & 15;
            size_t go = (size_t)(z * 64 + row) * SEQ + kt * 128 + c * 8;
            CP_ASYNC16(sb + FL_OFF_V(buf) + row * FL_VSTR + c * 16, vth_g + go);
            CP_ASYNC16(sb + FL_OFF_V(buf) + FL_VT + row * FL_VSTR + c * 16, vtl_g + go);
        }
        CP_COMMIT();
    };

    loadQ();
    loadKV(0, 0);

    float m_[2] = { -1e30f, -1e30f }, l_[2] = { 0.f, 0.f };
    float o[8][4];
    #pragma unroll
    for (int nt = 0; nt < 8; nt++)
        #pragma unroll
        for (int e = 0; e < 4; e++) o[nt][e] = 0.f;
    uint32_t qh[4][4], ql[4][4];

    for (int kt = 0; kt < 16; kt++) {
        const int buf = kt & 1;
        if (kt + 1 < 16) { loadKV(kt + 1, buf ^ 1); cp_wait<1>(); }
        else             { cp_wait<0>(); }
        __syncthreads();
        if (kt == 0) {
            #pragma unroll
            for (int kc = 0; kc < 4; kc++) {
                const int row = wid * 16 + (mat & 1) * 8 + l8;
                const uint32_t ad = sb + row * FL_QSTR + kc * 32 + (mat >> 1) * 16;
                ldmx4(qh[kc], ad);
                ldmx4(ql[kc], ad + FL_QT);
            }
        }
        // ---- S = Q @ K_tile^T ----
        float s[16][4];
        #pragma unroll
        for (int j = 0; j < 16; j++)
            #pragma unroll
            for (int e = 0; e < 4; e++) s[j][e] = 0.f;
        #pragma unroll
        for (int j2 = 0; j2 < 8; j2++) {
            const int n = j2 * 16 + (mat >> 1) * 8 + l8;
            #pragma unroll
            for (int kc = 0; kc < 4; kc++) {
                uint32_t bh4[4], bl4[4];
                const uint32_t bd = sb + FL_OFF_K(buf) + n * FL_QSTR + kc * 32 + (mat & 1) * 16;
                ldmx4(bh4, bd);
                ldmx4(bl4, bd + FL_QT);
                #pragma unroll
                for (int e = 0; e < 2; e++) {
                    mma16816(s[j2 * 2 + e], qh[kc], bh4[e * 2], bh4[e * 2 + 1]);
                    mma16816(s[j2 * 2 + e], qh[kc], bl4[e * 2], bl4[e * 2 + 1]);
                    mma16816(s[j2 * 2 + e], ql[kc], bh4[e * 2], bh4[e * 2 + 1]);
                }
            }
        }
        // ---- + bias ----
        const int r0 = m0 + wid * 16 + (lane >> 2);
        #pragma unroll
        for (int j = 0; j < 16; j++) {
            const int col = kt * 128 + j * 8 + 2 * (lane & 3);
            const float2 b0 = *reinterpret_cast<const float2*>(
                bias + ((size_t)zh * SEQ + r0) * SEQ + col);
            const float2 b1 = *reinterpret_cast<const float2*>(
                bias + ((size_t)zh * SEQ + r0 + 8) * SEQ + col);
            s[j][0] += b0.x; s[j][1] += b0.y;
            s[j][2] += b1.x; s[j][3] += b1.y;
        }
        // ---- online softmax ----
        float mx[2] = { -1e30f, -1e30f };
        #pragma unroll
        for (int j = 0; j < 16; j++) {
            mx[0] = fmaxf(mx[0], fmaxf(s[j][0], s[j][1]));
            mx[1] = fmaxf(mx[1], fmaxf(s[j][2], s[j][3]));
        }
        #pragma unroll
        for (int off = 1; off <= 2; off <<= 1) {
            mx[0] = fmaxf(mx[0], __shfl_xor_sync(0xffffffffu, mx[0], off));
            mx[1] = fmaxf(mx[1], __shfl_xor_sync(0xffffffffu, mx[1], off));
        }
        float al2[2];
        #pragma unroll
        for (int h = 0; h < 2; h++) {
            const float nm = fmaxf(m_[h], mx[h]);
            al2[h] = __expf(m_[h] - nm);
            m_[h] = nm;
        }
        float rs[2] = { 0.f, 0.f };
        #pragma unroll
        for (int j = 0; j < 16; j++) {
            s[j][0] = __expf(s[j][0] - m_[0]);
            s[j][1] = __expf(s[j][1] - m_[0]);
            s[j][2] = __expf(s[j][2] - m_[1]);
            s[j][3] = __expf(s[j][3] - m_[1]);
            rs[0] += s[j][0] + s[j][1];
            rs[1] += s[j][2] + s[j][3];
        }
        #pragma unroll
        for (int off = 1; off <= 2; off <<= 1) {
            rs[0] += __shfl_xor_sync(0xffffffffu, rs[0], off);
            rs[1] += __shfl_xor_sync(0xffffffffu, rs[1], off);
        }
        l_[0] = l_[0] * al2[0] + rs[0];
        l_[1] = l_[1] * al2[1] + rs[1];
        #pragma unroll
        for (int nt = 0; nt < 8; nt++) {
            o[nt][0] *= al2[0]; o[nt][1] *= al2[0];
            o[nt][2] *= al2[1]; o[nt][3] *= al2[1];
        }
        // ---- O += P @ V_tile ----
        #pragma unroll
        for (int kc2 = 0; kc2 < 8; kc2++) {
            uint32_t pa[4], pl[4];
            #pragma unroll
            for (int u = 0; u < 2; u++) {         // u: tile 2*kc2+u (k-halves)
                #pragma unroll
                for (int hh = 0; hh < 2; hh++) {  // hh: row r / r+8
                    const float v0 = s[2 * kc2 + u][hh * 2];
                    const float v1 = s[2 * kc2 + u][hh * 2 + 1];
                    __nv_bfloat16 h0, h1, lo0, lo1;
                    split_bf16(v0, h0, lo0);
                    split_bf16(v1, h1, lo1);
                    pa[u * 2 + hh] = pack_bf(h0, h1);
                    pl[u * 2 + hh] = pack_bf(lo0, lo1);
                }
            }
            #pragma unroll
            for (int j2v = 0; j2v < 4; j2v++) {
                const int n = j2v * 16 + (mat >> 1) * 8 + l8;
                uint32_t vh4[4], vl4[4];
                const uint32_t bd = sb + FL_OFF_V(buf) + n * FL_VSTR + kc2 * 32 + (mat & 1) * 16;
                ldmx4(vh4, bd);
                ldmx4(vl4, bd + FL_VT);
                #pragma unroll
                for (int e = 0; e < 2; e++) {
                    const int nt = j2v * 2 + e;
                    mma16816(o[nt], pa, vh4[e * 2], vh4[e * 2 + 1]);
                    mma16816(o[nt], pa, vl4[e * 2], vl4[e * 2 + 1]);
                    mma16816(o[nt], pl, vh4[e * 2], vh4[e * 2 + 1]);
                }
            }
        }
        __syncthreads();
    }

    // ---- epilogue: O /= l, write f32 ----
    const float inv0 = 1.0f / l_[0], inv1 = 1.0f / l_[1];
    const int r0 = m0 + wid * 16 + (lane >> 2);
    #pragma unroll
    for (int nt = 0; nt < 8; nt++) {
        const int col = zh * 64 + nt * 8 + 2 * (lane & 3);
        *reinterpret_cast<float2*>(O + (size_t)(zb * SEQ + r0) * DMODEL + col) =
            make_float2(o[nt][0] * inv0, o[nt][1] * inv0);
        *reinterpret_cast<float2*>(O + (size_t)(zb * SEQ + r0 + 8) * DMODEL + col) =
            make_float2(o[nt][2] * inv1, o[nt][3] * inv1);
    }
}

// ---------------- launch ----------------
extern "C" void kernel_launch(void* const* d_in, const int* in_sizes, int n_in,
                              void* d_out, int out_size) {
    const int*   ids    = (const int*)  d_in[0];
    const float* embed  = (const float*)d_in[1];
    const float* Wq     = (const float*)d_in[2];
    const float* Wk     = (const float*)d_in[3];
    const float* Wv     = (const float*)d_in[4];
    const float* Wo     = (const float*)d_in[5];
    const float* relb   = (const float*)d_in[6];
    const float* wi0    = (const float*)d_in[7];
    const float* wi1    = (const float*)d_in[8];
    const float* wo_ffn = (const float*)d_in[9];
    const float* ln0    = (const float*)d_in[10];
    const float* ln1    = (const float*)d_in[11];
    const float* flw    = (const float*)d_in[12];
    float* out = (float*)d_out;

    float *x, *h, *q, *k, *v, *o, *f0, *f1, *bias;
    __nv_bfloat16 *ah, *al, *wh, *wl, *vth, *vtl;
    cudaGetSymbolAddress((void**)&x,  g_x);
    cudaGetSymbolAddress((void**)&h,  g_h);
    cudaGetSymbolAddress((void**)&q,  g_q);
    cudaGetSymbolAddress((void**)&k,  g_k);
    cudaGetSymbolAddress((void**)&v,  g_v);
    cudaGetSymbolAddress((void**)&o,  g_o);
    cudaGetSymbolAddress((void**)&f0, g_f0);
    cudaGetSymbolAddress((void**)&f1, g_f1);
    cudaGetSymbolAddress((void**)&bias, g_bias);
    cudaGetSymbolAddress((void**)&ah, g_ah);
    cudaGetSymbolAddress((void**)&al, g_al);
    cudaGetSymbolAddress((void**)&wh, g_wh);
    cudaGetSymbolAddress((void**)&wl, g_wl);
    cudaGetSymbolAddress((void**)&vth, g_vth);
    cudaGetSymbolAddress((void**)&vtl, g_vtl);

    cudaFuncSetAttribute(mgemm_k<0>, cudaFuncAttributeMaxDynamicSharedMemorySize, MG_SMEM);
    cudaFuncSetAttribute(mgemm_k<1>, cudaFuncAttributeMaxDynamicSharedMemorySize, MG_SMEM);
    cudaFuncSetAttribute(flash_k, cudaFuncAttributeMaxDynamicSharedMemorySize, FL_SMEM);

    float* out_bias = ((size_t)out_size > OUTX) ? (out + OUTX) : nullptr;

    embed_k<<<NROWS, 256>>>(ids, embed, x);
    {
        size_t nb = ((size_t)NH * SEQ * SEQ + 255) / 256;
        bias_k<<<(unsigned)nb, 256>>>(relb, bias, out_bias);
    }

    const size_t DD  = (size_t)DMODEL * DMODEL;
    const size_t DF  = (size_t)DMODEL * DFF_;
    const size_t QK  = (size_t)NROWS * DMODEL;

    for (int i = 0; i < NL; i++) {
        // ---- self attention ----
        rms_k<<<NROWS, 256>>>(x, ln0 + (size_t)i * DMODEL, h);
        cvt_act_k<<<NROWS * DMODEL / 1024, 256>>>(h, ah, al, NROWS * DMODEL);
        {
            dim3 gW(DMODEL / 32, DMODEL / 32);
            cvt_wt_k<<<gW, 256>>>(Wq + i * DD, wh,          wl,          DMODEL, DMODEL);
            cvt_wt_k<<<gW, 256>>>(Wk + i * DD, wh + DD,     wl + DD,     DMODEL, DMODEL);
            cvt_wt_k<<<gW, 256>>>(Wv + i * DD, wh + 2 * DD, wl + 2 * DD, DMODEL, DMODEL);
        }
        mgemm_k<0><<<dim3(4, 32, 3), 256, MG_SMEM>>>(ah, al, wh, wl,
                                                     q, k, v, nullptr,
                                                     DMODEL, DMODEL, DD);
        // split q/k; transpose+split v
        cvt_act_k<<<NROWS * DMODEL / 1024, 256>>>(q, ah, al, NROWS * DMODEL);
        cvt_act_k<<<NROWS * DMODEL / 1024, 256>>>(k, ah + QK, al + QK, NROWS * DMODEL);
        cvt_vt_k<<<dim3(SEQ / 32, DHEAD / 32, BATCH * NH), 256>>>(v, vth, vtl);
        // fused attention
        flash_k<<<dim3(SEQ / 128, 1, BATCH * NH), 256, FL_SMEM>>>(
            ah, al, ah + QK, al + QK, vth, vtl, bias, o);
        // x = x + o @ Wo
        cvt_act_k<<<NROWS * DMODEL / 1024, 256>>>(o, ah, al, NROWS * DMODEL);
        cvt_wt_k<<<dim3(DMODEL / 32, DMODEL / 32), 256>>>(Wo + i * DD, wh, wl, DMODEL, DMODEL);
        mgemm_k<1><<<dim3(4, 32, 1), 256, MG_SMEM>>>(ah, al, wh, wl,
                                                     x, x, x, x,
                                                     DMODEL, DMODEL, 0);
        // ---- gated-GELU FFN ----
        rms_k<<<NROWS, 256>>>(x, ln1 + (size_t)i * DMODEL, h);
        cvt_act_k<<<NROWS * DMODEL / 1024, 256>>>(h, ah, al, NROWS * DMODEL);
        {
            dim3 gW(DFF_ / 32, DMODEL / 32);
            cvt_wt_k<<<gW, 256>>>(wi0 + i * DF, wh,      wl,      DMODEL, DFF_);
            cvt_wt_k<<<gW, 256>>>(wi1 + i * DF, wh + DF, wl + DF, DMODEL, DFF_);
        }
        mgemm_k<0><<<dim3(8, 32, 2), 256, MG_SMEM>>>(ah, al, wh, wl,
                                                     f0, f1, f1, nullptr,
                                                     DMODEL, DFF_, DF);
        geglu_k<<<4096, 256>>>(f0, f1, NROWS * DFF_);
        cvt_act_k<<<NROWS * DFF_ / 1024, 256>>>(f0, ah, al, NROWS * DFF_);
        cvt_wt_k<<<dim3(DMODEL / 32, DFF_ / 32), 256>>>(wo_ffn + i * DF, wh, wl, DFF_, DMODEL);
        mgemm_k<1><<<dim3(4, 32, 1), 256, MG_SMEM>>>(ah, al, wh, wl,
                                                     x, x, x, x,
                                                     DFF_, DMODEL, 0);
    }
    rms_k<<<NROWS, 256>>>(x, flw, out);
}

// round 10
// speedup vs baseline: 2.2842x; 1.0505x over previous
#include <cuda_runtime.h>
#include <cuda_bf16.h>
#include <cstdint>
#include <math.h>

#define NL    4
#define DMODEL 512
#define NH    8
#define DHEAD 64
#define DFF_  1024
#define SEQ   2048
#define BATCH 2
#define NROWS (BATCH*SEQ)          // 4096
#define OUTX  ((size_t)NROWS*DMODEL)  // 2097152
#define QKSZ  ((size_t)NROWS*DMODEL)  // 2M elements

typedef unsigned long long u64;

// ---------------- scratch ----------------
__device__ float g_x [NROWS*DMODEL];
__device__ float g_v [NROWS*DMODEL];
__device__ float g_f0[NROWS*DFF_];
__device__ float g_f1[NROWS*DFF_];
__device__ float g_bias[(size_t)NH*SEQ*SEQ];               // pos bias
// bf16 split buffers
__device__ __nv_bfloat16 g_ah[NROWS*DFF_];                 // 4M: slot0 [0,2M) + slot1 [2M,4M)
__device__ __nv_bfloat16 g_al[NROWS*DFF_];
__device__ __nv_bfloat16 g_oh[NROWS*DMODEL];               // q-split / spare
__device__ __nv_bfloat16 g_ol[NROWS*DMODEL];
__device__ __nv_bfloat16 g_wh[DMODEL*DFF_*2];
__device__ __nv_bfloat16 g_wl[DMODEL*DFF_*2];
__device__ __nv_bfloat16 g_vth[(size_t)BATCH*NH*DHEAD*SEQ]; // V^T hi [B,H,DH,S]
__device__ __nv_bfloat16 g_vtl[(size_t)BATCH*NH*DHEAD*SEQ];

// ---------------- helpers ----------------
__device__ __forceinline__ uint32_t smem_u32(const void* p) {
    uint32_t a;
    asm("{ .reg .u64 t; cvta.to.shared.u64 t, %1; cvt.u32.u64 %0, t; }" : "=r"(a) : "l"(p));
    return a;
}
#define CP_ASYNC16(sa, ga) \
    asm volatile("cp.async.cg.shared.global [%0], [%1], 16;" :: "r"(sa), "l"(ga))
#define CP_COMMIT() asm volatile("cp.async.commit_group;" ::: "memory")
template <int N>
__device__ __forceinline__ void cp_wait() {
    asm volatile("cp.async.wait_group %0;" :: "n"(N) : "memory");
}
__device__ __forceinline__ void ldmx4(uint32_t* r, uint32_t addr) {
    asm volatile("ldmatrix.sync.aligned.m8n8.x4.shared.b16 {%0,%1,%2,%3}, [%4];"
                 : "=r"(r[0]), "=r"(r[1]), "=r"(r[2]), "=r"(r[3]) : "r"(addr));
}
__device__ __forceinline__ void mma16816(float* d, const uint32_t* a,
                                         uint32_t b0, uint32_t b1) {
    asm volatile(
        "mma.sync.aligned.m16n8k16.row.col.f32.bf16.bf16.f32 "
        "{%0,%1,%2,%3}, {%4,%5,%6,%7}, {%8,%9}, {%0,%1,%2,%3};"
        : "+f"(d[0]), "+f"(d[1]), "+f"(d[2]), "+f"(d[3])
        : "r"(a[0]), "r"(a[1]), "r"(a[2]), "r"(a[3]), "r"(b0), "r"(b1));
}
__device__ __forceinline__ uint32_t pack_bf(__nv_bfloat16 a, __nv_bfloat16 b) {
    __nv_bfloat162 p(a, b);
    return *reinterpret_cast<uint32_t*>(&p);
}
__device__ __forceinline__ void split_bf16(float v, __nv_bfloat16& h, __nv_bfloat16& l) {
    h = __float2bfloat16(v);
    l = __float2bfloat16(v - __bfloat162float(h));
}
// split float2 -> two bf162 words written to hi/lo arrays
__device__ __forceinline__ void split_store2(float a, float b,
                                             __nv_bfloat16* hi, __nv_bfloat16* lo) {
    __nv_bfloat16 h0, h1, l0, l1;
    split_bf16(a, h0, l0);
    split_bf16(b, h1, l1);
    *reinterpret_cast<uint32_t*>(hi) = pack_bf(h0, h1);
    *reinterpret_cast<uint32_t*>(lo) = pack_bf(l0, l1);
}

// ---------------- small kernels ----------------
__global__ __launch_bounds__(256) void embed_k(const int* __restrict__ ids,
                                               const float* __restrict__ emb,
                                               float* __restrict__ x) {
    const int row = blockIdx.x;
    const size_t src = (size_t)ids[row] * DMODEL;
    const size_t dst = (size_t)row * DMODEL;
    for (int i = threadIdx.x; i < DMODEL; i += 256) x[dst + i] = emb[src + i];
}

__global__ __launch_bounds__(256) void bias_k(const float* __restrict__ rb,
                                              float* __restrict__ bias,
                                              float* __restrict__ out2) {
    size_t idx = (size_t)blockIdx.x * 256 + threadIdx.x;
    if (idx >= (size_t)NH * SEQ * SEQ) return;
    int kk = (int)(idx & (SEQ - 1));
    int qq = (int)((idx >> 11) & (SEQ - 1));
    int hh = (int)(idx >> 22);
    int rel = kk - qq;
    int bucket = (rel > 0) ? 16 : 0;
    int rp = (rel < 0) ? -rel : rel;
    int add;
    if (rp < 8) {
        add = rp;
    } else {
        float t = logf((float)rp / 8.0f);
        t = t / 2.7725887298583984f;
        t = t * 8.0f;
        add = 8 + (int)t;
        if (add > 15) add = 15;
    }
    float val = rb[(bucket + add) * NH + hh];
    bias[idx] = val;
    if (out2) out2[idx] = val;
}

// RMS layernorm -> split bf16 hi/lo
__global__ __launch_bounds__(256) void rms_split_k(const float* __restrict__ x,
                                                   const float* __restrict__ w,
                                                   __nv_bfloat16* __restrict__ hi,
                                                   __nv_bfloat16* __restrict__ lo) {
    const size_t base = (size_t)blockIdx.x * DMODEL;
    const int t = threadIdx.x;
    float v0 = x[base + t], v1 = x[base + t + 256];
    float ss = v0 * v0 + v1 * v1;
    #pragma unroll
    for (int off = 16; off; off >>= 1) ss += __shfl_xor_sync(0xffffffffu, ss, off);
    __shared__ float red[8];
    __shared__ float bval;
    if ((t & 31) == 0) red[t >> 5] = ss;
    __syncthreads();
    if (t == 0) {
        float tot = 0.f;
        #pragma unroll
        for (int i = 0; i < 8; i++) tot += red[i];
        bval = rsqrtf(tot * (1.0f / DMODEL) + 1e-6f);
    }
    __syncthreads();
    const float inv = bval;
    float y0 = w[t] * (v0 * inv);
    float y1 = w[t + 256] * (v1 * inv);
    __nv_bfloat16 h, l;
    split_bf16(y0, h, l);
    hi[base + t] = h; lo[base + t] = l;
    split_bf16(y1, h, l);
    hi[base + t + 256] = h; lo[base + t + 256] = l;
}

// final RMS layernorm -> f32 out
__global__ __launch_bounds__(256) void rms_k(const float* __restrict__ x,
                                             const float* __restrict__ w,
                                             float* __restrict__ y) {
    const size_t base = (size_t)blockIdx.x * DMODEL;
    const int t = threadIdx.x;
    float v0 = x[base + t], v1 = x[base + t + 256];
    float ss = v0 * v0 + v1 * v1;
    #pragma unroll
    for (int off = 16; off; off >>= 1) ss += __shfl_xor_sync(0xffffffffu, ss, off);
    __shared__ float red[8];
    __shared__ float bval;
    if ((t & 31) == 0) red[t >> 5] = ss;
    __syncthreads();
    if (t == 0) {
        float tot = 0.f;
        #pragma unroll
        for (int i = 0; i < 8; i++) tot += red[i];
        bval = rsqrtf(tot * (1.0f / DMODEL) + 1e-6f);
    }
    __syncthreads();
    const float inv = bval;
    y[base + t]       = w[t]       * (v0 * inv);
    y[base + t + 256] = w[t + 256] * (v1 * inv);
}

// gated-GELU -> split bf16 hi/lo
__global__ __launch_bounds__(256) void geglu_split_k(const float* __restrict__ f0,
                                                     const float* __restrict__ f1,
                                                     __nv_bfloat16* __restrict__ hi,
                                                     __nv_bfloat16* __restrict__ lo, int n) {
    int i = (blockIdx.x * 256 + threadIdx.x) * 2;
    if (i >= n) return;
    float2 a = *reinterpret_cast<const float2*>(f0 + i);
    float2 b = *reinterpret_cast<const float2*>(f1 + i);
    float r0, r1;
    {
        float xx = a.x;
        float inner = 0.7978845608028654f * (xx + 0.044715f * (xx * xx * xx));
        r0 = 0.5f * xx * (1.0f + tanhf(inner)) * b.x;
    }
    {
        float xx = a.y;
        float inner = 0.7978845608028654f * (xx + 0.044715f * (xx * xx * xx));
        r1 = 0.5f * xx * (1.0f + tanhf(inner)) * b.y;
    }
    split_store2(r0, r1, hi + i, lo + i);
}

// W[K,N] f32 -> transposed Wt[N,K] hi/lo bf16
__global__ __launch_bounds__(256) void cvt_wt_k(const float* __restrict__ W,
                                                __nv_bfloat16* __restrict__ th,
                                                __nv_bfloat16* __restrict__ tl,
                                                int Kd, int Nd) {
    __shared__ float tile[32][33];
    int kb = blockIdx.y * 32, nb = blockIdx.x * 32;
    int tx = threadIdx.x & 31, ty = threadIdx.x >> 5;
    for (int r = ty; r < 32; r += 8)
        tile[r][tx] = W[(size_t)(kb + r) * Nd + nb + tx];
    __syncthreads();
    for (int r = ty; r < 32; r += 8) {
        float v = tile[tx][r];
        __nv_bfloat16 h, l;
        split_bf16(v, h, l);
        size_t oidx = (size_t)(nb + r) * Kd + kb + tx;
        th[oidx] = h;
        tl[oidx] = l;
    }
}
// V [NROWS, 512] f32 -> V^T [B,H,DH,S] hi/lo bf16
__global__ __launch_bounds__(256) void cvt_vt_k(const float* __restrict__ v,
                                                __nv_bfloat16* __restrict__ th,
                                                __nv_bfloat16* __restrict__ tl) {
    __shared__ float tile[32][33];
    const int z = blockIdx.z;
    const int zb = z >> 3, zh = z & 7;
    const int s0 = blockIdx.x * 32;
    const int d0 = blockIdx.y * 32;
    const int tx = threadIdx.x & 31, ty = threadIdx.x >> 5;
    for (int r = ty; r < 32; r += 8)
        tile[r][tx] = v[(size_t)(zb * SEQ + s0 + r) * DMODEL + zh * DHEAD + d0 + tx];
    __syncthreads();
    for (int r = ty; r < 32; r += 8) {
        float val = tile[tx][r];
        __nv_bfloat16 h, l;
        split_bf16(val, h, l);
        size_t oidx = ((size_t)z * DHEAD + d0 + r) * SEQ + s0 + tx;
        th[oidx] = h;
        tl[oidx] = l;
    }
}

// ---------------- warp-MMA bf16x3 GEMM core macroized pieces ----------------
#define MG_ROWB   80
#define MG_TILE   (128 * MG_ROWB)
#define MG_BUF    (4 * MG_TILE)
#define MG_SMEM   (2 * MG_BUF)

// Dense GEMM. EPI: 0 plain f32, 1 f32 + residual E.
template <int EPI>
__global__ __launch_bounds__(256) void mgemm_k(
    const __nv_bfloat16* __restrict__ ah, const __nv_bfloat16* __restrict__ al,
    const __nv_bfloat16* __restrict__ wh, const __nv_bfloat16* __restrict__ wl,
    float* C0, float* C1, float* C2,
    const float* __restrict__ E, int K, int ldc, size_t wSlot)
{
    extern __shared__ char smem[];
    const uint32_t sb = smem_u32(smem);
    const int t = threadIdx.x;
    const int lane = t & 31, wid = t >> 5;
    const int wr = wid & 1, wc = wid >> 1;
    const int z = blockIdx.z;
    const __nv_bfloat16* Bh = wh + (size_t)z * wSlot;
    const __nv_bfloat16* Bl = wl + (size_t)z * wSlot;
    float* C = (z == 0) ? C0 : (z == 1) ? C1 : C2;
    const int m0 = blockIdx.y * 128, n0 = blockIdx.x * 128;

    float d[4][4][4];
    #pragma unroll
    for (int mi = 0; mi < 4; mi++)
        #pragma unroll
        for (int nj = 0; nj < 4; nj++)
            #pragma unroll
            for (int r = 0; r < 4; r++) d[mi][nj][r] = 0.f;

    const int lr = t >> 2;
    const int lc = t & 3;
    const __nv_bfloat16* srcs[4] = { ah, al, Bh, Bl };

    auto issue = [&](int kc, int buf) {
        const uint32_t base = sb + buf * MG_BUF;
        #pragma unroll
        for (int tile = 0; tile < 4; tile++) {
            const __nv_bfloat16* s = srcs[tile];
            const int baseRow = (tile < 2) ? m0 : n0;
            #pragma unroll
            for (int h = 0; h < 2; h++) {
                const int row = lr + h * 64;
                const __nv_bfloat16* g = s + (size_t)(baseRow + row) * K + kc * 32 + lc * 8;
                CP_ASYNC16(base + tile * MG_TILE + row * MG_ROWB + lc * 16, g);
            }
        }
        CP_COMMIT();
    };

    const int nch = K >> 5;
    issue(0, 0);

    const int mat = lane >> 3, l8 = lane & 7;
    for (int kc = 0; kc < nch; kc++) {
        const int buf = kc & 1;
        if (kc + 1 < nch) { issue(kc + 1, buf ^ 1); cp_wait<1>(); }
        else              { cp_wait<0>(); }
        __syncthreads();
        const uint32_t bbase = sb + buf * MG_BUF;
        #pragma unroll
        for (int kk = 0; kk < 2; kk++) {
            uint32_t Ah[4][4], Al[4][4], Bhf[2][4], Blf[2][4];
            #pragma unroll
            for (int mi = 0; mi < 4; mi++) {
                const int row = wr * 64 + mi * 16 + (mat & 1) * 8 + l8;
                const uint32_t ad = bbase + row * MG_ROWB + kk * 32 + (mat >> 1) * 16;
                ldmx4(Ah[mi], ad);
                ldmx4(Al[mi], ad + MG_TILE);
            }
            #pragma unroll
            for (int nj2 = 0; nj2 < 2; nj2++) {
                const int n = wc * 32 + nj2 * 16 + (mat >> 1) * 8 + l8;
                const uint32_t bd = bbase + 2 * MG_TILE + n * MG_ROWB + kk * 32 + (mat & 1) * 16;
                ldmx4(Bhf[nj2], bd);
                ldmx4(Blf[nj2], bd + MG_TILE);
            }
            #pragma unroll
            for (int mi = 0; mi < 4; mi++)
                #pragma unroll
                for (int nj = 0; nj < 4; nj++) {
                    const int g = nj >> 1, o = (nj & 1) * 2;
                    mma16816(d[mi][nj], Ah[mi], Bhf[g][o], Bhf[g][o + 1]);
                    mma16816(d[mi][nj], Ah[mi], Blf[g][o], Blf[g][o + 1]);
                    mma16816(d[mi][nj], Al[mi], Bhf[g][o], Bhf[g][o + 1]);
                }
        }
        __syncthreads();
    }

    #pragma unroll
    for (int mi = 0; mi < 4; mi++) {
        #pragma unroll
        for (int nj = 0; nj < 4; nj++) {
            const int row = m0 + wr * 64 + mi * 16 + (lane >> 2);
            const int col = n0 + wc * 32 + nj * 8 + (lane & 3) * 2;
            #pragma unroll
            for (int hh = 0; hh < 2; hh++) {
                const int m = row + hh * 8;
                float2 cv = make_float2(d[mi][nj][hh * 2], d[mi][nj][hh * 2 + 1]);
                if constexpr (EPI == 1) {
                    const float2 rv = *reinterpret_cast<const float2*>(
                        E + (size_t)m * ldc + col);
                    cv.x += rv.x; cv.y += rv.y;
                }
                *reinterpret_cast<float2*>(C + (size_t)m * ldc + col) = cv;
            }
        }
    }
}

// QKV GEMM: z=0 -> split bf16 (qh,ql); z=1 -> split (kh,kl); z=2 -> f32 v.
__global__ __launch_bounds__(256) void mgemm_qkv_k(
    const __nv_bfloat16* __restrict__ ah, const __nv_bfloat16* __restrict__ al,
    const __nv_bfloat16* __restrict__ wh, const __nv_bfloat16* __restrict__ wl,
    __nv_bfloat16* __restrict__ qh, __nv_bfloat16* __restrict__ ql,
    __nv_bfloat16* __restrict__ kh, __nv_bfloat16* __restrict__ kl,
    float* __restrict__ vout, size_t wSlot)
{
    constexpr int K = DMODEL;
    extern __shared__ char smem[];
    const uint32_t sb = smem_u32(smem);
    const int t = threadIdx.x;
    const int lane = t & 31, wid = t >> 5;
    const int wr = wid & 1, wc = wid >> 1;
    const int z = blockIdx.z;
    const __nv_bfloat16* Bh = wh + (size_t)z * wSlot;
    const __nv_bfloat16* Bl = wl + (size_t)z * wSlot;
    const int m0 = blockIdx.y * 128, n0 = blockIdx.x * 128;

    float d[4][4][4];
    #pragma unroll
    for (int mi = 0; mi < 4; mi++)
        #pragma unroll
        for (int nj = 0; nj < 4; nj++)
            #pragma unroll
            for (int r = 0; r < 4; r++) d[mi][nj][r] = 0.f;

    const int lr = t >> 2;
    const int lc = t & 3;
    const __nv_bfloat16* srcs[4] = { ah, al, Bh, Bl };

    auto issue = [&](int kc, int buf) {
        const uint32_t base = sb + buf * MG_BUF;
        #pragma unroll
        for (int tile = 0; tile < 4; tile++) {
            const __nv_bfloat16* s = srcs[tile];
            const int baseRow = (tile < 2) ? m0 : n0;
            #pragma unroll
            for (int h = 0; h < 2; h++) {
                const int row = lr + h * 64;
                const __nv_bfloat16* g = s + (size_t)(baseRow + row) * K + kc * 32 + lc * 8;
                CP_ASYNC16(base + tile * MG_TILE + row * MG_ROWB + lc * 16, g);
            }
        }
        CP_COMMIT();
    };

    const int nch = K >> 5;
    issue(0, 0);

    const int mat = lane >> 3, l8 = lane & 7;
    for (int kc = 0; kc < nch; kc++) {
        const int buf = kc & 1;
        if (kc + 1 < nch) { issue(kc + 1, buf ^ 1); cp_wait<1>(); }
        else              { cp_wait<0>(); }
        __syncthreads();
        const uint32_t bbase = sb + buf * MG_BUF;
        #pragma unroll
        for (int kk = 0; kk < 2; kk++) {
            uint32_t Ah[4][4], Al[4][4], Bhf[2][4], Blf[2][4];
            #pragma unroll
            for (int mi = 0; mi < 4; mi++) {
                const int row = wr * 64 + mi * 16 + (mat & 1) * 8 + l8;
                const uint32_t ad = bbase + row * MG_ROWB + kk * 32 + (mat >> 1) * 16;
                ldmx4(Ah[mi], ad);
                ldmx4(Al[mi], ad + MG_TILE);
            }
            #pragma unroll
            for (int nj2 = 0; nj2 < 2; nj2++) {
                const int n = wc * 32 + nj2 * 16 + (mat >> 1) * 8 + l8;
                const uint32_t bd = bbase + 2 * MG_TILE + n * MG_ROWB + kk * 32 + (mat & 1) * 16;
                ldmx4(Bhf[nj2], bd);
                ldmx4(Blf[nj2], bd + MG_TILE);
            }
            #pragma unroll
            for (int mi = 0; mi < 4; mi++)
                #pragma unroll
                for (int nj = 0; nj < 4; nj++) {
                    const int g = nj >> 1, o = (nj & 1) * 2;
                    mma16816(d[mi][nj], Ah[mi], Bhf[g][o], Bhf[g][o + 1]);
                    mma16816(d[mi][nj], Ah[mi], Blf[g][o], Blf[g][o + 1]);
                    mma16816(d[mi][nj], Al[mi], Bhf[g][o], Bhf[g][o + 1]);
                }
        }
        __syncthreads();
    }

    __nv_bfloat16* H = (z == 0) ? qh : kh;
    __nv_bfloat16* L = (z == 0) ? ql : kl;
    #pragma unroll
    for (int mi = 0; mi < 4; mi++) {
        #pragma unroll
        for (int nj = 0; nj < 4; nj++) {
            const int row = m0 + wr * 64 + mi * 16 + (lane >> 2);
            const int col = n0 + wc * 32 + nj * 8 + (lane & 3) * 2;
            #pragma unroll
            for (int hh = 0; hh < 2; hh++) {
                const int m = row + hh * 8;
                const size_t off = (size_t)m * DMODEL + col;
                if (z == 2) {
                    *reinterpret_cast<float2*>(vout + off) =
                        make_float2(d[mi][nj][hh * 2], d[mi][nj][hh * 2 + 1]);
                } else {
                    split_store2(d[mi][nj][hh * 2], d[mi][nj][hh * 2 + 1],
                                 H + off, L + off);
                }
            }
        }
    }
}

// ---------------- fused flash attention (bf16x3 MMA, online softmax) ----------------
#define FL_QSTR 144
#define FL_VSTR 272
#define FL_QT   (128 * FL_QSTR)
#define FL_VT   (64 * FL_VSTR)
#define FL_OFF_K(buf) (2 * FL_QT + (buf) * 2 * FL_QT)
#define FL_OFF_V(buf) (6 * FL_QT + (buf) * 2 * FL_VT)
#define FL_SMEM (6 * FL_QT + 4 * FL_VT)
__global__ __launch_bounds__(256) void flash_k(
    const __nv_bfloat16* __restrict__ qh_g, const __nv_bfloat16* __restrict__ ql_g,
    const __nv_bfloat16* __restrict__ kh_g, const __nv_bfloat16* __restrict__ kl_g,
    const __nv_bfloat16* __restrict__ vth_g, const __nv_bfloat16* __restrict__ vtl_g,
    const float* __restrict__ bias,
    __nv_bfloat16* __restrict__ Ohi, __nv_bfloat16* __restrict__ Olo)
{
    extern __shared__ char smem[];
    const uint32_t sb = smem_u32(smem);
    const int t = threadIdx.x, lane = t & 31, wid = t >> 5;
    const int z = blockIdx.z, zb = z >> 3, zh = z & 7;
    const int m0 = blockIdx.x * 128;
    const int mat = lane >> 3, l8 = lane & 7;

    auto loadQ = [&]() {
        #pragma unroll
        for (int i = 0; i < 4; i++) {
            int idx = t + i * 256, row = idx >> 3, c = idx & 7;
            size_t go = (size_t)(zb * SEQ + m0 + row) * DMODEL + zh * 64 + c * 8;
            CP_ASYNC16(sb + row * FL_QSTR + c * 16, qh_g + go);
            CP_ASYNC16(sb + FL_QT + row * FL_QSTR + c * 16, ql_g + go);
        }
    };
    auto loadKV = [&](int kt, int buf) {
        #pragma unroll
        for (int i = 0; i < 4; i++) {
            int idx = t + i * 256, row = idx >> 3, c = idx & 7;
            size_t go = (size_t)(zb * SEQ + kt * 128 + row) * DMODEL + zh * 64 + c * 8;
            CP_ASYNC16(sb + FL_OFF_K(buf) + row * FL_QSTR + c * 16, kh_g + go);
            CP_ASYNC16(sb + FL_OFF_K(buf) + FL_QT + row * FL_QSTR + c * 16, kl_g + go);
        }
        #pragma unroll
        for (int i = 0; i < 4; i++) {
            int idx = t + i * 256, row = idx >> 4, c = idx & 15;
            size_t go = (size_t)(z * 64 + row) * SEQ + kt * 128 + c * 8;
            CP_ASYNC16(sb + FL_OFF_V(buf) + row * FL_VSTR + c * 16, vth_g + go);
            CP_ASYNC16(sb + FL_OFF_V(buf) + FL_VT + row * FL_VSTR + c * 16, vtl_g + go);
        }
        CP_COMMIT();
    };

    loadQ();
    loadKV(0, 0);

    float m_[2] = { -1e30f, -1e30f }, l_[2] = { 0.f, 0.f };
    float o[8][4];
    #pragma unroll
    for (int nt = 0; nt < 8; nt++)
        #pragma unroll
        for (int e = 0; e < 4; e++) o[nt][e] = 0.f;
    uint32_t qh[4][4], ql[4][4];

    for (int kt = 0; kt < 16; kt++) {
        const int buf = kt & 1;
        if (kt + 1 < 16) { loadKV(kt + 1, buf ^ 1); cp_wait<1>(); }
        else             { cp_wait<0>(); }
        __syncthreads();
        if (kt == 0) {
            #pragma unroll
            for (int kc = 0; kc < 4; kc++) {
                const int row = wid * 16 + (mat & 1) * 8 + l8;
                const uint32_t ad = sb + row * FL_QSTR + kc * 32 + (mat >> 1) * 16;
                ldmx4(qh[kc], ad);
                ldmx4(ql[kc], ad + FL_QT);
            }
        }
        float s[16][4];
        #pragma unroll
        for (int j = 0; j < 16; j++)
            #pragma unroll
            for (int e = 0; e < 4; e++) s[j][e] = 0.f;
        #pragma unroll
        for (int j2 = 0; j2 < 8; j2++) {
            const int n = j2 * 16 + (mat >> 1) * 8 + l8;
            #pragma unroll
            for (int kc = 0; kc < 4; kc++) {
                uint32_t bh4[4], bl4[4];
                const uint32_t bd = sb + FL_OFF_K(buf) + n * FL_QSTR + kc * 32 + (mat & 1) * 16;
                ldmx4(bh4, bd);
                ldmx4(bl4, bd + FL_QT);
                #pragma unroll
                for (int e = 0; e < 2; e++) {
                    mma16816(s[j2 * 2 + e], qh[kc], bh4[e * 2], bh4[e * 2 + 1]);
                    mma16816(s[j2 * 2 + e], qh[kc], bl4[e * 2], bl4[e * 2 + 1]);
                    mma16816(s[j2 * 2 + e], ql[kc], bh4[e * 2], bh4[e * 2 + 1]);
                }
            }
        }
        const int r0 = m0 + wid * 16 + (lane >> 2);
        #pragma unroll
        for (int j = 0; j < 16; j++) {
            const int col = kt * 128 + j * 8 + 2 * (lane & 3);
            const float2 b0 = *reinterpret_cast<const float2*>(
                bias + ((size_t)zh * SEQ + r0) * SEQ + col);
            const float2 b1 = *reinterpret_cast<const float2*>(
                bias + ((size_t)zh * SEQ + r0 + 8) * SEQ + col);
            s[j][0] += b0.x; s[j][1] += b0.y;
            s[j][2] += b1.x; s[j][3] += b1.y;
        }
        float mx[2] = { -1e30f, -1e30f };
        #pragma unroll
        for (int j = 0; j < 16; j++) {
            mx[0] = fmaxf(mx[0], fmaxf(s[j][0], s[j][1]));
            mx[1] = fmaxf(mx[1], fmaxf(s[j][2], s[j][3]));
        }
        #pragma unroll
        for (int off = 1; off <= 2; off <<= 1) {
            mx[0] = fmaxf(mx[0], __shfl_xor_sync(0xffffffffu, mx[0], off));
            mx[1] = fmaxf(mx[1], __shfl_xor_sync(0xffffffffu, mx[1], off));
        }
        float al2[2];
        #pragma unroll
        for (int h = 0; h < 2; h++) {
            const float nm = fmaxf(m_[h], mx[h]);
            al2[h] = __expf(m_[h] - nm);
            m_[h] = nm;
        }
        float rs[2] = { 0.f, 0.f };
        #pragma unroll
        for (int j = 0; j < 16; j++) {
            s[j][0] = __expf(s[j][0] - m_[0]);
            s[j][1] = __expf(s[j][1] - m_[0]);
            s[j][2] = __expf(s[j][2] - m_[1]);
            s[j][3] = __expf(s[j][3] - m_[1]);
            rs[0] += s[j][0] + s[j][1];
            rs[1] += s[j][2] + s[j][3];
        }
        #pragma unroll
        for (int off = 1; off <= 2; off <<= 1) {
            rs[0] += __shfl_xor_sync(0xffffffffu, rs[0], off);
            rs[1] += __shfl_xor_sync(0xffffffffu, rs[1], off);
        }
        l_[0] = l_[0] * al2[0] + rs[0];
        l_[1] = l_[1] * al2[1] + rs[1];
        #pragma unroll
        for (int nt = 0; nt < 8; nt++) {
            o[nt][0] *= al2[0]; o[nt][1] *= al2[0];
            o[nt][2] *= al2[1]; o[nt][3] *= al2[1];
        }
        #pragma unroll
        for (int kc2 = 0; kc2 < 8; kc2++) {
            uint32_t pa[4], pl[4];
            #pragma unroll
            for (int u = 0; u < 2; u++) {
                #pragma unroll
                for (int hh = 0; hh < 2; hh++) {
                    const float v0 = s[2 * kc2 + u][hh * 2];
                    const float v1 = s[2 * kc2 + u][hh * 2 + 1];
                    __nv_bfloat16 h0, h1, lo0, lo1;
                    split_bf16(v0, h0, lo0);
                    split_bf16(v1, h1, lo1);
                    pa[u * 2 + hh] = pack_bf(h0, h1);
                    pl[u * 2 + hh] = pack_bf(lo0, lo1);
                }
            }
            #pragma unroll
            for (int j2v = 0; j2v < 4; j2v++) {
                const int n = j2v * 16 + (mat >> 1) * 8 + l8;
                uint32_t vh4[4], vl4[4];
                const uint32_t bd = sb + FL_OFF_V(buf) + n * FL_VSTR + kc2 * 32 + (mat & 1) * 16;
                ldmx4(vh4, bd);
                ldmx4(vl4, bd + FL_VT);
                #pragma unroll
                for (int e = 0; e < 2; e++) {
                    const int nt = j2v * 2 + e;
                    mma16816(o[nt], pa, vh4[e * 2], vh4[e * 2 + 1]);
                    mma16816(o[nt], pa, vl4[e * 2], vl4[e * 2 + 1]);
                    mma16816(o[nt], pl, vh4[e * 2], vh4[e * 2 + 1]);
                }
            }
        }
        __syncthreads();
    }

    // epilogue: O /= l, split-store bf16
    const float inv0 = 1.0f / l_[0], inv1 = 1.0f / l_[1];
    const int r0 = m0 + wid * 16 + (lane >> 2);
    #pragma unroll
    for (int nt = 0; nt < 8; nt++) {
        const int col = zh * 64 + nt * 8 + 2 * (lane & 3);
        const size_t o0 = (size_t)(zb * SEQ + r0) * DMODEL + col;
        const size_t o1 = (size_t)(zb * SEQ + r0 + 8) * DMODEL + col;
        split_store2(o[nt][0] * inv0, o[nt][1] * inv0, Ohi + o0, Olo + o0);
        split_store2(o[nt][2] * inv1, o[nt][3] * inv1, Ohi + o1, Olo + o1);
    }
}

// ---------------- launch ----------------
extern "C" void kernel_launch(void* const* d_in, const int* in_sizes, int n_in,
                              void* d_out, int out_size) {
    const int*   ids    = (const int*)  d_in[0];
    const float* embed  = (const float*)d_in[1];
    const float* Wq     = (const float*)d_in[2];
    const float* Wk     = (const float*)d_in[3];
    const float* Wv     = (const float*)d_in[4];
    const float* Wo     = (const float*)d_in[5];
    const float* relb   = (const float*)d_in[6];
    const float* wi0    = (const float*)d_in[7];
    const float* wi1    = (const float*)d_in[8];
    const float* wo_ffn = (const float*)d_in[9];
    const float* ln0    = (const float*)d_in[10];
    const float* ln1    = (const float*)d_in[11];
    const float* flw    = (const float*)d_in[12];
    float* out = (float*)d_out;

    float *x, *v, *f0, *f1, *bias;
    __nv_bfloat16 *ah, *al, *oh, *ol, *wh, *wl, *vth, *vtl;
    cudaGetSymbolAddress((void**)&x,  g_x);
    cudaGetSymbolAddress((void**)&v,  g_v);
    cudaGetSymbolAddress((void**)&f0, g_f0);
    cudaGetSymbolAddress((void**)&f1, g_f1);
    cudaGetSymbolAddress((void**)&bias, g_bias);
    cudaGetSymbolAddress((void**)&ah, g_ah);
    cudaGetSymbolAddress((void**)&al, g_al);
    cudaGetSymbolAddress((void**)&oh, g_oh);
    cudaGetSymbolAddress((void**)&ol, g_ol);
    cudaGetSymbolAddress((void**)&wh, g_wh);
    cudaGetSymbolAddress((void**)&wl, g_wl);
    cudaGetSymbolAddress((void**)&vth, g_vth);
    cudaGetSymbolAddress((void**)&vtl, g_vtl);

    cudaFuncSetAttribute(mgemm_k<0>, cudaFuncAttributeMaxDynamicSharedMemorySize, MG_SMEM);
    cudaFuncSetAttribute(mgemm_k<1>, cudaFuncAttributeMaxDynamicSharedMemorySize, MG_SMEM);
    cudaFuncSetAttribute(mgemm_qkv_k, cudaFuncAttributeMaxDynamicSharedMemorySize, MG_SMEM);
    cudaFuncSetAttribute(flash_k, cudaFuncAttributeMaxDynamicSharedMemorySize, FL_SMEM);

    float* out_bias = ((size_t)out_size > OUTX) ? (out + OUTX) : nullptr;

    embed_k<<<NROWS, 256>>>(ids, embed, x);
    {
        size_t nb = ((size_t)NH * SEQ * SEQ + 255) / 256;
        bias_k<<<(unsigned)nb, 256>>>(relb, bias, out_bias);
    }

    const size_t DD  = (size_t)DMODEL * DMODEL;
    const size_t DF  = (size_t)DMODEL * DFF_;

    for (int i = 0; i < NL; i++) {
        // ---- self attention ----
        // h-split -> ah/al [0, QKSZ)
        rms_split_k<<<NROWS, 256>>>(x, ln0 + (size_t)i * DMODEL, ah, al);
        {
            dim3 gW(DMODEL / 32, DMODEL / 32);
            cvt_wt_k<<<gW, 256>>>(Wq + i * DD, wh,          wl,          DMODEL, DMODEL);
            cvt_wt_k<<<gW, 256>>>(Wk + i * DD, wh + DD,     wl + DD,     DMODEL, DMODEL);
            cvt_wt_k<<<gW, 256>>>(Wv + i * DD, wh + 2 * DD, wl + 2 * DD, DMODEL, DMODEL);
        }
        // q-split -> oh/ol, k-split -> ah/al [QKSZ, 2*QKSZ), v -> f32
        mgemm_qkv_k<<<dim3(4, 32, 3), 256, MG_SMEM>>>(ah, al, wh, wl,
                                                      oh, ol,
                                                      ah + QKSZ, al + QKSZ,
                                                      v, DD);
        cvt_vt_k<<<dim3(SEQ / 32, DHEAD / 32, BATCH * NH), 256>>>(v, vth, vtl);
        // flash: Q=(oh,ol), K=(ah+QKSZ,...), out-split -> ah/al [0, QKSZ)
        flash_k<<<dim3(SEQ / 128, 1, BATCH * NH), 256, FL_SMEM>>>(
            oh, ol, ah + QKSZ, al + QKSZ, vth, vtl, bias, ah, al);
        // x = x + o @ Wo
        cvt_wt_k<<<dim3(DMODEL / 32, DMODEL / 32), 256>>>(Wo + i * DD, wh, wl, DMODEL, DMODEL);
        mgemm_k<1><<<dim3(4, 32, 1), 256, MG_SMEM>>>(ah, al, wh, wl,
                                                     x, x, x, x,
                                                     DMODEL, DMODEL, 0);
        // ---- gated-GELU FFN ----
        rms_split_k<<<NROWS, 256>>>(x, ln1 + (size_t)i * DMODEL, ah, al);
        {
            dim3 gW(DFF_ / 32, DMODEL / 32);
            cvt_wt_k<<<gW, 256>>>(wi0 + i * DF, wh,      wl,      DMODEL, DFF_);
            cvt_wt_k<<<gW, 256>>>(wi1 + i * DF, wh + DF, wl + DF, DMODEL, DFF_);
        }
        mgemm_k<0><<<dim3(8, 32, 2), 256, MG_SMEM>>>(ah, al, wh, wl,
                                                     f0, f1, f1, nullptr,
                                                     DMODEL, DFF_, DF);
        // geglu-split -> ah/al full [0, NROWS*DFF_)
        geglu_split_k<<<NROWS * DFF_ / 512, 256>>>(f0, f1, ah, al, NROWS * DFF_);
        cvt_wt_k<<<dim3(DMODEL / 32, DFF_ / 32), 256>>>(wo_ffn + i * DF, wh, wl, DFF_, DMODEL);
        mgemm_k<1><<<dim3(4, 32, 1), 256, MG_SMEM>>>(ah, al, wh, wl,
                                                     x, x, x, x,
                                                     DFF_, DMODEL, 0);
    }
    rms_k<<<NROWS, 256>>>(x, flw, out);
}

// round 11
// speedup vs baseline: 2.4004x; 1.0509x over previous
#include <cuda_runtime.h>
#include <cuda_bf16.h>
#include <cstdint>
#include <math.h>

#define NL    4
#define DMODEL 512
#define NH    8
#define DHEAD 64
#define DFF_  1024
#define SEQ   2048
#define BATCH 2
#define NROWS (BATCH*SEQ)          // 4096
#define OUTX  ((size_t)NROWS*DMODEL)  // 2097152
#define QKSZ  ((size_t)NROWS*DMODEL)  // 2M elements

#define DDc   ((size_t)DMODEL*DMODEL)  // 262144
#define DFc   ((size_t)DMODEL*DFF_)    // 524288
#define WARENA (16*DDc + 12*DFc)       // 10485760 elems

typedef unsigned long long u64;

// ---------------- scratch ----------------
__device__ float g_x [NROWS*DMODEL];
__device__ float g_v [NROWS*DMODEL];
__device__ float g_f0[NROWS*DFF_];      // reused as bf16 hi for geglu output
__device__ float g_f1[NROWS*DFF_];      // reused as bf16 lo
__device__ float g_bias[(size_t)NH*SEQ*SEQ];
__device__ __nv_bfloat16 g_ah[NROWS*DFF_];
__device__ __nv_bfloat16 g_al[NROWS*DFF_];
__device__ __nv_bfloat16 g_oh[NROWS*DMODEL];
__device__ __nv_bfloat16 g_ol[NROWS*DMODEL];
__device__ __nv_bfloat16 g_wh[WARENA];   // all-layer weight arena hi
__device__ __nv_bfloat16 g_wl[WARENA];   // all-layer weight arena lo
__device__ __nv_bfloat16 g_vth[(size_t)BATCH*NH*DHEAD*SEQ];
__device__ __nv_bfloat16 g_vtl[(size_t)BATCH*NH*DHEAD*SEQ];

// ---------------- helpers ----------------
__device__ __forceinline__ uint32_t smem_u32(const void* p) {
    uint32_t a;
    asm("{ .reg .u64 t; cvta.to.shared.u64 t, %1; cvt.u32.u64 %0, t; }" : "=r"(a) : "l"(p));
    return a;
}
#define CP_ASYNC16(sa, ga) \
    asm volatile("cp.async.cg.shared.global [%0], [%1], 16;" :: "r"(sa), "l"(ga))
#define CP_COMMIT() asm volatile("cp.async.commit_group;" ::: "memory")
template <int N>
__device__ __forceinline__ void cp_wait() {
    asm volatile("cp.async.wait_group %0;" :: "n"(N) : "memory");
}
__device__ __forceinline__ void ldmx4(uint32_t* r, uint32_t addr) {
    asm volatile("ldmatrix.sync.aligned.m8n8.x4.shared.b16 {%0,%1,%2,%3}, [%4];"
                 : "=r"(r[0]), "=r"(r[1]), "=r"(r[2]), "=r"(r[3]) : "r"(addr));
}
__device__ __forceinline__ void mma16816(float* d, const uint32_t* a,
                                         uint32_t b0, uint32_t b1) {
    asm volatile(
        "mma.sync.aligned.m16n8k16.row.col.f32.bf16.bf16.f32 "
        "{%0,%1,%2,%3}, {%4,%5,%6,%7}, {%8,%9}, {%0,%1,%2,%3};"
        : "+f"(d[0]), "+f"(d[1]), "+f"(d[2]), "+f"(d[3])
        : "r"(a[0]), "r"(a[1]), "r"(a[2]), "r"(a[3]), "r"(b0), "r"(b1));
}
__device__ __forceinline__ uint32_t pack_bf(__nv_bfloat16 a, __nv_bfloat16 b) {
    __nv_bfloat162 p(a, b);
    return *reinterpret_cast<uint32_t*>(&p);
}
__device__ __forceinline__ void split_bf16(float v, __nv_bfloat16& h, __nv_bfloat16& l) {
    h = __float2bfloat16(v);
    l = __float2bfloat16(v - __bfloat162float(h));
}
__device__ __forceinline__ void split_store2(float a, float b,
                                             __nv_bfloat16* hi, __nv_bfloat16* lo) {
    __nv_bfloat16 h0, h1, l0, l1;
    split_bf16(a, h0, l0);
    split_bf16(b, h1, l1);
    *reinterpret_cast<uint32_t*>(hi) = pack_bf(h0, h1);
    *reinterpret_cast<uint32_t*>(lo) = pack_bf(l0, l1);
}
__device__ __forceinline__ float gelu_new(float xx) {
    float inner = 0.7978845608028654f * (xx + 0.044715f * (xx * xx * xx));
    return 0.5f * xx * (1.0f + tanhf(inner));
}

// ---------------- small kernels ----------------
__global__ __launch_bounds__(256) void embed_k(const int* __restrict__ ids,
                                               const float* __restrict__ emb,
                                               float* __restrict__ x) {
    const int row = blockIdx.x;
    const size_t src = (size_t)ids[row] * DMODEL;
    const size_t dst = (size_t)row * DMODEL;
    for (int i = threadIdx.x; i < DMODEL; i += 256) x[dst + i] = emb[src + i];
}

__global__ __launch_bounds__(256) void bias_k(const float* __restrict__ rb,
                                              float* __restrict__ bias,
                                              float* __restrict__ out2) {
    size_t idx = (size_t)blockIdx.x * 256 + threadIdx.x;
    if (idx >= (size_t)NH * SEQ * SEQ) return;
    int kk = (int)(idx & (SEQ - 1));
    int qq = (int)((idx >> 11) & (SEQ - 1));
    int hh = (int)(idx >> 22);
    int rel = kk - qq;
    int bucket = (rel > 0) ? 16 : 0;
    int rp = (rel < 0) ? -rel : rel;
    int add;
    if (rp < 8) {
        add = rp;
    } else {
        float t = logf((float)rp / 8.0f);
        t = t / 2.7725887298583984f;
        t = t * 8.0f;
        add = 8 + (int)t;
        if (add > 15) add = 15;
    }
    float val = rb[(bucket + add) * NH + hh];
    bias[idx] = val;
    if (out2) out2[idx] = val;
}

__global__ __launch_bounds__(256) void rms_split_k(const float* __restrict__ x,
                                                   const float* __restrict__ w,
                                                   __nv_bfloat16* __restrict__ hi,
                                                   __nv_bfloat16* __restrict__ lo) {
    const size_t base = (size_t)blockIdx.x * DMODEL;
    const int t = threadIdx.x;
    float v0 = x[base + t], v1 = x[base + t + 256];
    float ss = v0 * v0 + v1 * v1;
    #pragma unroll
    for (int off = 16; off; off >>= 1) ss += __shfl_xor_sync(0xffffffffu, ss, off);
    __shared__ float red[8];
    __shared__ float bval;
    if ((t & 31) == 0) red[t >> 5] = ss;
    __syncthreads();
    if (t == 0) {
        float tot = 0.f;
        #pragma unroll
        for (int i = 0; i < 8; i++) tot += red[i];
        bval = rsqrtf(tot * (1.0f / DMODEL) + 1e-6f);
    }
    __syncthreads();
    const float inv = bval;
    float y0 = w[t] * (v0 * inv);
    float y1 = w[t + 256] * (v1 * inv);
    __nv_bfloat16 h, l;
    split_bf16(y0, h, l);
    hi[base + t] = h; lo[base + t] = l;
    split_bf16(y1, h, l);
    hi[base + t + 256] = h; lo[base + t + 256] = l;
}

__global__ __launch_bounds__(256) void rms_k(const float* __restrict__ x,
                                             const float* __restrict__ w,
                                             float* __restrict__ y) {
    const size_t base = (size_t)blockIdx.x * DMODEL;
    const int t = threadIdx.x;
    float v0 = x[base + t], v1 = x[base + t + 256];
    float ss = v0 * v0 + v1 * v1;
    #pragma unroll
    for (int off = 16; off; off >>= 1) ss += __shfl_xor_sync(0xffffffffu, ss, off);
    __shared__ float red[8];
    __shared__ float bval;
    if ((t & 31) == 0) red[t >> 5] = ss;
    __syncthreads();
    if (t == 0) {
        float tot = 0.f;
        #pragma unroll
        for (int i = 0; i < 8; i++) tot += red[i];
        bval = rsqrtf(tot * (1.0f / DMODEL) + 1e-6f);
    }
    __syncthreads();
    const float inv = bval;
    y[base + t]       = w[t]       * (v0 * inv);
    y[base + t + 256] = w[t + 256] * (v1 * inv);
}

// all-layer weight transpose+split: blockIdx.z = layer
__global__ __launch_bounds__(256) void cvt_wt_all_k(const float* __restrict__ W,
                                                    __nv_bfloat16* __restrict__ th,
                                                    __nv_bfloat16* __restrict__ tl,
                                                    int Kd, int Nd,
                                                    size_t srcStride, size_t dstStride) {
    __shared__ float tile[32][33];
    const int l = blockIdx.z;
    W  += (size_t)l * srcStride;
    th += (size_t)l * dstStride;
    tl += (size_t)l * dstStride;
    int kb = blockIdx.y * 32, nb = blockIdx.x * 32;
    int tx = threadIdx.x & 31, ty = threadIdx.x >> 5;
    for (int r = ty; r < 32; r += 8)
        tile[r][tx] = W[(size_t)(kb + r) * Nd + nb + tx];
    __syncthreads();
    for (int r = ty; r < 32; r += 8) {
        float v = tile[tx][r];
        __nv_bfloat16 h, l2;
        split_bf16(v, h, l2);
        size_t oidx = (size_t)(nb + r) * Kd + kb + tx;
        th[oidx] = h;
        tl[oidx] = l2;
    }
}
// V [NROWS, 512] f32 -> V^T [B,H,DH,S] hi/lo bf16
__global__ __launch_bounds__(256) void cvt_vt_k(const float* __restrict__ v,
                                                __nv_bfloat16* __restrict__ th,
                                                __nv_bfloat16* __restrict__ tl) {
    __shared__ float tile[32][33];
    const int z = blockIdx.z;
    const int zb = z >> 3, zh = z & 7;
    const int s0 = blockIdx.x * 32;
    const int d0 = blockIdx.y * 32;
    const int tx = threadIdx.x & 31, ty = threadIdx.x >> 5;
    for (int r = ty; r < 32; r += 8)
        tile[r][tx] = v[(size_t)(zb * SEQ + s0 + r) * DMODEL + zh * DHEAD + d0 + tx];
    __syncthreads();
    for (int r = ty; r < 32; r += 8) {
        float val = tile[tx][r];
        __nv_bfloat16 h, l;
        split_bf16(val, h, l);
        size_t oidx = ((size_t)z * DHEAD + d0 + r) * SEQ + s0 + tx;
        th[oidx] = h;
        tl[oidx] = l;
    }
}

// ---------------- warp-MMA bf16x3 GEMM ----------------
#define MG_ROWB   80
#define MG_TILE   (128 * MG_ROWB)
#define MG_BUF    (4 * MG_TILE)
#define MG_SMEM   (2 * MG_BUF)

// Dense GEMM. EPI: 0 plain f32, 1 f32 + residual E.
template <int EPI>
__global__ __launch_bounds__(256) void mgemm_k(
    const __nv_bfloat16* __restrict__ ah, const __nv_bfloat16* __restrict__ al,
    const __nv_bfloat16* __restrict__ wh, const __nv_bfloat16* __restrict__ wl,
    float* C0, float* C1, float* C2,
    const float* __restrict__ E, int K, int ldc, size_t wSlot)
{
    extern __shared__ char smem[];
    const uint32_t sb = smem_u32(smem);
    const int t = threadIdx.x;
    const int lane = t & 31, wid = t >> 5;
    const int wr = wid & 1, wc = wid >> 1;
    const int z = blockIdx.z;
    const __nv_bfloat16* Bh = wh + (size_t)z * wSlot;
    const __nv_bfloat16* Bl = wl + (size_t)z * wSlot;
    float* C = (z == 0) ? C0 : (z == 1) ? C1 : C2;
    const int m0 = blockIdx.y * 128, n0 = blockIdx.x * 128;

    float d[4][4][4];
    #pragma unroll
    for (int mi = 0; mi < 4; mi++)
        #pragma unroll
        for (int nj = 0; nj < 4; nj++)
            #pragma unroll
            for (int r = 0; r < 4; r++) d[mi][nj][r] = 0.f;

    const int lr = t >> 2;
    const int lc = t & 3;
    const __nv_bfloat16* srcs[4] = { ah, al, Bh, Bl };

    auto issue = [&](int kc, int buf) {
        const uint32_t base = sb + buf * MG_BUF;
        #pragma unroll
        for (int tile = 0; tile < 4; tile++) {
            const __nv_bfloat16* s = srcs[tile];
            const int baseRow = (tile < 2) ? m0 : n0;
            #pragma unroll
            for (int h = 0; h < 2; h++) {
                const int row = lr + h * 64;
                const __nv_bfloat16* g = s + (size_t)(baseRow + row) * K + kc * 32 + lc * 8;
                CP_ASYNC16(base + tile * MG_TILE + row * MG_ROWB + lc * 16, g);
            }
        }
        CP_COMMIT();
    };

    const int nch = K >> 5;
    issue(0, 0);

    const int mat = lane >> 3, l8 = lane & 7;
    for (int kc = 0; kc < nch; kc++) {
        const int buf = kc & 1;
        if (kc + 1 < nch) { issue(kc + 1, buf ^ 1); cp_wait<1>(); }
        else              { cp_wait<0>(); }
        __syncthreads();
        const uint32_t bbase = sb + buf * MG_BUF;
        #pragma unroll
        for (int kk = 0; kk < 2; kk++) {
            uint32_t Ah[4][4], Al[4][4], Bhf[2][4], Blf[2][4];
            #pragma unroll
            for (int mi = 0; mi < 4; mi++) {
                const int row = wr * 64 + mi * 16 + (mat & 1) * 8 + l8;
                const uint32_t ad = bbase + row * MG_ROWB + kk * 32 + (mat >> 1) * 16;
                ldmx4(Ah[mi], ad);
                ldmx4(Al[mi], ad + MG_TILE);
            }
            #pragma unroll
            for (int nj2 = 0; nj2 < 2; nj2++) {
                const int n = wc * 32 + nj2 * 16 + (mat >> 1) * 8 + l8;
                const uint32_t bd = bbase + 2 * MG_TILE + n * MG_ROWB + kk * 32 + (mat & 1) * 16;
                ldmx4(Bhf[nj2], bd);
                ldmx4(Blf[nj2], bd + MG_TILE);
            }
            #pragma unroll
            for (int mi = 0; mi < 4; mi++)
                #pragma unroll
                for (int nj = 0; nj < 4; nj++) {
                    const int g = nj >> 1, o = (nj & 1) * 2;
                    mma16816(d[mi][nj], Ah[mi], Bhf[g][o], Bhf[g][o + 1]);
                    mma16816(d[mi][nj], Ah[mi], Blf[g][o], Blf[g][o + 1]);
                    mma16816(d[mi][nj], Al[mi], Bhf[g][o], Bhf[g][o + 1]);
                }
        }
        __syncthreads();
    }

    #pragma unroll
    for (int mi = 0; mi < 4; mi++) {
        #pragma unroll
        for (int nj = 0; nj < 4; nj++) {
            const int row = m0 + wr * 64 + mi * 16 + (lane >> 2);
            const int col = n0 + wc * 32 + nj * 8 + (lane & 3) * 2;
            #pragma unroll
            for (int hh = 0; hh < 2; hh++) {
                const int m = row + hh * 8;
                float2 cv = make_float2(d[mi][nj][hh * 2], d[mi][nj][hh * 2 + 1]);
                if constexpr (EPI == 1) {
                    const float2 rv = *reinterpret_cast<const float2*>(
                        E + (size_t)m * ldc + col);
                    cv.x += rv.x; cv.y += rv.y;
                }
                *reinterpret_cast<float2*>(C + (size_t)m * ldc + col) = cv;
            }
        }
    }
}

// QKV GEMM: z=0 -> split bf16 (qh,ql); z=1 -> split (kh,kl); z=2 -> f32 v.
__global__ __launch_bounds__(256) void mgemm_qkv_k(
    const __nv_bfloat16* __restrict__ ah, const __nv_bfloat16* __restrict__ al,
    const __nv_bfloat16* __restrict__ wh, const __nv_bfloat16* __restrict__ wl,
    __nv_bfloat16* __restrict__ qh, __nv_bfloat16* __restrict__ ql,
    __nv_bfloat16* __restrict__ kh, __nv_bfloat16* __restrict__ kl,
    float* __restrict__ vout, size_t wSlot)
{
    constexpr int K = DMODEL;
    extern __shared__ char smem[];
    const uint32_t sb = smem_u32(smem);
    const int t = threadIdx.x;
    const int lane = t & 31, wid = t >> 5;
    const int wr = wid & 1, wc = wid >> 1;
    const int z = blockIdx.z;
    const __nv_bfloat16* Bh = wh + (size_t)z * wSlot;
    const __nv_bfloat16* Bl = wl + (size_t)z * wSlot;
    const int m0 = blockIdx.y * 128, n0 = blockIdx.x * 128;

    float d[4][4][4];
    #pragma unroll
    for (int mi = 0; mi < 4; mi++)
        #pragma unroll
        for (int nj = 0; nj < 4; nj++)
            #pragma unroll
            for (int r = 0; r < 4; r++) d[mi][nj][r] = 0.f;

    const int lr = t >> 2;
    const int lc = t & 3;
    const __nv_bfloat16* srcs[4] = { ah, al, Bh, Bl };

    auto issue = [&](int kc, int buf) {
        const uint32_t base = sb + buf * MG_BUF;
        #pragma unroll
        for (int tile = 0; tile < 4; tile++) {
            const __nv_bfloat16* s = srcs[tile];
            const int baseRow = (tile < 2) ? m0 : n0;
            #pragma unroll
            for (int h = 0; h < 2; h++) {
                const int row = lr + h * 64;
                const __nv_bfloat16* g = s + (size_t)(baseRow + row) * K + kc * 32 + lc * 8;
                CP_ASYNC16(base + tile * MG_TILE + row * MG_ROWB + lc * 16, g);
            }
        }
        CP_COMMIT();
    };

    const int nch = K >> 5;
    issue(0, 0);

    const int mat = lane >> 3, l8 = lane & 7;
    for (int kc = 0; kc < nch; kc++) {
        const int buf = kc & 1;
        if (kc + 1 < nch) { issue(kc + 1, buf ^ 1); cp_wait<1>(); }
        else              { cp_wait<0>(); }
        __syncthreads();
        const uint32_t bbase = sb + buf * MG_BUF;
        #pragma unroll
        for (int kk = 0; kk < 2; kk++) {
            uint32_t Ah[4][4], Al[4][4], Bhf[2][4], Blf[2][4];
            #pragma unroll
            for (int mi = 0; mi < 4; mi++) {
                const int row = wr * 64 + mi * 16 + (mat & 1) * 8 + l8;
                const uint32_t ad = bbase + row * MG_ROWB + kk * 32 + (mat >> 1) * 16;
                ldmx4(Ah[mi], ad);
                ldmx4(Al[mi], ad + MG_TILE);
            }
            #pragma unroll
            for (int nj2 = 0; nj2 < 2; nj2++) {
                const int n = wc * 32 + nj2 * 16 + (mat >> 1) * 8 + l8;
                const uint32_t bd = bbase + 2 * MG_TILE + n * MG_ROWB + kk * 32 + (mat & 1) * 16;
                ldmx4(Bhf[nj2], bd);
                ldmx4(Blf[nj2], bd + MG_TILE);
            }
            #pragma unroll
            for (int mi = 0; mi < 4; mi++)
                #pragma unroll
                for (int nj = 0; nj < 4; nj++) {
                    const int g = nj >> 1, o = (nj & 1) * 2;
                    mma16816(d[mi][nj], Ah[mi], Bhf[g][o], Bhf[g][o + 1]);
                    mma16816(d[mi][nj], Ah[mi], Blf[g][o], Blf[g][o + 1]);
                    mma16816(d[mi][nj], Al[mi], Bhf[g][o], Bhf[g][o + 1]);
                }
        }
        __syncthreads();
    }

    __nv_bfloat16* H = (z == 0) ? qh : kh;
    __nv_bfloat16* L = (z == 0) ? ql : kl;
    #pragma unroll
    for (int mi = 0; mi < 4; mi++) {
        #pragma unroll
        for (int nj = 0; nj < 4; nj++) {
            const int row = m0 + wr * 64 + mi * 16 + (lane >> 2);
            const int col = n0 + wc * 32 + nj * 8 + (lane & 3) * 2;
            #pragma unroll
            for (int hh = 0; hh < 2; hh++) {
                const int m = row + hh * 8;
                const size_t off = (size_t)m * DMODEL + col;
                if (z == 2) {
                    *reinterpret_cast<float2*>(vout + off) =
                        make_float2(d[mi][nj][hh * 2], d[mi][nj][hh * 2 + 1]);
                } else {
                    split_store2(d[mi][nj][hh * 2], d[mi][nj][hh * 2 + 1],
                                 H + off, L + off);
                }
            }
        }
    }
}

// FFN-in fused: C0 = gelu(A@W0) * (A@W1), split bf16 out. K=DMODEL, N=DFF.
#define FFN_BUF  (6 * MG_TILE)          // Ah,Al,B0h,B0l,B1h,B1l
#define FFN_SMEM (2 * FFN_BUF)          // 122880
__global__ __launch_bounds__(256) void mgemm_ffn_k(
    const __nv_bfloat16* __restrict__ ah, const __nv_bfloat16* __restrict__ al,
    const __nv_bfloat16* __restrict__ w0h, const __nv_bfloat16* __restrict__ w0l,
    const __nv_bfloat16* __restrict__ w1h, const __nv_bfloat16* __restrict__ w1l,
    __nv_bfloat16* __restrict__ Ghi, __nv_bfloat16* __restrict__ Glo)
{
    constexpr int K = DMODEL;
    extern __shared__ char smem[];
    const uint32_t sb = smem_u32(smem);
    const int t = threadIdx.x;
    const int lane = t & 31, wid = t >> 5;
    const int wr = wid & 1, wc = wid >> 1;
    const int m0 = blockIdx.y * 128, n0 = blockIdx.x * 128;

    float d0[4][4][4], d1[4][4][4];
    #pragma unroll
    for (int mi = 0; mi < 4; mi++)
        #pragma unroll
        for (int nj = 0; nj < 4; nj++)
            #pragma unroll
            for (int r = 0; r < 4; r++) { d0[mi][nj][r] = 0.f; d1[mi][nj][r] = 0.f; }

    const int lr = t >> 2;
    const int lc = t & 3;
    const __nv_bfloat16* srcs[6] = { ah, al, w0h, w0l, w1h, w1l };

    auto issue = [&](int kc, int buf) {
        const uint32_t base = sb + buf * FFN_BUF;
        #pragma unroll
        for (int tile = 0; tile < 6; tile++) {
            const __nv_bfloat16* s = srcs[tile];
            const int baseRow = (tile < 2) ? m0 : n0;
            #pragma unroll
            for (int h = 0; h < 2; h++) {
                const int row = lr + h * 64;
                const __nv_bfloat16* g = s + (size_t)(baseRow + row) * K + kc * 32 + lc * 8;
                CP_ASYNC16(base + tile * MG_TILE + row * MG_ROWB + lc * 16, g);
            }
        }
        CP_COMMIT();
    };

    const int nch = K >> 5;
    issue(0, 0);

    const int mat = lane >> 3, l8 = lane & 7;
    for (int kc = 0; kc < nch; kc++) {
        const int buf = kc & 1;
        if (kc + 1 < nch) { issue(kc + 1, buf ^ 1); cp_wait<1>(); }
        else              { cp_wait<0>(); }
        __syncthreads();
        const uint32_t bbase = sb + buf * FFN_BUF;
        #pragma unroll
        for (int kk = 0; kk < 2; kk++) {
            uint32_t Ah[4][4], Al[4][4];
            #pragma unroll
            for (int mi = 0; mi < 4; mi++) {
                const int row = wr * 64 + mi * 16 + (mat & 1) * 8 + l8;
                const uint32_t ad = bbase + row * MG_ROWB + kk * 32 + (mat >> 1) * 16;
                ldmx4(Ah[mi], ad);
                ldmx4(Al[mi], ad + MG_TILE);
            }
            #pragma unroll
            for (int w = 0; w < 2; w++) {     // w: which weight matrix
                uint32_t Bhf[2][4], Blf[2][4];
                const uint32_t boff = bbase + (2 + 2 * w) * MG_TILE;
                #pragma unroll
                for (int nj2 = 0; nj2 < 2; nj2++) {
                    const int n = wc * 32 + nj2 * 16 + (mat >> 1) * 8 + l8;
                    const uint32_t bd = boff + n * MG_ROWB + kk * 32 + (mat & 1) * 16;
                    ldmx4(Bhf[nj2], bd);
                    ldmx4(Blf[nj2], bd + MG_TILE);
                }
                #pragma unroll
                for (int mi = 0; mi < 4; mi++)
                    #pragma unroll
                    for (int nj = 0; nj < 4; nj++) {
                        float* dd = w ? d1[mi][nj] : d0[mi][nj];
                        const int g = nj >> 1, o = (nj & 1) * 2;
                        mma16816(dd, Ah[mi], Bhf[g][o], Bhf[g][o + 1]);
                        mma16816(dd, Ah[mi], Blf[g][o], Blf[g][o + 1]);
                        mma16816(dd, Al[mi], Bhf[g][o], Bhf[g][o + 1]);
                    }
            }
        }
        __syncthreads();
    }

    #pragma unroll
    for (int mi = 0; mi < 4; mi++) {
        #pragma unroll
        for (int nj = 0; nj < 4; nj++) {
            const int row = m0 + wr * 64 + mi * 16 + (lane >> 2);
            const int col = n0 + wc * 32 + nj * 8 + (lane & 3) * 2;
            #pragma unroll
            for (int hh = 0; hh < 2; hh++) {
                const int m = row + hh * 8;
                const size_t off = (size_t)m * DFF_ + col;
                float r0 = gelu_new(d0[mi][nj][hh * 2])     * d1[mi][nj][hh * 2];
                float r1 = gelu_new(d0[mi][nj][hh * 2 + 1]) * d1[mi][nj][hh * 2 + 1];
                split_store2(r0, r1, Ghi + off, Glo + off);
            }
        }
    }
}

// ---------------- fused flash attention ----------------
#define FL_QSTR 144
#define FL_VSTR 272
#define FL_QT   (128 * FL_QSTR)
#define FL_VT   (64 * FL_VSTR)
#define FL_OFF_K(buf) (2 * FL_QT + (buf) * 2 * FL_QT)
#define FL_OFF_V(buf) (6 * FL_QT + (buf) * 2 * FL_VT)
#define FL_SMEM (6 * FL_QT + 4 * FL_VT)
__global__ __launch_bounds__(256) void flash_k(
    const __nv_bfloat16* __restrict__ qh_g, const __nv_bfloat16* __restrict__ ql_g,
    const __nv_bfloat16* __restrict__ kh_g, const __nv_bfloat16* __restrict__ kl_g,
    const __nv_bfloat16* __restrict__ vth_g, const __nv_bfloat16* __restrict__ vtl_g,
    const float* __restrict__ bias,
    __nv_bfloat16* __restrict__ Ohi, __nv_bfloat16* __restrict__ Olo)
{
    extern __shared__ char smem[];
    const uint32_t sb = smem_u32(smem);
    const int t = threadIdx.x, lane = t & 31, wid = t >> 5;
    const int z = blockIdx.z, zb = z >> 3, zh = z & 7;
    const int m0 = blockIdx.x * 128;
    const int mat = lane >> 3, l8 = lane & 7;

    auto loadQ = [&]() {
        #pragma unroll
        for (int i = 0; i < 4; i++) {
            int idx = t + i * 256, row = idx >> 3, c = idx & 7;
            size_t go = (size_t)(zb * SEQ + m0 + row) * DMODEL + zh * 64 + c * 8;
            CP_ASYNC16(sb + row * FL_QSTR + c * 16, qh_g + go);
            CP_ASYNC16(sb + FL_QT + row * FL_QSTR + c * 16, ql_g + go);
        }
    };
    auto loadKV = [&](int kt, int buf) {
        #pragma unroll
        for (int i = 0; i < 4; i++) {
            int idx = t + i * 256, row = idx >> 3, c = idx & 7;
            size_t go = (size_t)(zb * SEQ + kt * 128 + row) * DMODEL + zh * 64 + c * 8;
            CP_ASYNC16(sb + FL_OFF_K(buf) + row * FL_QSTR + c * 16, kh_g + go);
            CP_ASYNC16(sb + FL_OFF_K(buf) + FL_QT + row * FL_QSTR + c * 16, kl_g + go);
        }
        #pragma unroll
        for (int i = 0; i < 4; i++) {
            int idx = t + i * 256, row = idx >> 4, c = idx & 15;
            size_t go = (size_t)(z * 64 + row) * SEQ + kt * 128 + c * 8;
            CP_ASYNC16(sb + FL_OFF_V(buf) + row * FL_VSTR + c * 16, vth_g + go);
            CP_ASYNC16(sb + FL_OFF_V(buf) + FL_VT + row * FL_VSTR + c * 16, vtl_g + go);
        }
        CP_COMMIT();
    };

    loadQ();
    loadKV(0, 0);

    float m_[2] = { -1e30f, -1e30f }, l_[2] = { 0.f, 0.f };
    float o[8][4];
    #pragma unroll
    for (int nt = 0; nt < 8; nt++)
        #pragma unroll
        for (int e = 0; e < 4; e++) o[nt][e] = 0.f;
    uint32_t qh[4][4], ql[4][4];

    for (int kt = 0; kt < 16; kt++) {
        const int buf = kt & 1;
        if (kt + 1 < 16) { loadKV(kt + 1, buf ^ 1); cp_wait<1>(); }
        else             { cp_wait<0>(); }
        __syncthreads();
        if (kt == 0) {
            #pragma unroll
            for (int kc = 0; kc < 4; kc++) {
                const int row = wid * 16 + (mat & 1) * 8 + l8;
                const uint32_t ad = sb + row * FL_QSTR + kc * 32 + (mat >> 1) * 16;
                ldmx4(qh[kc], ad);
                ldmx4(ql[kc], ad + FL_QT);
            }
        }
        float s[16][4];
        #pragma unroll
        for (int j = 0; j < 16; j++)
            #pragma unroll
            for (int e = 0; e < 4; e++) s[j][e] = 0.f;
        #pragma unroll
        for (int j2 = 0; j2 < 8; j2++) {
            const int n = j2 * 16 + (mat >> 1) * 8 + l8;
            #pragma unroll
            for (int kc = 0; kc < 4; kc++) {
                uint32_t bh4[4], bl4[4];
                const uint32_t bd = sb + FL_OFF_K(buf) + n * FL_QSTR + kc * 32 + (mat & 1) * 16;
                ldmx4(bh4, bd);
                ldmx4(bl4, bd + FL_QT);
                #pragma unroll
                for (int e = 0; e < 2; e++) {
                    mma16816(s[j2 * 2 + e], qh[kc], bh4[e * 2], bh4[e * 2 + 1]);
                    mma16816(s[j2 * 2 + e], qh[kc], bl4[e * 2], bl4[e * 2 + 1]);
                    mma16816(s[j2 * 2 + e], ql[kc], bh4[e * 2], bh4[e * 2 + 1]);
                }
            }
        }
        const int r0 = m0 + wid * 16 + (lane >> 2);
        #pragma unroll
        for (int j = 0; j < 16; j++) {
            const int col = kt * 128 + j * 8 + 2 * (lane & 3);
            const float2 b0 = *reinterpret_cast<const float2*>(
                bias + ((size_t)zh * SEQ + r0) * SEQ + col);
            const float2 b1 = *reinterpret_cast<const float2*>(
                bias + ((size_t)zh * SEQ + r0 + 8) * SEQ + col);
            s[j][0] += b0.x; s[j][1] += b0.y;
            s[j][2] += b1.x; s[j][3] += b1.y;
        }
        float mx[2] = { -1e30f, -1e30f };
        #pragma unroll
        for (int j = 0; j < 16; j++) {
            mx[0] = fmaxf(mx[0], fmaxf(s[j][0], s[j][1]));
            mx[1] = fmaxf(mx[1], fmaxf(s[j][2], s[j][3]));
        }
        #pragma unroll
        for (int off = 1; off <= 2; off <<= 1) {
            mx[0] = fmaxf(mx[0], __shfl_xor_sync(0xffffffffu, mx[0], off));
            mx[1] = fmaxf(mx[1], __shfl_xor_sync(0xffffffffu, mx[1], off));
        }
        float al2[2];
        #pragma unroll
        for (int h = 0; h < 2; h++) {
            const float nm = fmaxf(m_[h], mx[h]);
            al2[h] = __expf(m_[h] - nm);
            m_[h] = nm;
        }
        float rs[2] = { 0.f, 0.f };
        #pragma unroll
        for (int j = 0; j < 16; j++) {
            s[j][0] = __expf(s[j][0] - m_[0]);
            s[j][1] = __expf(s[j][1] - m_[0]);
            s[j][2] = __expf(s[j][2] - m_[1]);
            s[j][3] = __expf(s[j][3] - m_[1]);
            rs[0] += s[j][0] + s[j][1];
            rs[1] += s[j][2] + s[j][3];
        }
        #pragma unroll
        for (int off = 1; off <= 2; off <<= 1) {
            rs[0] += __shfl_xor_sync(0xffffffffu, rs[0], off);
            rs[1] += __shfl_xor_sync(0xffffffffu, rs[1], off);
        }
        l_[0] = l_[0] * al2[0] + rs[0];
        l_[1] = l_[1] * al2[1] + rs[1];
        #pragma unroll
        for (int nt = 0; nt < 8; nt++) {
            o[nt][0] *= al2[0]; o[nt][1] *= al2[0];
            o[nt][2] *= al2[1]; o[nt][3] *= al2[1];
        }
        #pragma unroll
        for (int kc2 = 0; kc2 < 8; kc2++) {
            uint32_t pa[4], pl[4];
            #pragma unroll
            for (int u = 0; u < 2; u++) {
                #pragma unroll
                for (int hh = 0; hh < 2; hh++) {
                    const float v0 = s[2 * kc2 + u][hh * 2];
                    const float v1 = s[2 * kc2 + u][hh * 2 + 1];
                    __nv_bfloat16 h0, h1, lo0, lo1;
                    split_bf16(v0, h0, lo0);
                    split_bf16(v1, h1, lo1);
                    pa[u * 2 + hh] = pack_bf(h0, h1);
                    pl[u * 2 + hh] = pack_bf(lo0, lo1);
                }
            }
            #pragma unroll
            for (int j2v = 0; j2v < 4; j2v++) {
                const int n = j2v * 16 + (mat >> 1) * 8 + l8;
                uint32_t vh4[4], vl4[4];
                const uint32_t bd = sb + FL_OFF_V(buf) + n * FL_VSTR + kc2 * 32 + (mat & 1) * 16;
                ldmx4(vh4, bd);
                ldmx4(vl4, bd + FL_VT);
                #pragma unroll
                for (int e = 0; e < 2; e++) {
                    const int nt = j2v * 2 + e;
                    mma16816(o[nt], pa, vh4[e * 2], vh4[e * 2 + 1]);
                    mma16816(o[nt], pa, vl4[e * 2], vl4[e * 2 + 1]);
                    mma16816(o[nt], pl, vh4[e * 2], vh4[e * 2 + 1]);
                }
            }
        }
        __syncthreads();
    }

    const float inv0 = 1.0f / l_[0], inv1 = 1.0f / l_[1];
    const int r0 = m0 + wid * 16 + (lane >> 2);
    #pragma unroll
    for (int nt = 0; nt < 8; nt++) {
        const int col = zh * 64 + nt * 8 + 2 * (lane & 3);
        const size_t o0 = (size_t)(zb * SEQ + r0) * DMODEL + col;
        const size_t o1 = (size_t)(zb * SEQ + r0 + 8) * DMODEL + col;
        split_store2(o[nt][0] * inv0, o[nt][1] * inv0, Ohi + o0, Olo + o0);
        split_store2(o[nt][2] * inv1, o[nt][3] * inv1, Ohi + o1, Olo + o1);
    }
}

// ---------------- launch ----------------
extern "C" void kernel_launch(void* const* d_in, const int* in_sizes, int n_in,
                              void* d_out, int out_size) {
    const int*   ids    = (const int*)  d_in[0];
    const float* embed  = (const float*)d_in[1];
    const float* Wq     = (const float*)d_in[2];
    const float* Wk     = (const float*)d_in[3];
    const float* Wv     = (const float*)d_in[4];
    const float* Wo     = (const float*)d_in[5];
    const float* relb   = (const float*)d_in[6];
    const float* wi0    = (const float*)d_in[7];
    const float* wi1    = (const float*)d_in[8];
    const float* wo_ffn = (const float*)d_in[9];
    const float* ln0    = (const float*)d_in[10];
    const float* ln1    = (const float*)d_in[11];
    const float* flw    = (const float*)d_in[12];
    float* out = (float*)d_out;

    float *x, *v, *f0, *f1, *bias;
    __nv_bfloat16 *ah, *al, *oh, *ol, *wh, *wl, *vth, *vtl;
    cudaGetSymbolAddress((void**)&x,  g_x);
    cudaGetSymbolAddress((void**)&v,  g_v);
    cudaGetSymbolAddress((void**)&f0, g_f0);
    cudaGetSymbolAddress((void**)&f1, g_f1);
    cudaGetSymbolAddress((void**)&bias, g_bias);
    cudaGetSymbolAddress((void**)&ah, g_ah);
    cudaGetSymbolAddress((void**)&al, g_al);
    cudaGetSymbolAddress((void**)&oh, g_oh);
    cudaGetSymbolAddress((void**)&ol, g_ol);
    cudaGetSymbolAddress((void**)&wh, g_wh);
    cudaGetSymbolAddress((void**)&wl, g_wl);
    cudaGetSymbolAddress((void**)&vth, g_vth);
    cudaGetSymbolAddress((void**)&vtl, g_vtl);
    __nv_bfloat16* gh = (__nv_bfloat16*)f0;   // geglu output hi (reuse f32 buffer)
    __nv_bfloat16* gl = (__nv_bfloat16*)f1;   // geglu output lo

    cudaFuncSetAttribute(mgemm_k<0>, cudaFuncAttributeMaxDynamicSharedMemorySize, MG_SMEM);
    cudaFuncSetAttribute(mgemm_k<1>, cudaFuncAttributeMaxDynamicSharedMemorySize, MG_SMEM);
    cudaFuncSetAttribute(mgemm_qkv_k, cudaFuncAttributeMaxDynamicSharedMemorySize, MG_SMEM);
    cudaFuncSetAttribute(mgemm_ffn_k, cudaFuncAttributeMaxDynamicSharedMemorySize, FFN_SMEM);
    cudaFuncSetAttribute(flash_k, cudaFuncAttributeMaxDynamicSharedMemorySize, FL_SMEM);

    float* out_bias = ((size_t)out_size > OUTX) ? (out + OUTX) : nullptr;

    embed_k<<<NROWS, 256>>>(ids, embed, x);
    {
        size_t nb = ((size_t)NH * SEQ * SEQ + 255) / 256;
        bias_k<<<(unsigned)nb, 256>>>(relb, bias, out_bias);
    }
    // ---- hoisted all-layer weight conversions (7 launches) ----
    {
        dim3 gQ(DMODEL / 32, DMODEL / 32, NL);
        cvt_wt_all_k<<<gQ, 256>>>(Wq, wh,            wl,            DMODEL, DMODEL, DDc, DDc);
        cvt_wt_all_k<<<gQ, 256>>>(Wk, wh + 4 * DDc,  wl + 4 * DDc,  DMODEL, DMODEL, DDc, DDc);
        cvt_wt_all_k<<<gQ, 256>>>(Wv, wh + 8 * DDc,  wl + 8 * DDc,  DMODEL, DMODEL, DDc, DDc);
        cvt_wt_all_k<<<gQ, 256>>>(Wo, wh + 12 * DDc, wl + 12 * DDc, DMODEL, DMODEL, DDc, DDc);
        dim3 gF(DFF_ / 32, DMODEL / 32, NL);
        cvt_wt_all_k<<<gF, 256>>>(wi0, wh + 16 * DDc,           wl + 16 * DDc,           DMODEL, DFF_, DFc, DFc);
        cvt_wt_all_k<<<gF, 256>>>(wi1, wh + 16 * DDc + 4 * DFc, wl + 16 * DDc + 4 * DFc, DMODEL, DFF_, DFc, DFc);
        dim3 gO(DMODEL / 32, DFF_ / 32, NL);
        cvt_wt_all_k<<<gO, 256>>>(wo_ffn, wh + 16 * DDc + 8 * DFc, wl + 16 * DDc + 8 * DFc, DFF_, DMODEL, DFc, DFc);
    }

    for (int i = 0; i < NL; i++) {
        const size_t wQKV = (size_t)i * DDc;                 // +z*4DDc selects Wq/Wk/Wv
        const size_t wO   = 12 * DDc + (size_t)i * DDc;
        const size_t wI0  = 16 * DDc + (size_t)i * DFc;
        const size_t wI1  = 16 * DDc + 4 * DFc + (size_t)i * DFc;
        const size_t wOF  = 16 * DDc + 8 * DFc + (size_t)i * DFc;
        // ---- self attention ----
        rms_split_k<<<NROWS, 256>>>(x, ln0 + (size_t)i * DMODEL, ah, al);
        mgemm_qkv_k<<<dim3(4, 32, 3), 256, MG_SMEM>>>(ah, al, wh + wQKV, wl + wQKV,
                                                      oh, ol,
                                                      ah + QKSZ, al + QKSZ,
                                                      v, 4 * DDc);
        cvt_vt_k<<<dim3(SEQ / 32, DHEAD / 32, BATCH * NH), 256>>>(v, vth, vtl);
        flash_k<<<dim3(SEQ / 128, 1, BATCH * NH), 256, FL_SMEM>>>(
            oh, ol, ah + QKSZ, al + QKSZ, vth, vtl, bias, ah, al);
        mgemm_k<1><<<dim3(4, 32, 1), 256, MG_SMEM>>>(ah, al, wh + wO, wl + wO,
                                                     x, x, x, x,
                                                     DMODEL, DMODEL, 0);
        // ---- gated-GELU FFN (fused) ----
        rms_split_k<<<NROWS, 256>>>(x, ln1 + (size_t)i * DMODEL, ah, al);
        mgemm_ffn_k<<<dim3(DFF_ / 128, NROWS / 128), 256, FFN_SMEM>>>(
            ah, al, wh + wI0, wl + wI0, wh + wI1, wl + wI1, gh, gl);
        mgemm_k<1><<<dim3(4, 32, 1), 256, MG_SMEM>>>(gh, gl, wh + wOF, wl + wOF,
                                                     x, x, x, x,
                                                     DFF_, DMODEL, 0);
    }
    rms_k<<<NROWS, 256>>>(x, flw, out);
}

// round 12
// speedup vs baseline: 2.7686x; 1.1534x over previous
#include <cuda_runtime.h>
#include <cuda_bf16.h>
#include <cstdint>
#include <math.h>

#define NL    4
#define DMODEL 512
#define NH    8
#define DHEAD 64
#define DFF_  1024
#define SEQ   2048
#define BATCH 2
#define NROWS (BATCH*SEQ)          // 4096
#define OUTX  ((size_t)NROWS*DMODEL)  // 2097152
#define QKSZ  ((size_t)NROWS*DMODEL)  // 2M elements
#define NRELS 4095

#define DDc   ((size_t)DMODEL*DMODEL)  // 262144
#define DFc   ((size_t)DMODEL*DFF_)    // 524288
#define WARENA (16*DDc + 12*DFc)

typedef unsigned long long u64;

// ---------------- scratch ----------------
__device__ float g_x [NROWS*DMODEL];
__device__ float g_v [NROWS*DMODEL];
__device__ float g_f0[NROWS*DFF_];      // reused as bf16 hi for geglu output
__device__ float g_f1[NROWS*DFF_];      // reused as bf16 lo
__device__ float g_btab[NH*NRELS];      // per-head rel-bias table
__device__ __nv_bfloat16 g_ah[NROWS*DFF_];
__device__ __nv_bfloat16 g_al[NROWS*DFF_];
__device__ __nv_bfloat16 g_oh[NROWS*DMODEL];
__device__ __nv_bfloat16 g_ol[NROWS*DMODEL];
__device__ __nv_bfloat16 g_wh[WARENA];
__device__ __nv_bfloat16 g_wl[WARENA];
__device__ __nv_bfloat16 g_vth[(size_t)BATCH*NH*DHEAD*SEQ];
__device__ __nv_bfloat16 g_vtl[(size_t)BATCH*NH*DHEAD*SEQ];

// ---------------- helpers ----------------
__device__ __forceinline__ uint32_t smem_u32(const void* p) {
    uint32_t a;
    asm("{ .reg .u64 t; cvta.to.shared.u64 t, %1; cvt.u32.u64 %0, t; }" : "=r"(a) : "l"(p));
    return a;
}
#define CP_ASYNC16(sa, ga) \
    asm volatile("cp.async.cg.shared.global [%0], [%1], 16;" :: "r"(sa), "l"(ga))
#define CP_COMMIT() asm volatile("cp.async.commit_group;" ::: "memory")
template <int N>
__device__ __forceinline__ void cp_wait() {
    asm volatile("cp.async.wait_group %0;" :: "n"(N) : "memory");
}
__device__ __forceinline__ void ldmx4(uint32_t* r, uint32_t addr) {
    asm volatile("ldmatrix.sync.aligned.m8n8.x4.shared.b16 {%0,%1,%2,%3}, [%4];"
                 : "=r"(r[0]), "=r"(r[1]), "=r"(r[2]), "=r"(r[3]) : "r"(addr));
}
__device__ __forceinline__ void mma16816(float* d, const uint32_t* a,
                                         uint32_t b0, uint32_t b1) {
    asm volatile(
        "mma.sync.aligned.m16n8k16.row.col.f32.bf16.bf16.f32 "
        "{%0,%1,%2,%3}, {%4,%5,%6,%7}, {%8,%9}, {%0,%1,%2,%3};"
        : "+f"(d[0]), "+f"(d[1]), "+f"(d[2]), "+f"(d[3])
        : "r"(a[0]), "r"(a[1]), "r"(a[2]), "r"(a[3]), "r"(b0), "r"(b1));
}
__device__ __forceinline__ uint32_t pack_bf(__nv_bfloat16 a, __nv_bfloat16 b) {
    __nv_bfloat162 p(a, b);
    return *reinterpret_cast<uint32_t*>(&p);
}
__device__ __forceinline__ void split_bf16(float v, __nv_bfloat16& h, __nv_bfloat16& l) {
    h = __float2bfloat16(v);
    l = __float2bfloat16(v - __bfloat162float(h));
}
__device__ __forceinline__ void split_store2(float a, float b,
                                             __nv_bfloat16* hi, __nv_bfloat16* lo) {
    __nv_bfloat16 h0, h1, l0, l1;
    split_bf16(a, h0, l0);
    split_bf16(b, h1, l1);
    *reinterpret_cast<uint32_t*>(hi) = pack_bf(h0, h1);
    *reinterpret_cast<uint32_t*>(lo) = pack_bf(l0, l1);
}
__device__ __forceinline__ float gelu_new(float xx) {
    float inner = 0.7978845608028654f * (xx + 0.044715f * (xx * xx * xx));
    return 0.5f * xx * (1.0f + tanhf(inner));
}

// ---------------- small kernels ----------------
__global__ __launch_bounds__(256) void embed_k(const int* __restrict__ ids,
                                               const float* __restrict__ emb,
                                               float* __restrict__ x) {
    const int row = blockIdx.x;
    const size_t src = (size_t)ids[row] * DMODEL;
    const size_t dst = (size_t)row * DMODEL;
    for (int i = threadIdx.x; i < DMODEL; i += 256) x[dst + i] = emb[src + i];
}

// per-head rel-bias table: btab[h][rel+2047], rel in [-2047,2047]
__global__ __launch_bounds__(256) void bias_tab_k(const float* __restrict__ rb,
                                                  float* __restrict__ btab) {
    int idx = blockIdx.x * 256 + threadIdx.x;
    if (idx >= NH * NRELS) return;
    int hh = idx / NRELS;
    int rel = (idx % NRELS) - 2047;
    int bucket = (rel > 0) ? 16 : 0;
    int rp = (rel < 0) ? -rel : rel;
    int add;
    if (rp < 8) {
        add = rp;
    } else {
        float t = logf((float)rp / 8.0f);
        t = t / 2.7725887298583984f;
        t = t * 8.0f;
        add = 8 + (int)t;
        if (add > 15) add = 15;
    }
    btab[idx] = rb[(bucket + add) * NH + hh];
}

// materialize [1,H,S,S] pos_bias output from the table
__global__ __launch_bounds__(256) void bias_out_k(const float* __restrict__ btab,
                                                  float* __restrict__ out2) {
    size_t idx = (size_t)blockIdx.x * 256 + threadIdx.x;
    if (idx >= (size_t)NH * SEQ * SEQ) return;
    int kk = (int)(idx & (SEQ - 1));
    int qq = (int)((idx >> 11) & (SEQ - 1));
    int hh = (int)(idx >> 22);
    out2[idx] = btab[hh * NRELS + (kk - qq) + 2047];
}

__global__ __launch_bounds__(256) void rms_split_k(const float* __restrict__ x,
                                                   const float* __restrict__ w,
                                                   __nv_bfloat16* __restrict__ hi,
                                                   __nv_bfloat16* __restrict__ lo) {
    const size_t base = (size_t)blockIdx.x * DMODEL;
    const int t = threadIdx.x;
    float v0 = x[base + t], v1 = x[base + t + 256];
    float ss = v0 * v0 + v1 * v1;
    #pragma unroll
    for (int off = 16; off; off >>= 1) ss += __shfl_xor_sync(0xffffffffu, ss, off);
    __shared__ float red[8];
    __shared__ float bval;
    if ((t & 31) == 0) red[t >> 5] = ss;
    __syncthreads();
    if (t == 0) {
        float tot = 0.f;
        #pragma unroll
        for (int i = 0; i < 8; i++) tot += red[i];
        bval = rsqrtf(tot * (1.0f / DMODEL) + 1e-6f);
    }
    __syncthreads();
    const float inv = bval;
    float y0 = w[t] * (v0 * inv);
    float y1 = w[t + 256] * (v1 * inv);
    __nv_bfloat16 h, l;
    split_bf16(y0, h, l);
    hi[base + t] = h; lo[base + t] = l;
    split_bf16(y1, h, l);
    hi[base + t + 256] = h; lo[base + t + 256] = l;
}

__global__ __launch_bounds__(256) void rms_k(const float* __restrict__ x,
                                             const float* __restrict__ w,
                                             float* __restrict__ y) {
    const size_t base = (size_t)blockIdx.x * DMODEL;
    const int t = threadIdx.x;
    float v0 = x[base + t], v1 = x[base + t + 256];
    float ss = v0 * v0 + v1 * v1;
    #pragma unroll
    for (int off = 16; off; off >>= 1) ss += __shfl_xor_sync(0xffffffffu, ss, off);
    __shared__ float red[8];
    __shared__ float bval;
    if ((t & 31) == 0) red[t >> 5] = ss;
    __syncthreads();
    if (t == 0) {
        float tot = 0.f;
        #pragma unroll
        for (int i = 0; i < 8; i++) tot += red[i];
        bval = rsqrtf(tot * (1.0f / DMODEL) + 1e-6f);
    }
    __syncthreads();
    const float inv = bval;
    y[base + t]       = w[t]       * (v0 * inv);
    y[base + t + 256] = w[t + 256] * (v1 * inv);
}

__global__ __launch_bounds__(256) void cvt_wt_all_k(const float* __restrict__ W,
                                                    __nv_bfloat16* __restrict__ th,
                                                    __nv_bfloat16* __restrict__ tl,
                                                    int Kd, int Nd,
                                                    size_t srcStride, size_t dstStride) {
    __shared__ float tile[32][33];
    const int l = blockIdx.z;
    W  += (size_t)l * srcStride;
    th += (size_t)l * dstStride;
    tl += (size_t)l * dstStride;
    int kb = blockIdx.y * 32, nb = blockIdx.x * 32;
    int tx = threadIdx.x & 31, ty = threadIdx.x >> 5;
    for (int r = ty; r < 32; r += 8)
        tile[r][tx] = W[(size_t)(kb + r) * Nd + nb + tx];
    __syncthreads();
    for (int r = ty; r < 32; r += 8) {
        float v = tile[tx][r];
        __nv_bfloat16 h, l2;
        split_bf16(v, h, l2);
        size_t oidx = (size_t)(nb + r) * Kd + kb + tx;
        th[oidx] = h;
        tl[oidx] = l2;
    }
}
__global__ __launch_bounds__(256) void cvt_vt_k(const float* __restrict__ v,
                                                __nv_bfloat16* __restrict__ th,
                                                __nv_bfloat16* __restrict__ tl) {
    __shared__ float tile[32][33];
    const int z = blockIdx.z;
    const int zb = z >> 3, zh = z & 7;
    const int s0 = blockIdx.x * 32;
    const int d0 = blockIdx.y * 32;
    const int tx = threadIdx.x & 31, ty = threadIdx.x >> 5;
    for (int r = ty; r < 32; r += 8)
        tile[r][tx] = v[(size_t)(zb * SEQ + s0 + r) * DMODEL + zh * DHEAD + d0 + tx];
    __syncthreads();
    for (int r = ty; r < 32; r += 8) {
        float val = tile[tx][r];
        __nv_bfloat16 h, l;
        split_bf16(val, h, l);
        size_t oidx = ((size_t)z * DHEAD + d0 + r) * SEQ + s0 + tx;
        th[oidx] = h;
        tl[oidx] = l;
    }
}

// ---------------- warp-MMA bf16x3 GEMM ----------------
#define MG_ROWB   80
#define MG_TILE   (128 * MG_ROWB)
#define MG_BUF    (4 * MG_TILE)
#define MG_SMEM   (2 * MG_BUF)

template <int EPI>
__global__ __launch_bounds__(256) void mgemm_k(
    const __nv_bfloat16* __restrict__ ah, const __nv_bfloat16* __restrict__ al,
    const __nv_bfloat16* __restrict__ wh, const __nv_bfloat16* __restrict__ wl,
    float* C0, float* C1, float* C2,
    const float* __restrict__ E, int K, int ldc, size_t wSlot)
{
    extern __shared__ char smem[];
    const uint32_t sb = smem_u32(smem);
    const int t = threadIdx.x;
    const int lane = t & 31, wid = t >> 5;
    const int wr = wid & 1, wc = wid >> 1;
    const int z = blockIdx.z;
    const __nv_bfloat16* Bh = wh + (size_t)z * wSlot;
    const __nv_bfloat16* Bl = wl + (size_t)z * wSlot;
    float* C = (z == 0) ? C0 : (z == 1) ? C1 : C2;
    const int m0 = blockIdx.y * 128, n0 = blockIdx.x * 128;

    float d[4][4][4];
    #pragma unroll
    for (int mi = 0; mi < 4; mi++)
        #pragma unroll
        for (int nj = 0; nj < 4; nj++)
            #pragma unroll
            for (int r = 0; r < 4; r++) d[mi][nj][r] = 0.f;

    const int lr = t >> 2;
    const int lc = t & 3;
    const __nv_bfloat16* srcs[4] = { ah, al, Bh, Bl };

    auto issue = [&](int kc, int buf) {
        const uint32_t base = sb + buf * MG_BUF;
        #pragma unroll
        for (int tile = 0; tile < 4; tile++) {
            const __nv_bfloat16* s = srcs[tile];
            const int baseRow = (tile < 2) ? m0 : n0;
            #pragma unroll
            for (int h = 0; h < 2; h++) {
                const int row = lr + h * 64;
                const __nv_bfloat16* g = s + (size_t)(baseRow + row) * K + kc * 32 + lc * 8;
                CP_ASYNC16(base + tile * MG_TILE + row * MG_ROWB + lc * 16, g);
            }
        }
        CP_COMMIT();
    };

    const int nch = K >> 5;
    issue(0, 0);

    const int mat = lane >> 3, l8 = lane & 7;
    for (int kc = 0; kc < nch; kc++) {
        const int buf = kc & 1;
        if (kc + 1 < nch) { issue(kc + 1, buf ^ 1); cp_wait<1>(); }
        else              { cp_wait<0>(); }
        __syncthreads();
        const uint32_t bbase = sb + buf * MG_BUF;
        #pragma unroll
        for (int kk = 0; kk < 2; kk++) {
            uint32_t Ah[4][4], Al[4][4], Bhf[2][4], Blf[2][4];
            #pragma unroll
            for (int mi = 0; mi < 4; mi++) {
                const int row = wr * 64 + mi * 16 + (mat & 1) * 8 + l8;
                const uint32_t ad = bbase + row * MG_ROWB + kk * 32 + (mat >> 1) * 16;
                ldmx4(Ah[mi], ad);
                ldmx4(Al[mi], ad + MG_TILE);
            }
            #pragma unroll
            for (int nj2 = 0; nj2 < 2; nj2++) {
                const int n = wc * 32 + nj2 * 16 + (mat >> 1) * 8 + l8;
                const uint32_t bd = bbase + 2 * MG_TILE + n * MG_ROWB + kk * 32 + (mat & 1) * 16;
                ldmx4(Bhf[nj2], bd);
                ldmx4(Blf[nj2], bd + MG_TILE);
            }
            #pragma unroll
            for (int mi = 0; mi < 4; mi++)
                #pragma unroll
                for (int nj = 0; nj < 4; nj++) {
                    const int g = nj >> 1, o = (nj & 1) * 2;
                    mma16816(d[mi][nj], Ah[mi], Bhf[g][o], Bhf[g][o + 1]);
                    mma16816(d[mi][nj], Ah[mi], Blf[g][o], Blf[g][o + 1]);
                    mma16816(d[mi][nj], Al[mi], Bhf[g][o], Bhf[g][o + 1]);
                }
        }
        __syncthreads();
    }

    #pragma unroll
    for (int mi = 0; mi < 4; mi++) {
        #pragma unroll
        for (int nj = 0; nj < 4; nj++) {
            const int row = m0 + wr * 64 + mi * 16 + (lane >> 2);
            const int col = n0 + wc * 32 + nj * 8 + (lane & 3) * 2;
            #pragma unroll
            for (int hh = 0; hh < 2; hh++) {
                const int m = row + hh * 8;
                float2 cv = make_float2(d[mi][nj][hh * 2], d[mi][nj][hh * 2 + 1]);
                if constexpr (EPI == 1) {
                    const float2 rv = *reinterpret_cast<const float2*>(
                        E + (size_t)m * ldc + col);
                    cv.x += rv.x; cv.y += rv.y;
                }
                *reinterpret_cast<float2*>(C + (size_t)m * ldc + col) = cv;
            }
        }
    }
}

// QKV GEMM: z=0 -> split bf16 (qh,ql); z=1 -> split (kh,kl); z=2 -> f32 v.
__global__ __launch_bounds__(256) void mgemm_qkv_k(
    const __nv_bfloat16* __restrict__ ah, const __nv_bfloat16* __restrict__ al,
    const __nv_bfloat16* __restrict__ wh, const __nv_bfloat16* __restrict__ wl,
    __nv_bfloat16* __restrict__ qh, __nv_bfloat16* __restrict__ ql,
    __nv_bfloat16* __restrict__ kh, __nv_bfloat16* __restrict__ kl,
    float* __restrict__ vout, size_t wSlot)
{
    constexpr int K = DMODEL;
    extern __shared__ char smem[];
    const uint32_t sb = smem_u32(smem);
    const int t = threadIdx.x;
    const int lane = t & 31, wid = t >> 5;
    const int wr = wid & 1, wc = wid >> 1;
    const int z = blockIdx.z;
    const __nv_bfloat16* Bh = wh + (size_t)z * wSlot;
    const __nv_bfloat16* Bl = wl + (size_t)z * wSlot;
    const int m0 = blockIdx.y * 128, n0 = blockIdx.x * 128;

    float d[4][4][4];
    #pragma unroll
    for (int mi = 0; mi < 4; mi++)
        #pragma unroll
        for (int nj = 0; nj < 4; nj++)
            #pragma unroll
            for (int r = 0; r < 4; r++) d[mi][nj][r] = 0.f;

    const int lr = t >> 2;
    const int lc = t & 3;
    const __nv_bfloat16* srcs[4] = { ah, al, Bh, Bl };

    auto issue = [&](int kc, int buf) {
        const uint32_t base = sb + buf * MG_BUF;
        #pragma unroll
        for (int tile = 0; tile < 4; tile++) {
            const __nv_bfloat16* s = srcs[tile];
            const int baseRow = (tile < 2) ? m0 : n0;
            #pragma unroll
            for (int h = 0; h < 2; h++) {
                const int row = lr + h * 64;
                const __nv_bfloat16* g = s + (size_t)(baseRow + row) * K + kc * 32 + lc * 8;
                CP_ASYNC16(base + tile * MG_TILE + row * MG_ROWB + lc * 16, g);
            }
        }
        CP_COMMIT();
    };

    const int nch = K >> 5;
    issue(0, 0);

    const int mat = lane >> 3, l8 = lane & 7;
    for (int kc = 0; kc < nch; kc++) {
        const int buf = kc & 1;
        if (kc + 1 < nch) { issue(kc + 1, buf ^ 1); cp_wait<1>(); }
        else              { cp_wait<0>(); }
        __syncthreads();
        const uint32_t bbase = sb + buf * MG_BUF;
        #pragma unroll
        for (int kk = 0; kk < 2; kk++) {
            uint32_t Ah[4][4], Al[4][4], Bhf[2][4], Blf[2][4];
            #pragma unroll
            for (int mi = 0; mi < 4; mi++) {
                const int row = wr * 64 + mi * 16 + (mat & 1) * 8 + l8;
                const uint32_t ad = bbase + row * MG_ROWB + kk * 32 + (mat >> 1) * 16;
                ldmx4(Ah[mi], ad);
                ldmx4(Al[mi], ad + MG_TILE);
            }
            #pragma unroll
            for (int nj2 = 0; nj2 < 2; nj2++) {
                const int n = wc * 32 + nj2 * 16 + (mat >> 1) * 8 + l8;
                const uint32_t bd = bbase + 2 * MG_TILE + n * MG_ROWB + kk * 32 + (mat & 1) * 16;
                ldmx4(Bhf[nj2], bd);
                ldmx4(Blf[nj2], bd + MG_TILE);
            }
            #pragma unroll
            for (int mi = 0; mi < 4; mi++)
                #pragma unroll
                for (int nj = 0; nj < 4; nj++) {
                    const int g = nj >> 1, o = (nj & 1) * 2;
                    mma16816(d[mi][nj], Ah[mi], Bhf[g][o], Bhf[g][o + 1]);
                    mma16816(d[mi][nj], Ah[mi], Blf[g][o], Blf[g][o + 1]);
                    mma16816(d[mi][nj], Al[mi], Bhf[g][o], Bhf[g][o + 1]);
                }
        }
        __syncthreads();
    }

    __nv_bfloat16* H = (z == 0) ? qh : kh;
    __nv_bfloat16* L = (z == 0) ? ql : kl;
    #pragma unroll
    for (int mi = 0; mi < 4; mi++) {
        #pragma unroll
        for (int nj = 0; nj < 4; nj++) {
            const int row = m0 + wr * 64 + mi * 16 + (lane >> 2);
            const int col = n0 + wc * 32 + nj * 8 + (lane & 3) * 2;
            #pragma unroll
            for (int hh = 0; hh < 2; hh++) {
                const int m = row + hh * 8;
                const size_t off = (size_t)m * DMODEL + col;
                if (z == 2) {
                    *reinterpret_cast<float2*>(vout + off) =
                        make_float2(d[mi][nj][hh * 2], d[mi][nj][hh * 2 + 1]);
                } else {
                    split_store2(d[mi][nj][hh * 2], d[mi][nj][hh * 2 + 1],
                                 H + off, L + off);
                }
            }
        }
    }
}

// FFN-in fused: gelu(A@W0) * (A@W1), split bf16 out.
#define FFN_BUF  (6 * MG_TILE)
#define FFN_SMEM (2 * FFN_BUF)
__global__ __launch_bounds__(256) void mgemm_ffn_k(
    const __nv_bfloat16* __restrict__ ah, const __nv_bfloat16* __restrict__ al,
    const __nv_bfloat16* __restrict__ w0h, const __nv_bfloat16* __restrict__ w0l,
    const __nv_bfloat16* __restrict__ w1h, const __nv_bfloat16* __restrict__ w1l,
    __nv_bfloat16* __restrict__ Ghi, __nv_bfloat16* __restrict__ Glo)
{
    constexpr int K = DMODEL;
    extern __shared__ char smem[];
    const uint32_t sb = smem_u32(smem);
    const int t = threadIdx.x;
    const int lane = t & 31, wid = t >> 5;
    const int wr = wid & 1, wc = wid >> 1;
    const int m0 = blockIdx.y * 128, n0 = blockIdx.x * 128;

    float d0[4][4][4], d1[4][4][4];
    #pragma unroll
    for (int mi = 0; mi < 4; mi++)
        #pragma unroll
        for (int nj = 0; nj < 4; nj++)
            #pragma unroll
            for (int r = 0; r < 4; r++) { d0[mi][nj][r] = 0.f; d1[mi][nj][r] = 0.f; }

    const int lr = t >> 2;
    const int lc = t & 3;
    const __nv_bfloat16* srcs[6] = { ah, al, w0h, w0l, w1h, w1l };

    auto issue = [&](int kc, int buf) {
        const uint32_t base = sb + buf * FFN_BUF;
        #pragma unroll
        for (int tile = 0; tile < 6; tile++) {
            const __nv_bfloat16* s = srcs[tile];
            const int baseRow = (tile < 2) ? m0 : n0;
            #pragma unroll
            for (int h = 0; h < 2; h++) {
                const int row = lr + h * 64;
                const __nv_bfloat16* g = s + (size_t)(baseRow + row) * K + kc * 32 + lc * 8;
                CP_ASYNC16(base + tile * MG_TILE + row * MG_ROWB + lc * 16, g);
            }
        }
        CP_COMMIT();
    };

    const int nch = K >> 5;
    issue(0, 0);

    const int mat = lane >> 3, l8 = lane & 7;
    for (int kc = 0; kc < nch; kc++) {
        const int buf = kc & 1;
        if (kc + 1 < nch) { issue(kc + 1, buf ^ 1); cp_wait<1>(); }
        else              { cp_wait<0>(); }
        __syncthreads();
        const uint32_t bbase = sb + buf * FFN_BUF;
        #pragma unroll
        for (int kk = 0; kk < 2; kk++) {
            uint32_t Ah[4][4], Al[4][4];
            #pragma unroll
            for (int mi = 0; mi < 4; mi++) {
                const int row = wr * 64 + mi * 16 + (mat & 1) * 8 + l8;
                const uint32_t ad = bbase + row * MG_ROWB + kk * 32 + (mat >> 1) * 16;
                ldmx4(Ah[mi], ad);
                ldmx4(Al[mi], ad + MG_TILE);
            }
            #pragma unroll
            for (int w = 0; w < 2; w++) {
                uint32_t Bhf[2][4], Blf[2][4];
                const uint32_t boff = bbase + (2 + 2 * w) * MG_TILE;
                #pragma unroll
                for (int nj2 = 0; nj2 < 2; nj2++) {
                    const int n = wc * 32 + nj2 * 16 + (mat >> 1) * 8 + l8;
                    const uint32_t bd = boff + n * MG_ROWB + kk * 32 + (mat & 1) * 16;
                    ldmx4(Bhf[nj2], bd);
                    ldmx4(Blf[nj2], bd + MG_TILE);
                }
                #pragma unroll
                for (int mi = 0; mi < 4; mi++)
                    #pragma unroll
                    for (int nj = 0; nj < 4; nj++) {
                        float* dd = w ? d1[mi][nj] : d0[mi][nj];
                        const int g = nj >> 1, o = (nj & 1) * 2;
                        mma16816(dd, Ah[mi], Bhf[g][o], Bhf[g][o + 1]);
                        mma16816(dd, Ah[mi], Blf[g][o], Blf[g][o + 1]);
                        mma16816(dd, Al[mi], Bhf[g][o], Bhf[g][o + 1]);
                    }
            }
        }
        __syncthreads();
    }

    #pragma unroll
    for (int mi = 0; mi < 4; mi++) {
        #pragma unroll
        for (int nj = 0; nj < 4; nj++) {
            const int row = m0 + wr * 64 + mi * 16 + (lane >> 2);
            const int col = n0 + wc * 32 + nj * 8 + (lane & 3) * 2;
            #pragma unroll
            for (int hh = 0; hh < 2; hh++) {
                const int m = row + hh * 8;
                const size_t off = (size_t)m * DFF_ + col;
                float r0 = gelu_new(d0[mi][nj][hh * 2])     * d1[mi][nj][hh * 2];
                float r1 = gelu_new(d0[mi][nj][hh * 2 + 1]) * d1[mi][nj][hh * 2 + 1];
                split_store2(r0, r1, Ghi + off, Glo + off);
            }
        }
    }
}

// ---------------- fused flash attention (smem bias table) ----------------
#define FL_QSTR 144
#define FL_VSTR 272
#define FL_QT   (128 * FL_QSTR)
#define FL_VT   (64 * FL_VSTR)
#define FL_OFF_K(buf) (2 * FL_QT + (buf) * 2 * FL_QT)
#define FL_OFF_V(buf) (6 * FL_QT + (buf) * 2 * FL_VT)
#define FL_BIAS_OFF (6 * FL_QT + 4 * FL_VT)     // 180224
#define FL_SMEM (FL_BIAS_OFF + 16384)           // 196608
__global__ __launch_bounds__(256) void flash_k(
    const __nv_bfloat16* __restrict__ qh_g, const __nv_bfloat16* __restrict__ ql_g,
    const __nv_bfloat16* __restrict__ kh_g, const __nv_bfloat16* __restrict__ kl_g,
    const __nv_bfloat16* __restrict__ vth_g, const __nv_bfloat16* __restrict__ vtl_g,
    const float* __restrict__ btab,
    __nv_bfloat16* __restrict__ Ohi, __nv_bfloat16* __restrict__ Olo)
{
    extern __shared__ char smem[];
    const uint32_t sb = smem_u32(smem);
    float* smb = reinterpret_cast<float*>(smem + FL_BIAS_OFF);
    const int t = threadIdx.x, lane = t & 31, wid = t >> 5;
    const int z = blockIdx.z, zb = z >> 3, zh = z & 7;
    const int m0 = blockIdx.x * 128;
    const int mat = lane >> 3, l8 = lane & 7;

    auto loadQ = [&]() {
        #pragma unroll
        for (int i = 0; i < 4; i++) {
            int idx = t + i * 256, row = idx >> 3, c = idx & 7;
            size_t go = (size_t)(zb * SEQ + m0 + row) * DMODEL + zh * 64 + c * 8;
            CP_ASYNC16(sb + row * FL_QSTR + c * 16, qh_g + go);
            CP_ASYNC16(sb + FL_QT + row * FL_QSTR + c * 16, ql_g + go);
        }
    };
    auto loadKV = [&](int kt, int buf) {
        #pragma unroll
        for (int i = 0; i < 4; i++) {
            int idx = t + i * 256, row = idx >> 3, c = idx & 7;
            size_t go = (size_t)(zb * SEQ + kt * 128 + row) * DMODEL + zh * 64 + c * 8;
            CP_ASYNC16(sb + FL_OFF_K(buf) + row * FL_QSTR + c * 16, kh_g + go);
            CP_ASYNC16(sb + FL_OFF_K(buf) + FL_QT + row * FL_QSTR + c * 16, kl_g + go);
        }
        #pragma unroll
        for (int i = 0; i < 4; i++) {
            int idx = t + i * 256, row = idx >> 4, c = idx & 15;
            size_t go = (size_t)(z * 64 + row) * SEQ + kt * 128 + c * 8;
            CP_ASYNC16(sb + FL_OFF_V(buf) + row * FL_VSTR + c * 16, vth_g + go);
            CP_ASYNC16(sb + FL_OFF_V(buf) + FL_VT + row * FL_VSTR + c * 16, vtl_g + go);
        }
        CP_COMMIT();
    };

    loadQ();
    loadKV(0, 0);
    // per-head rel-bias table into smem (visible after the kt=0 __syncthreads)
    for (int i = t; i < NRELS; i += 256) smb[i] = btab[zh * NRELS + i];

    float m_[2] = { -1e30f, -1e30f }, l_[2] = { 0.f, 0.f };
    float o[8][4];
    #pragma unroll
    for (int nt = 0; nt < 8; nt++)
        #pragma unroll
        for (int e = 0; e < 4; e++) o[nt][e] = 0.f;
    uint32_t qh[4][4], ql[4][4];

    for (int kt = 0; kt < 16; kt++) {
        const int buf = kt & 1;
        if (kt + 1 < 16) { loadKV(kt + 1, buf ^ 1); cp_wait<1>(); }
        else             { cp_wait<0>(); }
        __syncthreads();
        if (kt == 0) {
            #pragma unroll
            for (int kc = 0; kc < 4; kc++) {
                const int row = wid * 16 + (mat & 1) * 8 + l8;
                const uint32_t ad = sb + row * FL_QSTR + kc * 32 + (mat >> 1) * 16;
                ldmx4(qh[kc], ad);
                ldmx4(ql[kc], ad + FL_QT);
            }
        }
        float s[16][4];
        #pragma unroll
        for (int j = 0; j < 16; j++)
            #pragma unroll
            for (int e = 0; e < 4; e++) s[j][e] = 0.f;
        #pragma unroll
        for (int j2 = 0; j2 < 8; j2++) {
            const int n = j2 * 16 + (mat >> 1) * 8 + l8;
            #pragma unroll
            for (int kc = 0; kc < 4; kc++) {
                uint32_t bh4[4], bl4[4];
                const uint32_t bd = sb + FL_OFF_K(buf) + n * FL_QSTR + kc * 32 + (mat & 1) * 16;
                ldmx4(bh4, bd);
                ldmx4(bl4, bd + FL_QT);
                #pragma unroll
                for (int e = 0; e < 2; e++) {
                    mma16816(s[j2 * 2 + e], qh[kc], bh4[e * 2], bh4[e * 2 + 1]);
                    mma16816(s[j2 * 2 + e], qh[kc], bl4[e * 2], bl4[e * 2 + 1]);
                    mma16816(s[j2 * 2 + e], ql[kc], bh4[e * 2], bh4[e * 2 + 1]);
                }
            }
        }
        // ---- + bias from smem table: idx = col - row + 2047 ----
        const int r0 = m0 + wid * 16 + (lane >> 2);
        const int relbase = kt * 128 + 2 * (lane & 3) - r0 + 2047;
        #pragma unroll
        for (int j = 0; j < 16; j++) {
            const int idx = relbase + j * 8;
            s[j][0] += smb[idx];     s[j][1] += smb[idx + 1];
            s[j][2] += smb[idx - 8]; s[j][3] += smb[idx - 7];
        }
        float mx[2] = { -1e30f, -1e30f };
        #pragma unroll
        for (int j = 0; j < 16; j++) {
            mx[0] = fmaxf(mx[0], fmaxf(s[j][0], s[j][1]));
            mx[1] = fmaxf(mx[1], fmaxf(s[j][2], s[j][3]));
        }
        #pragma unroll
        for (int off = 1; off <= 2; off <<= 1) {
            mx[0] = fmaxf(mx[0], __shfl_xor_sync(0xffffffffu, mx[0], off));
            mx[1] = fmaxf(mx[1], __shfl_xor_sync(0xffffffffu, mx[1], off));
        }
        float al2[2];
        #pragma unroll
        for (int h = 0; h < 2; h++) {
            const float nm = fmaxf(m_[h], mx[h]);
            al2[h] = __expf(m_[h] - nm);
            m_[h] = nm;
        }
        float rs[2] = { 0.f, 0.f };
        #pragma unroll
        for (int j = 0; j < 16; j++) {
            s[j][0] = __expf(s[j][0] - m_[0]);
            s[j][1] = __expf(s[j][1] - m_[0]);
            s[j][2] = __expf(s[j][2] - m_[1]);
            s[j][3] = __expf(s[j][3] - m_[1]);
            rs[0] += s[j][0] + s[j][1];
            rs[1] += s[j][2] + s[j][3];
        }
        #pragma unroll
        for (int off = 1; off <= 2; off <<= 1) {
            rs[0] += __shfl_xor_sync(0xffffffffu, rs[0], off);
            rs[1] += __shfl_xor_sync(0xffffffffu, rs[1], off);
        }
        l_[0] = l_[0] * al2[0] + rs[0];
        l_[1] = l_[1] * al2[1] + rs[1];
        #pragma unroll
        for (int nt = 0; nt < 8; nt++) {
            o[nt][0] *= al2[0]; o[nt][1] *= al2[0];
            o[nt][2] *= al2[1]; o[nt][3] *= al2[1];
        }
        #pragma unroll
        for (int kc2 = 0; kc2 < 8; kc2++) {
            uint32_t pa[4], pl[4];
            #pragma unroll
            for (int u = 0; u < 2; u++) {
                #pragma unroll
                for (int hh = 0; hh < 2; hh++) {
                    const float v0 = s[2 * kc2 + u][hh * 2];
                    const float v1 = s[2 * kc2 + u][hh * 2 + 1];
                    __nv_bfloat16 h0, h1, lo0, lo1;
                    split_bf16(v0, h0, lo0);
                    split_bf16(v1, h1, lo1);
                    pa[u * 2 + hh] = pack_bf(h0, h1);
                    pl[u * 2 + hh] = pack_bf(lo0, lo1);
                }
            }
            #pragma unroll
            for (int j2v = 0; j2v < 4; j2v++) {
                const int n = j2v * 16 + (mat >> 1) * 8 + l8;
                uint32_t vh4[4], vl4[4];
                const uint32_t bd = sb + FL_OFF_V(buf) + n * FL_VSTR + kc2 * 32 + (mat & 1) * 16;
                ldmx4(vh4, bd);
                ldmx4(vl4, bd + FL_VT);
                #pragma unroll
                for (int e = 0; e < 2; e++) {
                    const int nt = j2v * 2 + e;
                    mma16816(o[nt], pa, vh4[e * 2], vh4[e * 2 + 1]);
                    mma16816(o[nt], pa, vl4[e * 2], vl4[e * 2 + 1]);
                    mma16816(o[nt], pl, vh4[e * 2], vh4[e * 2 + 1]);
                }
            }
        }
        __syncthreads();
    }

    const float inv0 = 1.0f / l_[0], inv1 = 1.0f / l_[1];
    const int r0 = m0 + wid * 16 + (lane >> 2);
    #pragma unroll
    for (int nt = 0; nt < 8; nt++) {
        const int col = zh * 64 + nt * 8 + 2 * (lane & 3);
        const size_t o0 = (size_t)(zb * SEQ + r0) * DMODEL + col;
        const size_t o1 = (size_t)(zb * SEQ + r0 + 8) * DMODEL + col;
        split_store2(o[nt][0] * inv0, o[nt][1] * inv0, Ohi + o0, Olo + o0);
        split_store2(o[nt][2] * inv1, o[nt][3] * inv1, Ohi + o1, Olo + o1);
    }
}

// ---------------- launch ----------------
extern "C" void kernel_launch(void* const* d_in, const int* in_sizes, int n_in,
                              void* d_out, int out_size) {
    const int*   ids    = (const int*)  d_in[0];
    const float* embed  = (const float*)d_in[1];
    const float* Wq     = (const float*)d_in[2];
    const float* Wk     = (const float*)d_in[3];
    const float* Wv     = (const float*)d_in[4];
    const float* Wo     = (const float*)d_in[5];
    const float* relb   = (const float*)d_in[6];
    const float* wi0    = (const float*)d_in[7];
    const float* wi1    = (const float*)d_in[8];
    const float* wo_ffn = (const float*)d_in[9];
    const float* ln0    = (const float*)d_in[10];
    const float* ln1    = (const float*)d_in[11];
    const float* flw    = (const float*)d_in[12];
    float* out = (float*)d_out;

    float *x, *v, *f0, *f1, *btab;
    __nv_bfloat16 *ah, *al, *oh, *ol, *wh, *wl, *vth, *vtl;
    cudaGetSymbolAddress((void**)&x,  g_x);
    cudaGetSymbolAddress((void**)&v,  g_v);
    cudaGetSymbolAddress((void**)&f0, g_f0);
    cudaGetSymbolAddress((void**)&f1, g_f1);
    cudaGetSymbolAddress((void**)&btab, g_btab);
    cudaGetSymbolAddress((void**)&ah, g_ah);
    cudaGetSymbolAddress((void**)&al, g_al);
    cudaGetSymbolAddress((void**)&oh, g_oh);
    cudaGetSymbolAddress((void**)&ol, g_ol);
    cudaGetSymbolAddress((void**)&wh, g_wh);
    cudaGetSymbolAddress((void**)&wl, g_wl);
    cudaGetSymbolAddress((void**)&vth, g_vth);
    cudaGetSymbolAddress((void**)&vtl, g_vtl);
    __nv_bfloat16* gh = (__nv_bfloat16*)f0;
    __nv_bfloat16* gl = (__nv_bfloat16*)f1;

    cudaFuncSetAttribute(mgemm_k<0>, cudaFuncAttributeMaxDynamicSharedMemorySize, MG_SMEM);
    cudaFuncSetAttribute(mgemm_k<1>, cudaFuncAttributeMaxDynamicSharedMemorySize, MG_SMEM);
    cudaFuncSetAttribute(mgemm_qkv_k, cudaFuncAttributeMaxDynamicSharedMemorySize, MG_SMEM);
    cudaFuncSetAttribute(mgemm_ffn_k, cudaFuncAttributeMaxDynamicSharedMemorySize, FFN_SMEM);
    cudaFuncSetAttribute(flash_k, cudaFuncAttributeMaxDynamicSharedMemorySize, FL_SMEM);

    float* out_bias = ((size_t)out_size > OUTX) ? (out + OUTX) : nullptr;

    embed_k<<<NROWS, 256>>>(ids, embed, x);
    bias_tab_k<<<(NH * NRELS + 255) / 256, 256>>>(relb, btab);
    if (out_bias) {
        size_t nb = ((size_t)NH * SEQ * SEQ + 255) / 256;
        bias_out_k<<<(unsigned)nb, 256>>>(btab, out_bias);
    }
    // ---- hoisted all-layer weight conversions ----
    {
        dim3 gQ(DMODEL / 32, DMODEL / 32, NL);
        cvt_wt_all_k<<<gQ, 256>>>(Wq, wh,            wl,            DMODEL, DMODEL, DDc, DDc);
        cvt_wt_all_k<<<gQ, 256>>>(Wk, wh + 4 * DDc,  wl + 4 * DDc,  DMODEL, DMODEL, DDc, DDc);
        cvt_wt_all_k<<<gQ, 256>>>(Wv, wh + 8 * DDc,  wl + 8 * DDc,  DMODEL, DMODEL, DDc, DDc);
        cvt_wt_all_k<<<gQ, 256>>>(Wo, wh + 12 * DDc, wl + 12 * DDc, DMODEL, DMODEL, DDc, DDc);
        dim3 gF(DFF_ / 32, DMODEL / 32, NL);
        cvt_wt_all_k<<<gF, 256>>>(wi0, wh + 16 * DDc,           wl + 16 * DDc,           DMODEL, DFF_, DFc, DFc);
        cvt_wt_all_k<<<gF, 256>>>(wi1, wh + 16 * DDc + 4 * DFc, wl + 16 * DDc + 4 * DFc, DMODEL, DFF_, DFc, DFc);
        dim3 gO(DMODEL / 32, DFF_ / 32, NL);
        cvt_wt_all_k<<<gO, 256>>>(wo_ffn, wh + 16 * DDc + 8 * DFc, wl + 16 * DDc + 8 * DFc, DFF_, DMODEL, DFc, DFc);
    }

    for (int i = 0; i < NL; i++) {
        const size_t wQKV = (size_t)i * DDc;
        const size_t wO   = 12 * DDc + (size_t)i * DDc;
        const size_t wI0  = 16 * DDc + (size_t)i * DFc;
        const size_t wI1  = 16 * DDc + 4 * DFc + (size_t)i * DFc;
        const size_t wOF  = 16 * DDc + 8 * DFc + (size_t)i * DFc;
        // ---- self attention ----
        rms_split_k<<<NROWS, 256>>>(x, ln0 + (size_t)i * DMODEL, ah, al);
        mgemm_qkv_k<<<dim3(4, 32, 3), 256, MG_SMEM>>>(ah, al, wh + wQKV, wl + wQKV,
                                                      oh, ol,
                                                      ah + QKSZ, al + QKSZ,
                                                      v, 4 * DDc);
        cvt_vt_k<<<dim3(SEQ / 32, DHEAD / 32, BATCH * NH), 256>>>(v, vth, vtl);
        flash_k<<<dim3(SEQ / 128, 1, BATCH * NH), 256, FL_SMEM>>>(
            oh, ol, ah + QKSZ, al + QKSZ, vth, vtl, btab, ah, al);
        mgemm_k<1><<<dim3(4, 32, 1), 256, MG_SMEM>>>(ah, al, wh + wO, wl + wO,
                                                     x, x, x, x,
                                                     DMODEL, DMODEL, 0);
        // ---- gated-GELU FFN (fused) ----
        rms_split_k<<<NROWS, 256>>>(x, ln1 + (size_t)i * DMODEL, ah, al);
        mgemm_ffn_k<<<dim3(DFF_ / 128, NROWS / 128), 256, FFN_SMEM>>>(
            ah, al, wh + wI0, wl + wI0, wh + wI1, wl + wI1, gh, gl);
        mgemm_k<1><<<dim3(4, 32, 1), 256, MG_SMEM>>>(gh, gl, wh + wOF, wl + wOF,
                                                     x, x, x, x,
                                                     DFF_, DMODEL, 0);
    }
    rms_k<<<NROWS, 256>>>(x, flw, out);
}